// round 1
// baseline (speedup 1.0000x reference)
#include <cuda_runtime.h>
#include <cuda_bf16.h>

// ---------------------------------------------------------------------------
// QuantumAttention: out = softmax((q_q . k_q)^2) @ v @ Wo + bo
// with q_q = normalize(x @ (Wq@We) + (bq@We + be)), k_q likewise.
// Key restructure: q/k 1024x1024 GEMMs are folded into 1024x16 projections.
// ---------------------------------------------------------------------------

#define B_ 4
#define S_ 2048
#define H_ 1024
#define QD_ 16
#define ROWS_ (B_ * S_)          // 8192

// ------------------------------- scratch ----------------------------------
__device__ float g_WqeT[QD_ * H_];     // [16][1024]  (transposed Wq@We)
__device__ float g_WkeT[QD_ * H_];
__device__ float g_bqe[QD_];
__device__ float g_bke[QD_];
__device__ float g_qq[ROWS_ * QD_];    // unit-normalized q embeddings
__device__ float g_kq[ROWS_ * QD_];
__device__ float g_v[ROWS_ * H_];      // 32 MB
__device__ float g_attn[(long long)B_ * S_ * S_];   // 64 MB
__device__ float g_att[ROWS_ * H_];    // 32 MB

// ------------------------- 1) fold We into Wq / Wk -------------------------
// WqeT[o][i] = sum_k Wq[i][k] * We[k][o];  bqe[o] = sum_k bq[k]*We[k][o] + be[o]
__global__ void precompute_kernel(const float* __restrict__ Wq,
                                  const float* __restrict__ Wk,
                                  const float* __restrict__ We,
                                  const float* __restrict__ bq,
                                  const float* __restrict__ bk,
                                  const float* __restrict__ be)
{
    int idx = blockIdx.x * blockDim.x + threadIdx.x;   // 0 .. 32767
    int m   = idx >> 14;            // 0: Wq, 1: Wk
    int rem = idx & 16383;
    int i   = rem >> 4;             // 0..1023 (input row of W)
    int o   = rem & 15;             // 0..15

    const float* W = (m == 0) ? Wq : Wk;
    float s = 0.f;
    #pragma unroll 4
    for (int k = 0; k < H_; k++)
        s = fmaf(W[(long long)i * H_ + k], We[k * QD_ + o], s);
    float* dst = (m == 0) ? g_WqeT : g_WkeT;
    dst[o * H_ + i] = s;

    if (idx < 2 * QD_) {            // folded biases
        int mm = idx >> 4;
        int oo = idx & 15;
        const float* bb = (mm == 0) ? bq : bk;
        float bs = 0.f;
        for (int k = 0; k < H_; k++)
            bs = fmaf(bb[k], We[k * QD_ + oo], bs);
        bs += be[oo];
        if (mm == 0) g_bqe[oo] = bs; else g_bke[oo] = bs;
    }
}

// --------------------- 2) embed: q_q and k_q in one pass -------------------
// one block per token row; 4 warps: warps 0-1 -> q dims, warps 2-3 -> k dims.
__global__ __launch_bounds__(128)
void embed_kernel(const float* __restrict__ x)
{
    __shared__ float xs[H_];
    __shared__ float zbuf[2 * QD_];

    long long row = blockIdx.x;
    const float* xr = x + row * H_;
    int tid = threadIdx.x;

    #pragma unroll
    for (int i = tid; i < H_ / 4; i += 128)
        *(float4*)&xs[i * 4] = *(const float4*)&xr[i * 4];
    __syncthreads();

    int warp = tid >> 5, lane = tid & 31;
    const float* WT = (warp < 2) ? g_WqeT : g_WkeT;
    int obase = (warp & 1) * 8;
    int zbase = (warp < 2) ? 0 : QD_;

    #pragma unroll
    for (int oo = 0; oo < 8; oo++) {
        int o = obase + oo;
        const float* w = WT + o * H_;
        float s = 0.f;
        #pragma unroll 8
        for (int k = lane; k < H_; k += 32)
            s = fmaf(xs[k], w[k], s);
        #pragma unroll
        for (int off = 16; off > 0; off >>= 1)
            s += __shfl_down_sync(0xffffffffu, s, off);
        if (lane == 0) zbuf[zbase + o] = s;
    }
    __syncthreads();

    if (tid < 32) {
        bool isq = tid < QD_;
        int d = tid & 15;
        float z = zbuf[tid] + (isq ? g_bqe[d] : g_bke[d]);
        float sq = z * z;
        #pragma unroll
        for (int off = 8; off > 0; off >>= 1)     // reduce within 16-lane half
            sq += __shfl_xor_sync(0xffffffffu, sq, off);
        float inv = rsqrtf(sq + 1e-8f);
        float val = z * inv;
        float* dst = isq ? g_qq : g_kq;
        dst[row * QD_ + d] = val;
    }
}

// ---------------- 3/5/6) fp32 SGEMM  C = A@B (+bias), batched --------------
// 128x128 block tile, BK=16, 256 threads, 8x8 per thread. Dims must be
// multiples of the tile (true for all call sites: M in {2048,8192}, N=1024,
// K in {1024,2048}).
__global__ __launch_bounds__(256, 2)
void sgemm128(const float* __restrict__ A, const float* __restrict__ Bm,
              const float* __restrict__ bias, float* __restrict__ C,
              int M, int N, int K,
              long long sA, long long sB, long long sC)
{
    constexpr int BK = 16;
    __shared__ float As[BK][132];   // padded: avoid 4-way store conflicts
    __shared__ float Bs[BK][128];

    A  += (long long)blockIdx.z * sA;
    Bm += (long long)blockIdx.z * sB;
    C  += (long long)blockIdx.z * sC;

    const int tid = threadIdx.x;
    const int bm = blockIdx.y * 128;
    const int bn = blockIdx.x * 128;

    const int tx = tid & 15;
    const int ty = tid >> 4;
    const int row0 = ty * 8;
    const int col0 = tx * 8;

    const int aRow = tid >> 2;          // 0..63
    const int aCol = (tid & 3) * 4;     // 0,4,8,12
    const int bRow = tid >> 5;          // 0..7
    const int bCol = (tid & 31) * 4;    // 0..124

    float acc[8][8] = {};

    for (int k0 = 0; k0 < K; k0 += BK) {
        #pragma unroll
        for (int r = 0; r < 2; r++) {
            int ar = aRow + r * 64;
            float4 av = *(const float4*)&A[(long long)(bm + ar) * K + k0 + aCol];
            As[aCol + 0][ar] = av.x;
            As[aCol + 1][ar] = av.y;
            As[aCol + 2][ar] = av.z;
            As[aCol + 3][ar] = av.w;
        }
        #pragma unroll
        for (int r = 0; r < 2; r++) {
            int br = bRow + r * 8;
            *(float4*)&Bs[br][bCol] =
                *(const float4*)&Bm[(long long)(k0 + br) * N + bn + bCol];
        }
        __syncthreads();

        #pragma unroll
        for (int k = 0; k < BK; k++) {
            float a[8], b[8];
            *(float4*)&a[0] = *(const float4*)&As[k][row0];
            *(float4*)&a[4] = *(const float4*)&As[k][row0 + 4];
            *(float4*)&b[0] = *(const float4*)&Bs[k][col0];
            *(float4*)&b[4] = *(const float4*)&Bs[k][col0 + 4];
            #pragma unroll
            for (int i = 0; i < 8; i++)
                #pragma unroll
                for (int j = 0; j < 8; j++)
                    acc[i][j] = fmaf(a[i], b[j], acc[i][j]);
        }
        __syncthreads();
    }

    #pragma unroll
    for (int i = 0; i < 8; i++) {
        long long crow = bm + row0 + i;
        #pragma unroll
        for (int j = 0; j < 8; j += 4) {
            float4 o;
            o.x = acc[i][j + 0]; o.y = acc[i][j + 1];
            o.z = acc[i][j + 2]; o.w = acc[i][j + 3];
            if (bias) {
                o.x += bias[bn + col0 + j + 0];
                o.y += bias[bn + col0 + j + 1];
                o.z += bias[bn + col0 + j + 2];
                o.w += bias[bn + col0 + j + 3];
            }
            *(float4*)&C[crow * N + bn + col0 + j] = o;
        }
    }
}

// ------------------- 4) scores + softmax -> attn matrix --------------------
// ov = <q_q, k_q> in [-1,1]  =>  s = ov^2 in [0,1]  =>  no max-subtraction
// needed (softmax is shift-invariant; exp(s) in [1, e]).
__global__ __launch_bounds__(256)
void attn_kernel(float* __restrict__ attnOut)
{
    int b = blockIdx.y;
    int i = blockIdx.x;
    int tid = threadIdx.x;

    __shared__ float qs[QD_];
    __shared__ float red[8];

    const float* q = g_qq + ((long long)b * S_ + i) * QD_;
    if (tid < QD_) qs[tid] = q[tid];
    __syncthreads();

    float qr[QD_];
    #pragma unroll
    for (int d = 0; d < QD_; d++) qr[d] = qs[d];

    const float* kq = g_kq + (long long)b * S_ * QD_;
    float e[8];
    float lsum = 0.f;

    #pragma unroll
    for (int jj = 0; jj < 8; jj++) {
        int j = tid + jj * 256;
        const float4* kp = (const float4*)(kq + (long long)j * QD_);
        float4 k0 = kp[0], k1 = kp[1], k2 = kp[2], k3 = kp[3];
        float ov = qr[0]*k0.x + qr[1]*k0.y + qr[2]*k0.z + qr[3]*k0.w
                 + qr[4]*k1.x + qr[5]*k1.y + qr[6]*k1.z + qr[7]*k1.w
                 + qr[8]*k2.x + qr[9]*k2.y + qr[10]*k2.z + qr[11]*k2.w
                 + qr[12]*k3.x + qr[13]*k3.y + qr[14]*k3.z + qr[15]*k3.w;
        float ee = __expf(ov * ov);
        e[jj] = ee;
        lsum += ee;
    }

    // block reduce
    #pragma unroll
    for (int off = 16; off > 0; off >>= 1)
        lsum += __shfl_xor_sync(0xffffffffu, lsum, off);
    if ((tid & 31) == 0) red[tid >> 5] = lsum;
    __syncthreads();
    float tot = red[0] + red[1] + red[2] + red[3]
              + red[4] + red[5] + red[6] + red[7];
    float inv = 1.f / tot;

    float* orow = attnOut + ((long long)b * S_ + i) * S_;
    #pragma unroll
    for (int jj = 0; jj < 8; jj++)
        orow[tid + jj * 256] = e[jj] * inv;
}

// ---------------------------------------------------------------------------
extern "C" void kernel_launch(void* const* d_in, const int* in_sizes, int n_in,
                              void* d_out, int out_size)
{
    const float* x  = (const float*)d_in[0];
    const float* Wq = (const float*)d_in[1];
    const float* bq = (const float*)d_in[2];
    const float* Wk = (const float*)d_in[3];
    const float* bk = (const float*)d_in[4];
    const float* Wv = (const float*)d_in[5];
    const float* bv = (const float*)d_in[6];
    const float* We = (const float*)d_in[7];
    const float* be = (const float*)d_in[8];
    const float* Wo = (const float*)d_in[9];
    const float* bo = (const float*)d_in[10];
    float* out = (float*)d_out;

    float *gv, *gattn, *gatt;
    cudaGetSymbolAddress((void**)&gv,    g_v);
    cudaGetSymbolAddress((void**)&gattn, g_attn);
    cudaGetSymbolAddress((void**)&gatt,  g_att);

    // 1) fold We into Wq/Wk
    precompute_kernel<<<128, 256>>>(Wq, Wk, We, bq, bk, be);

    // 2) q_q / k_q embeddings
    embed_kernel<<<ROWS_, 128>>>(x);

    // 3) v = x @ Wv + bv        [8192,1024] = [8192,1024]@[1024,1024]
    sgemm128<<<dim3(H_/128, ROWS_/128, 1), 256>>>(
        x, Wv, bv, gv, ROWS_, H_, H_, 0, 0, 0);

    // 4) attn = softmax((q_q . k_q)^2)
    attn_kernel<<<dim3(S_, B_), 256>>>(gattn);

    // 5) attended = attn @ v    (batched over B)
    sgemm128<<<dim3(H_/128, S_/128, B_), 256>>>(
        gattn, gv, nullptr, gatt, S_, H_, S_,
        (long long)S_ * S_, (long long)S_ * H_, (long long)S_ * H_);

    // 6) out = attended @ Wo + bo
    sgemm128<<<dim3(H_/128, ROWS_/128, 1), 256>>>(
        gatt, Wo, bo, out, ROWS_, H_, H_, 0, 0, 0);
}

// round 3
// speedup vs baseline: 2.4558x; 2.4558x over previous
#include <cuda_runtime.h>
#include <cuda_bf16.h>

// ---------------------------------------------------------------------------
// QuantumAttention, restructured:
//   out = attn @ (x @ (Wv@Wo) + bv@Wo) + bo,   attn = softmax((q_q.k_q)^2)
//   q_q = normalize(x @ (Wq@We) + (bq@We+be)),  k_q likewise.
// GEMMs in split-bf16 (bf16x3) on mma.sync.m16n8k16 (plain sm_103 PTX).
// ---------------------------------------------------------------------------

#define B_ 4
#define S_ 2048
#define H_ 1024
#define QD_ 16
#define ROWS_ (B_ * S_)          // 8192

typedef unsigned int u32;
typedef __nv_bfloat16 bf16;

// ------------------------------- scratch ----------------------------------
__device__ float g_WqeT[QD_ * H_];
__device__ float g_WkeT[QD_ * H_];
__device__ float g_bqe[QD_];
__device__ float g_bke[QD_];
__device__ float g_qq[ROWS_ * QD_];
__device__ float g_kq[ROWS_ * QD_];
__device__ float g_b2[H_];

__device__ bf16 g_xh[ROWS_ * H_];
__device__ bf16 g_xl[ROWS_ * H_];
__device__ bf16 g_Wvh[H_ * H_];
__device__ bf16 g_Wvl[H_ * H_];
__device__ bf16 g_Woh[H_ * H_];
__device__ bf16 g_Wol[H_ * H_];
__device__ bf16 g_W2h[H_ * H_];
__device__ bf16 g_W2l[H_ * H_];
__device__ bf16 g_v2h[ROWS_ * H_];
__device__ bf16 g_v2l[ROWS_ * H_];
__device__ bf16 g_attnh[(long long)B_ * S_ * S_];
__device__ bf16 g_attnl[(long long)B_ * S_ * S_];

// ----------------------------- PTX helpers --------------------------------
__device__ __forceinline__ u32 smem_u32(const void* p) {
    u32 a;
    asm("{ .reg .u64 t; cvta.to.shared.u64 t, %1; cvt.u32.u64 %0, t; }"
        : "=r"(a) : "l"(p));
    return a;
}
__device__ __forceinline__ void cpa16(u32 d, const void* g) {
    asm volatile("cp.async.cg.shared.global [%0], [%1], 16;" :: "r"(d), "l"(g));
}
#define CP_COMMIT() asm volatile("cp.async.commit_group;" ::: "memory")
#define CP_WAIT(n)  asm volatile("cp.async.wait_group %0;" :: "n"(n) : "memory")

__device__ __forceinline__ void ldsm4(u32* r, u32 a) {
    asm volatile("ldmatrix.sync.aligned.m8n8.x4.shared.b16 {%0,%1,%2,%3}, [%4];"
        : "=r"(r[0]), "=r"(r[1]), "=r"(r[2]), "=r"(r[3]) : "r"(a));
}
__device__ __forceinline__ void ldsm4t(u32* r, u32 a) {
    asm volatile("ldmatrix.sync.aligned.m8n8.x4.trans.shared.b16 {%0,%1,%2,%3}, [%4];"
        : "=r"(r[0]), "=r"(r[1]), "=r"(r[2]), "=r"(r[3]) : "r"(a));
}
__device__ __forceinline__ void mma16816(float* d, const u32* a, const u32* b) {
    asm volatile("mma.sync.aligned.m16n8k16.row.col.f32.bf16.bf16.f32 "
        "{%0,%1,%2,%3}, {%4,%5,%6,%7}, {%8,%9}, {%0,%1,%2,%3};"
        : "+f"(d[0]), "+f"(d[1]), "+f"(d[2]), "+f"(d[3])
        : "r"(a[0]), "r"(a[1]), "r"(a[2]), "r"(a[3]), "r"(b[0]), "r"(b[1]));
}

// ------------------------- 1) fold We into Wq / Wk -------------------------
__global__ void precompute_kernel(const float* __restrict__ Wq,
                                  const float* __restrict__ Wk,
                                  const float* __restrict__ We,
                                  const float* __restrict__ bq,
                                  const float* __restrict__ bk,
                                  const float* __restrict__ be)
{
    int idx = blockIdx.x * blockDim.x + threadIdx.x;
    int m   = idx >> 14;
    int rem = idx & 16383;
    int i   = rem >> 4;
    int o   = rem & 15;

    const float* W = (m == 0) ? Wq : Wk;
    float s = 0.f;
    #pragma unroll 4
    for (int k = 0; k < H_; k++)
        s = fmaf(W[(long long)i * H_ + k], We[k * QD_ + o], s);
    float* dst = (m == 0) ? g_WqeT : g_WkeT;
    dst[o * H_ + i] = s;

    if (idx < 2 * QD_) {
        int mm = idx >> 4, oo = idx & 15;
        const float* bb = (mm == 0) ? bq : bk;
        float bs = 0.f;
        for (int k = 0; k < H_; k++)
            bs = fmaf(bb[k], We[k * QD_ + oo], bs);
        bs += be[oo];
        if (mm == 0) g_bqe[oo] = bs; else g_bke[oo] = bs;
    }
}

// ---------------------- 1b) b2 = bv @ Wo  (1024-vector) --------------------
__global__ __launch_bounds__(256)
void b2_kernel(const float* __restrict__ bv, const float* __restrict__ Wo)
{
    int n = blockIdx.x * 256 + threadIdx.x;
    float s = 0.f;
    #pragma unroll 8
    for (int k = 0; k < H_; k++)
        s = fmaf(bv[k], Wo[(long long)k * H_ + n], s);
    g_b2[n] = s;
}

// --------------------- 2) embed: q_q and k_q in one pass -------------------
__global__ __launch_bounds__(128)
void embed_kernel(const float* __restrict__ x)
{
    __shared__ float xs[H_];
    __shared__ float zbuf[2 * QD_];

    long long row = blockIdx.x;
    const float* xr = x + row * H_;
    int tid = threadIdx.x;

    #pragma unroll
    for (int i = tid; i < H_ / 4; i += 128)
        *(float4*)&xs[i * 4] = *(const float4*)&xr[i * 4];
    __syncthreads();

    int warp = tid >> 5, lane = tid & 31;
    const float* WT = (warp < 2) ? g_WqeT : g_WkeT;
    int obase = (warp & 1) * 8;
    int zbase = (warp < 2) ? 0 : QD_;

    #pragma unroll
    for (int oo = 0; oo < 8; oo++) {
        int o = obase + oo;
        const float* w = WT + o * H_;
        float s = 0.f;
        #pragma unroll 8
        for (int k = lane; k < H_; k += 32)
            s = fmaf(xs[k], w[k], s);
        #pragma unroll
        for (int off = 16; off > 0; off >>= 1)
            s += __shfl_down_sync(0xffffffffu, s, off);
        if (lane == 0) zbuf[zbase + o] = s;
    }
    __syncthreads();

    if (tid < 32) {
        bool isq = tid < QD_;
        int d = tid & 15;
        float z = zbuf[tid] + (isq ? g_bqe[d] : g_bke[d]);
        float sq = z * z;
        #pragma unroll
        for (int off = 8; off > 0; off >>= 1)
            sq += __shfl_xor_sync(0xffffffffu, sq, off);
        float inv = rsqrtf(sq + 1e-8f);
        float* dst = isq ? g_qq : g_kq;
        dst[row * QD_ + d] = z * inv;
    }
}

// --------------------- 3) split fp32 -> bf16 hi/lo -------------------------
__global__ __launch_bounds__(256)
void split_kernel(const float* __restrict__ src,
                  bf16* __restrict__ h, bf16* __restrict__ l)
{
    int i = blockIdx.x * 256 + threadIdx.x;
    float4 v = ((const float4*)src)[i];
    bf16 h0 = __float2bfloat16(v.x), h1 = __float2bfloat16(v.y);
    bf16 h2 = __float2bfloat16(v.z), h3 = __float2bfloat16(v.w);
    __nv_bfloat162* hp = (__nv_bfloat162*)h;
    __nv_bfloat162* lp = (__nv_bfloat162*)l;
    hp[2*i]   = __nv_bfloat162(h0, h1);
    hp[2*i+1] = __nv_bfloat162(h2, h3);
    lp[2*i]   = __nv_bfloat162(__float2bfloat16(v.x - __bfloat162float(h0)),
                               __float2bfloat16(v.y - __bfloat162float(h1)));
    lp[2*i+1] = __nv_bfloat162(__float2bfloat16(v.z - __bfloat162float(h2)),
                               __float2bfloat16(v.w - __bfloat162float(h3)));
}

// ------------------- 4) scores + softmax -> bf16 split ---------------------
// 8 query rows per block, 2048 keys; 16x k-reuse vs 1 row/block.
__global__ __launch_bounds__(256)
void attn_kernel(bf16* __restrict__ ah, bf16* __restrict__ al)
{
    int b = blockIdx.y;
    int q0 = blockIdx.x * 8;
    int tid = threadIdx.x;
    int lane = tid & 31, wid = tid >> 5;

    __shared__ float qs[8][QD_];
    __shared__ float red[8][9];

    if (tid < 128)
        ((float*)qs)[tid] = g_qq[((long long)b * S_ + q0) * QD_ + tid];
    __syncthreads();

    const float* kq = g_kq + (long long)b * S_ * QD_;
    float e[8][8];
    float sum[8] = {0.f, 0.f, 0.f, 0.f, 0.f, 0.f, 0.f, 0.f};

    #pragma unroll
    for (int j = 0; j < 8; j++) {
        int kk = tid + j * 256;
        const float4* kp = (const float4*)(kq + (long long)kk * QD_);
        float4 k0 = kp[0], k1 = kp[1], k2 = kp[2], k3 = kp[3];
        #pragma unroll
        for (int q = 0; q < 8; q++) {
            const float* qr = qs[q];
            float ov = qr[0]*k0.x + qr[1]*k0.y + qr[2]*k0.z + qr[3]*k0.w
                     + qr[4]*k1.x + qr[5]*k1.y + qr[6]*k1.z + qr[7]*k1.w
                     + qr[8]*k2.x + qr[9]*k2.y + qr[10]*k2.z + qr[11]*k2.w
                     + qr[12]*k3.x + qr[13]*k3.y + qr[14]*k3.z + qr[15]*k3.w;
            float ee = __expf(ov * ov);
            e[q][j] = ee;
            sum[q] += ee;
        }
    }

    #pragma unroll
    for (int q = 0; q < 8; q++) {
        float s = sum[q];
        #pragma unroll
        for (int off = 16; off > 0; off >>= 1)
            s += __shfl_xor_sync(0xffffffffu, s, off);
        if (lane == 0) red[wid][q] = s;
    }
    __syncthreads();

    float inv[8];
    #pragma unroll
    for (int q = 0; q < 8; q++) {
        float t = 0.f;
        #pragma unroll
        for (int w = 0; w < 8; w++) t += red[w][q];
        inv[q] = 1.f / t;
    }

    #pragma unroll
    for (int q = 0; q < 8; q++) {
        long long rowo = ((long long)b * S_ + q0 + q) * S_;
        #pragma unroll
        for (int j = 0; j < 8; j++) {
            float p = e[q][j] * inv[q];
            bf16 hh = __float2bfloat16(p);
            ah[rowo + tid + j * 256] = hh;
            al[rowo + tid + j * 256] = __float2bfloat16(p - __bfloat162float(hh));
        }
    }
}

// ---------------- 5) split-bf16 GEMM on mma.sync (bf16x3) ------------------
// C[M,N] = A[M,K] @ B[K,N], A and B as bf16 (hi,lo) pairs, fp32 accum.
// Tile 128x128xBK32, 8 warps of 64x32. 3 MMA terms: AhBh + AlBh + AhBl.
// mode 0: Cf fp32 (+bias).  mode 1: Ch/Cl bf16 split (+bias if non-null).
#define APITCH 80                    // 32 bf16 = 64B rows padded to 80B
#define BPITCH 272                   // 128 bf16 = 256B rows padded to 272B
#define ATILE (128 * APITCH)         // 10240
#define BTILE (32 * BPITCH)          // 8704
#define STAGE (2 * ATILE + 2 * BTILE)// 37888

__device__ __forceinline__ void load_stage(u32 sb,
    const bf16* __restrict__ Ah, const bf16* __restrict__ Al,
    const bf16* __restrict__ Bh, const bf16* __restrict__ Bl,
    int bm, int bn, int k0, int K, int N, int tid)
{
    #pragma unroll
    for (int i = 0; i < 2; i++) {
        int u = tid + i * 256;
        int r = u >> 2, c = u & 3;
        long long g = (long long)(bm + r) * K + k0 + c * 8;
        cpa16(sb + r * APITCH + c * 16, Ah + g);
        cpa16(sb + ATILE + r * APITCH + c * 16, Al + g);
    }
    #pragma unroll
    for (int i = 0; i < 2; i++) {
        int u = tid + i * 256;
        int r = u >> 4, c = u & 15;
        long long g = (long long)(k0 + r) * N + bn + c * 8;
        cpa16(sb + 2 * ATILE + r * BPITCH + c * 16, Bh + g);
        cpa16(sb + 2 * ATILE + BTILE + r * BPITCH + c * 16, Bl + g);
    }
}

__global__ __launch_bounds__(256)
void mmagemm(const bf16* __restrict__ Ah, const bf16* __restrict__ Al,
             const bf16* __restrict__ Bh, const bf16* __restrict__ Bl,
             const float* __restrict__ bias, float* __restrict__ Cf,
             bf16* __restrict__ Ch, bf16* __restrict__ Cl,
             int M, int N, int K,
             long long sA, long long sB, long long sC, int mode)
{
    extern __shared__ char dsm[];
    u32 sbase = smem_u32(dsm);

    const int tid = threadIdx.x;
    const int wid = tid >> 5, lane = tid & 31;
    const int bn = blockIdx.x * 128, bm = blockIdx.y * 128, z = blockIdx.z;
    Ah += (long long)z * sA; Al += (long long)z * sA;
    Bh += (long long)z * sB; Bl += (long long)z * sB;

    const int wm = (wid >> 2) * 64;
    const int wn = (wid & 3) * 32;

    float acc[4][4][4] = {};

    const int NC = K >> 5;
    load_stage(sbase, Ah, Al, Bh, Bl, bm, bn, 0, K, N, tid);
    CP_COMMIT();

    // per-lane ldmatrix address components
    const int arow = lane & 15;
    const int ak8  = ((lane >> 4) & 1) * 8;
    const int bk   = lane & 15;
    const int bn8  = ((lane >> 4) & 1) * 8;

    for (int c = 0; c < NC; c++) {
        if (c + 1 < NC) {
            load_stage(sbase + ((c + 1) & 1) * STAGE, Ah, Al, Bh, Bl,
                       bm, bn, (c + 1) << 5, K, N, tid);
            CP_COMMIT();
            CP_WAIT(1);
        } else {
            CP_WAIT(0);
        }
        __syncthreads();

        u32 st = sbase + (c & 1) * STAGE;
        u32 As = st, Als = st + ATILE;
        u32 Bs = st + 2 * ATILE, Bls = Bs + BTILE;

        #pragma unroll
        for (int ks = 0; ks < 32; ks += 16) {
            u32 bh[2][4], bl[2][4];
            #pragma unroll
            for (int n2 = 0; n2 < 2; n2++) {
                u32 boff = (ks + bk) * BPITCH + (wn + 16 * n2 + bn8) * 2;
                ldsm4t(bh[n2], Bs + boff);
                ldsm4t(bl[n2], Bls + boff);
            }
            #pragma unroll
            for (int m = 0; m < 4; m++) {
                u32 ah[4], al[4];
                u32 aoff = (wm + 16 * m + arow) * APITCH + (ks + ak8) * 2;
                ldsm4(ah, As + aoff);
                ldsm4(al, Als + aoff);
                #pragma unroll
                for (int j = 0; j < 4; j++) {
                    const u32* bhp = &bh[j >> 1][(j & 1) * 2];
                    const u32* blp = &bl[j >> 1][(j & 1) * 2];
                    mma16816(acc[m][j], ah, bhp);
                    mma16816(acc[m][j], al, bhp);
                    mma16816(acc[m][j], ah, blp);
                }
            }
        }
        __syncthreads();
    }

    // ------------------------------ epilogue -------------------------------
    const int trow = lane >> 2;
    const int tcol = (lane & 3) * 2;

    #pragma unroll
    for (int m = 0; m < 4; m++) {
        #pragma unroll
        for (int j = 0; j < 4; j++) {
            int col = bn + wn + 8 * j + tcol;
            float b0 = bias ? bias[col] : 0.f;
            float b1 = bias ? bias[col + 1] : 0.f;
            #pragma unroll
            for (int h = 0; h < 2; h++) {
                long long row = bm + wm + 16 * m + trow + h * 8;
                float v0 = acc[m][j][2 * h + 0] + b0;
                float v1 = acc[m][j][2 * h + 1] + b1;
                long long idx = (long long)z * sC + row * N + col;
                if (mode == 0) {
                    *(float2*)(Cf + idx) = make_float2(v0, v1);
                } else {
                    bf16 h0 = __float2bfloat16(v0);
                    bf16 h1 = __float2bfloat16(v1);
                    *(__nv_bfloat162*)(Ch + idx) = __nv_bfloat162(h0, h1);
                    *(__nv_bfloat162*)(Cl + idx) = __nv_bfloat162(
                        __float2bfloat16(v0 - __bfloat162float(h0)),
                        __float2bfloat16(v1 - __bfloat162float(h1)));
                }
            }
        }
    }
}

// ---------------------------------------------------------------------------
extern "C" void kernel_launch(void* const* d_in, const int* in_sizes, int n_in,
                              void* d_out, int out_size)
{
    const float* x  = (const float*)d_in[0];
    const float* Wq = (const float*)d_in[1];
    const float* bq = (const float*)d_in[2];
    const float* Wk = (const float*)d_in[3];
    const float* bk = (const float*)d_in[4];
    const float* Wv = (const float*)d_in[5];
    const float* bv = (const float*)d_in[6];
    const float* We = (const float*)d_in[7];
    const float* be = (const float*)d_in[8];
    const float* Wo = (const float*)d_in[9];
    const float* bo = (const float*)d_in[10];
    float* out = (float*)d_out;

    bf16 *xh, *xl, *Wvh, *Wvl, *Woh, *Wol, *W2h, *W2l, *v2h, *v2l, *anh, *anl;
    float* b2;
    cudaGetSymbolAddress((void**)&xh,  g_xh);
    cudaGetSymbolAddress((void**)&xl,  g_xl);
    cudaGetSymbolAddress((void**)&Wvh, g_Wvh);
    cudaGetSymbolAddress((void**)&Wvl, g_Wvl);
    cudaGetSymbolAddress((void**)&Woh, g_Woh);
    cudaGetSymbolAddress((void**)&Wol, g_Wol);
    cudaGetSymbolAddress((void**)&W2h, g_W2h);
    cudaGetSymbolAddress((void**)&W2l, g_W2l);
    cudaGetSymbolAddress((void**)&v2h, g_v2h);
    cudaGetSymbolAddress((void**)&v2l, g_v2l);
    cudaGetSymbolAddress((void**)&anh, g_attnh);
    cudaGetSymbolAddress((void**)&anl, g_attnl);
    cudaGetSymbolAddress((void**)&b2,  g_b2);

    const int GSMEM = 2 * STAGE;   // 75776
    cudaFuncSetAttribute(mmagemm, cudaFuncAttributeMaxDynamicSharedMemorySize, GSMEM);

    // 1) fold We into Wq/Wk;  b2 = bv @ Wo
    precompute_kernel<<<128, 256>>>(Wq, Wk, We, bq, bk, be);
    b2_kernel<<<H_ / 256, 256>>>(bv, Wo);
    // 2) q_q / k_q embeddings
    embed_kernel<<<ROWS_, 128>>>(x);
    // 3) bf16 splits (natural layout; no transposes needed)
    split_kernel<<<ROWS_ * H_ / 4 / 256, 256>>>(x, xh, xl);
    split_kernel<<<H_ * H_ / 4 / 256, 256>>>(Wv, Wvh, Wvl);
    split_kernel<<<H_ * H_ / 4 / 256, 256>>>(Wo, Woh, Wol);
    // 4) softmax probs -> bf16 split
    attn_kernel<<<dim3(S_ / 8, B_), 256>>>(anh, anl);
    // 5) W2 = Wv @ Wo  (bf16 split out)
    mmagemm<<<dim3(H_ / 128, H_ / 128, 1), 256, GSMEM>>>(
        Wvh, Wvl, Woh, Wol, nullptr, nullptr, W2h, W2l,
        H_, H_, H_, 0, 0, 0, 1);
    // 6) v2 = x @ W2 + b2  (bf16 split out, natural layout)
    mmagemm<<<dim3(H_ / 128, ROWS_ / 128, 1), 256, GSMEM>>>(
        xh, xl, W2h, W2l, b2, nullptr, v2h, v2l,
        ROWS_, H_, H_, 0, 0, 0, 1);
    // 7) out = attn @ v2 + bo  (fp32, batched over B)
    mmagemm<<<dim3(H_ / 128, S_ / 128, B_), 256, GSMEM>>>(
        anh, anl, v2h, v2l, bo, out, nullptr, nullptr,
        S_, H_, S_, (long long)S_ * S_, (long long)S_ * H_,
        (long long)S_ * H_, 0);
}

// round 4
// speedup vs baseline: 3.1936x; 1.3005x over previous
#include <cuda_runtime.h>
#include <cuda_fp16.h>

// ---------------------------------------------------------------------------
// QuantumAttention, restructured:
//   out = attn @ (x @ (Wv@Wo) + bv@Wo) + bo,  attn = softmax((q_q.k_q)^2)
//   q_q = normalize(x @ (Wq@We) + (bq@We+be)), k_q likewise.
// GEMMs in split-fp16 (2-term compensated) on mma.sync.m16n8k16.f32.f16.f16.
// ---------------------------------------------------------------------------

#define B_ 4
#define S_ 2048
#define H_ 1024
#define QD_ 16
#define ROWS_ (B_ * S_)          // 8192

typedef unsigned int u32;

// ------------------------------- scratch ----------------------------------
__device__ float g_WqeT[QD_ * H_];
__device__ float g_WkeT[QD_ * H_];
__device__ float g_bqe[QD_];
__device__ float g_bke[QD_];
__device__ float g_qq[ROWS_ * QD_];
__device__ float g_kq[ROWS_ * QD_];
__device__ float g_b2[H_];

__device__ half g_xh[ROWS_ * H_];
__device__ half g_Wvh[H_ * H_];
__device__ half g_Wvl[H_ * H_];
__device__ half g_Woh[H_ * H_];
__device__ half g_Wol[H_ * H_];
__device__ half g_W2h[H_ * H_];
__device__ half g_W2l[H_ * H_];
__device__ half g_v2h[ROWS_ * H_];
__device__ half g_attnh[(long long)B_ * S_ * S_];
__device__ half g_attnl[(long long)B_ * S_ * S_];

// ----------------------------- PTX helpers --------------------------------
__device__ __forceinline__ u32 smem_u32(const void* p) {
    u32 a;
    asm("{ .reg .u64 t; cvta.to.shared.u64 t, %1; cvt.u32.u64 %0, t; }"
        : "=r"(a) : "l"(p));
    return a;
}
__device__ __forceinline__ void cpa16(u32 d, const void* g) {
    asm volatile("cp.async.cg.shared.global [%0], [%1], 16;" :: "r"(d), "l"(g));
}
#define CP_COMMIT() asm volatile("cp.async.commit_group;" ::: "memory")
#define CP_WAIT(n)  asm volatile("cp.async.wait_group %0;" :: "n"(n) : "memory")

__device__ __forceinline__ void ldsm4(u32* r, u32 a) {
    asm volatile("ldmatrix.sync.aligned.m8n8.x4.shared.b16 {%0,%1,%2,%3}, [%4];"
        : "=r"(r[0]), "=r"(r[1]), "=r"(r[2]), "=r"(r[3]) : "r"(a));
}
__device__ __forceinline__ void ldsm4t(u32* r, u32 a) {
    asm volatile("ldmatrix.sync.aligned.m8n8.x4.trans.shared.b16 {%0,%1,%2,%3}, [%4];"
        : "=r"(r[0]), "=r"(r[1]), "=r"(r[2]), "=r"(r[3]) : "r"(a));
}
__device__ __forceinline__ void mma16816(float* d, const u32* a, const u32* b) {
    asm volatile("mma.sync.aligned.m16n8k16.row.col.f32.f16.f16.f32 "
        "{%0,%1,%2,%3}, {%4,%5,%6,%7}, {%8,%9}, {%0,%1,%2,%3};"
        : "+f"(d[0]), "+f"(d[1]), "+f"(d[2]), "+f"(d[3])
        : "r"(a[0]), "r"(a[1]), "r"(a[2]), "r"(a[3]), "r"(b[0]), "r"(b[1]));
}

// ------------------- 1) fold We into Wq/Wk (warp per row) ------------------
// WqeT[o][i] = sum_k Wq[i][k]*We[k][o].  Virtual row i==1024 folds the bias.
__global__ __launch_bounds__(256)
void precompute_kernel(const float* __restrict__ Wq,
                       const float* __restrict__ Wk,
                       const float* __restrict__ We,
                       const float* __restrict__ bq,
                       const float* __restrict__ bk,
                       const float* __restrict__ be)
{
    extern __shared__ float Wes[];          // [1024][17] padded
    int tid = threadIdx.x;
    for (int idx = tid; idx < H_ * QD_; idx += 256)
        Wes[(idx >> 4) * 17 + (idx & 15)] = We[idx];
    __syncthreads();

    int wg = blockIdx.x * 8 + (tid >> 5);
    if (wg >= 2 * (H_ + 1)) return;
    int m = wg / (H_ + 1);
    int i = wg % (H_ + 1);
    int lane = tid & 31;
    const float* W  = m ? Wk : Wq;
    const float* bb = m ? bk : bq;

    float p[QD_];
    #pragma unroll
    for (int o = 0; o < QD_; o++) p[o] = 0.f;

    for (int kk = 0; kk < H_ / 32; kk++) {
        int k = kk * 32 + lane;
        float w = (i < H_) ? W[(long long)i * H_ + k] : bb[k];
        const float* wr = &Wes[k * 17];
        #pragma unroll
        for (int o = 0; o < QD_; o++) p[o] = fmaf(w, wr[o], p[o]);
    }
    #pragma unroll
    for (int off = 16; off; off >>= 1)
        #pragma unroll
        for (int o = 0; o < QD_; o++)
            p[o] += __shfl_xor_sync(0xffffffffu, p[o], off);

    if (lane == 0) {
        if (i < H_) {
            float* dst = m ? g_WkeT : g_WqeT;
            #pragma unroll
            for (int o = 0; o < QD_; o++) dst[o * H_ + i] = p[o];
        } else {
            float* dst = m ? g_bke : g_bqe;
            #pragma unroll
            for (int o = 0; o < QD_; o++) dst[o] = p[o] + be[o];
        }
    }
}

// ---------------------- 1b) b2 = bv @ Wo  (1024-vector) --------------------
__global__ __launch_bounds__(256)
void b2_kernel(const float* __restrict__ bv, const float* __restrict__ Wo)
{
    int n = blockIdx.x * 256 + threadIdx.x;
    float s = 0.f;
    #pragma unroll 8
    for (int k = 0; k < H_; k++)
        s = fmaf(bv[k], Wo[(long long)k * H_ + n], s);
    g_b2[n] = s;
}

// ------------- 2) embed: 64 rows/block, W staged in smem once --------------
#define ERB 64
__global__ __launch_bounds__(256)
void embed_kernel(const float* __restrict__ x)
{
    extern __shared__ float sm[];
    float* Ws = sm;                       // [32][1024]: 16 q dims then 16 k
    float* xb = sm + 32 * H_;             // [2][1024] double buffer
    __shared__ float zbuf[32];

    int tid = threadIdx.x, lane = tid & 31, w = tid >> 5;

    for (int idx = tid; idx < QD_ * H_; idx += 256) {
        Ws[idx]            = g_WqeT[idx];
        Ws[QD_ * H_ + idx] = g_WkeT[idx];
    }
    long long row0 = (long long)blockIdx.x * ERB;

    float4 nxt = *(const float4*)&x[row0 * H_ + tid * 4];
    *(float4*)&xb[tid * 4] = nxt;
    __syncthreads();

    for (int r = 0; r < ERB; r++) {
        if (r + 1 < ERB)
            nxt = *(const float4*)&x[(row0 + r + 1) * H_ + tid * 4];

        const float* xs = xb + (r & 1) * H_;
        float xr[32];
        #pragma unroll
        for (int i = 0; i < 8; i++)
            *(float4*)&xr[i * 4] = *(const float4*)&xs[i * 128 + lane * 4];

        #pragma unroll
        for (int oo = 0; oo < 4; oo++) {
            int o = w * 4 + oo;
            const float* wrow = Ws + o * H_;
            float s = 0.f;
            #pragma unroll
            for (int i = 0; i < 8; i++) {
                float4 wv = *(const float4*)&wrow[i * 128 + lane * 4];
                s += xr[i*4]*wv.x + xr[i*4+1]*wv.y + xr[i*4+2]*wv.z + xr[i*4+3]*wv.w;
            }
            #pragma unroll
            for (int off = 16; off; off >>= 1)
                s += __shfl_xor_sync(0xffffffffu, s, off);
            if (lane == 0) zbuf[o] = s;
        }
        __syncthreads();

        if (tid < 32) {
            int o = tid & 15;
            bool isq = tid < 16;
            float z = zbuf[tid] + (isq ? g_bqe[o] : g_bke[o]);
            float sq = z * z;
            #pragma unroll
            for (int off = 8; off; off >>= 1)
                sq += __shfl_xor_sync(0xffffffffu, sq, off);
            float val = z * rsqrtf(sq + 1e-8f);
            (isq ? g_qq : g_kq)[(row0 + r) * QD_ + o] = val;
        }
        if (r + 1 < ERB)
            *(float4*)&xb[((r + 1) & 1) * H_ + tid * 4] = nxt;
        __syncthreads();
    }
}

// --------------------- 3) fp32 -> fp16 (hi only / hi+lo) -------------------
__global__ __launch_bounds__(256)
void split_h(const float* __restrict__ src, half* __restrict__ h)
{
    int i = blockIdx.x * 256 + threadIdx.x;
    float4 v = ((const float4*)src)[i];
    half2* hp = (half2*)h;
    hp[2*i]   = __floats2half2_rn(v.x, v.y);
    hp[2*i+1] = __floats2half2_rn(v.z, v.w);
}

__global__ __launch_bounds__(256)
void split_hl(const float* __restrict__ src,
              half* __restrict__ h, half* __restrict__ l)
{
    int i = blockIdx.x * 256 + threadIdx.x;
    float4 v = ((const float4*)src)[i];
    half h0 = __float2half_rn(v.x), h1 = __float2half_rn(v.y);
    half h2 = __float2half_rn(v.z), h3 = __float2half_rn(v.w);
    half2* hp = (half2*)h;
    half2* lp = (half2*)l;
    hp[2*i]   = __halves2half2(h0, h1);
    hp[2*i+1] = __halves2half2(h2, h3);
    lp[2*i]   = __floats2half2_rn(v.x - __half2float(h0), v.y - __half2float(h1));
    lp[2*i+1] = __floats2half2_rn(v.z - __half2float(h2), v.w - __half2float(h3));
}

// ------------- 4) scores + softmax -> fp16 split (x1024 scaled) ------------
__global__ __launch_bounds__(256)
void attn_kernel(half* __restrict__ ah, half* __restrict__ al)
{
    int b = blockIdx.y;
    int q0 = blockIdx.x * 8;
    int tid = threadIdx.x;
    int lane = tid & 31, wid = tid >> 5;

    __shared__ float qs[8][QD_];
    __shared__ float red[8][9];

    if (tid < 128)
        ((float*)qs)[tid] = g_qq[((long long)b * S_ + q0) * QD_ + tid];
    __syncthreads();

    const float* kq = g_kq + (long long)b * S_ * QD_;
    float e[8][8];
    float sum[8] = {};

    #pragma unroll
    for (int j = 0; j < 8; j++) {
        int kk = tid + j * 256;
        const float4* kp = (const float4*)(kq + (long long)kk * QD_);
        float4 k0 = kp[0], k1 = kp[1], k2 = kp[2], k3 = kp[3];
        #pragma unroll
        for (int q = 0; q < 8; q++) {
            const float* qr = qs[q];
            float ov = qr[0]*k0.x + qr[1]*k0.y + qr[2]*k0.z + qr[3]*k0.w
                     + qr[4]*k1.x + qr[5]*k1.y + qr[6]*k1.z + qr[7]*k1.w
                     + qr[8]*k2.x + qr[9]*k2.y + qr[10]*k2.z + qr[11]*k2.w
                     + qr[12]*k3.x + qr[13]*k3.y + qr[14]*k3.z + qr[15]*k3.w;
            float ee = __expf(ov * ov);
            e[q][j] = ee;
            sum[q] += ee;
        }
    }

    #pragma unroll
    for (int q = 0; q < 8; q++) {
        float s = sum[q];
        #pragma unroll
        for (int off = 16; off; off >>= 1)
            s += __shfl_xor_sync(0xffffffffu, s, off);
        if (lane == 0) red[wid][q] = s;
    }
    __syncthreads();

    float inv[8];
    #pragma unroll
    for (int q = 0; q < 8; q++) {
        float t = 0.f;
        #pragma unroll
        for (int w = 0; w < 8; w++) t += red[w][q];
        inv[q] = 1024.f / t;              // x1024: keeps lo parts normal fp16
    }

    #pragma unroll
    for (int q = 0; q < 8; q++) {
        long long rowo = ((long long)b * S_ + q0 + q) * S_;
        #pragma unroll
        for (int j = 0; j < 8; j++) {
            float p = e[q][j] * inv[q];
            half hh = __float2half_rn(p);
            ah[rowo + tid + j * 256] = hh;
            al[rowo + tid + j * 256] = __float2half_rn(p - __half2float(hh));
        }
    }
}

// --------------- 5) split-fp16 GEMM on mma.sync (templated) ----------------
// C[M,N] = A[M,K] @ B[K,N]; terms: AhBh (+AlBh if ASPLIT)(+AhBl if BSPLIT).
// OMODE 0: fp32 out = acc*oscale + bias; 1: fp16 split out; 2: fp16 plain out.
#define APITCH 80                      // 32 half = 64B + 16 pad
#define BPITCH 272                     // 128 half = 256B + 16 pad
#define ATILE (128 * APITCH)           // 10240
#define BTILE (32 * BPITCH)            // 8704

template<bool ASPLIT, bool BSPLIT>
__device__ __forceinline__ void load_stage(u32 sb,
    const half* __restrict__ Ah, const half* __restrict__ Al,
    const half* __restrict__ Bh, const half* __restrict__ Bl,
    int bm, int bn, int k0, int K, int N, int tid)
{
    constexpr int BOFF = ATILE * (ASPLIT ? 2 : 1);
    #pragma unroll
    for (int i = 0; i < 2; i++) {
        int u = tid + i * 256;
        int r = u >> 2, c = u & 3;
        long long g = (long long)(bm + r) * K + k0 + c * 8;
        cpa16(sb + r * APITCH + c * 16, Ah + g);
        if (ASPLIT) cpa16(sb + ATILE + r * APITCH + c * 16, Al + g);
    }
    #pragma unroll
    for (int i = 0; i < 2; i++) {
        int u = tid + i * 256;
        int r = u >> 4, c = u & 15;
        long long g = (long long)(k0 + r) * N + bn + c * 8;
        cpa16(sb + BOFF + r * BPITCH + c * 16, Bh + g);
        if (BSPLIT) cpa16(sb + BOFF + BTILE + r * BPITCH + c * 16, Bl + g);
    }
}

template<bool ASPLIT, bool BSPLIT, int OMODE>
__global__ __launch_bounds__(256)
void mmagemm(const half* __restrict__ Ah, const half* __restrict__ Al,
             const half* __restrict__ Bh, const half* __restrict__ Bl,
             const float* __restrict__ bias, float oscale,
             float* __restrict__ Cf, half* __restrict__ Ch, half* __restrict__ Cl,
             int M, int N, int K, long long sA, long long sB, long long sC)
{
    constexpr int BOFF = ATILE * (ASPLIT ? 2 : 1);
    constexpr int STG  = BOFF + BTILE * (BSPLIT ? 2 : 1);

    extern __shared__ char dsm[];
    u32 sbase = smem_u32(dsm);

    const int tid = threadIdx.x;
    const int wid = tid >> 5, lane = tid & 31;
    const int bn = blockIdx.x * 128, bm = blockIdx.y * 128, z = blockIdx.z;
    Ah += (long long)z * sA; if (ASPLIT) Al += (long long)z * sA;
    Bh += (long long)z * sB; if (BSPLIT) Bl += (long long)z * sB;

    const int wm = (wid >> 2) * 64;
    const int wn = (wid & 3) * 32;

    float acc[4][4][4] = {};

    const int NC = K >> 5;
    load_stage<ASPLIT, BSPLIT>(sbase, Ah, Al, Bh, Bl, bm, bn, 0, K, N, tid);
    CP_COMMIT();

    const int arow = lane & 15;
    const int ak8  = ((lane >> 4) & 1) * 8;
    const int bk   = lane & 15;
    const int bn8  = ((lane >> 4) & 1) * 8;

    for (int c = 0; c < NC; c++) {
        if (c + 1 < NC) {
            load_stage<ASPLIT, BSPLIT>(sbase + ((c + 1) & 1) * STG,
                Ah, Al, Bh, Bl, bm, bn, (c + 1) << 5, K, N, tid);
            CP_COMMIT();
            CP_WAIT(1);
        } else {
            CP_WAIT(0);
        }
        __syncthreads();

        u32 st = sbase + (c & 1) * STG;
        u32 As = st, Als = st + ATILE;
        u32 Bs = st + BOFF, Bls = Bs + BTILE;

        #pragma unroll
        for (int ks = 0; ks < 32; ks += 16) {
            u32 bh[2][4], bl[2][4];
            #pragma unroll
            for (int n2 = 0; n2 < 2; n2++) {
                u32 boff = (ks + bk) * BPITCH + (wn + 16 * n2 + bn8) * 2;
                ldsm4t(bh[n2], Bs + boff);
                if (BSPLIT) ldsm4t(bl[n2], Bls + boff);
            }
            #pragma unroll
            for (int m = 0; m < 4; m++) {
                u32 ah[4], al[4];
                u32 aoff = (wm + 16 * m + arow) * APITCH + (ks + ak8) * 2;
                ldsm4(ah, As + aoff);
                if (ASPLIT) ldsm4(al, Als + aoff);
                #pragma unroll
                for (int j = 0; j < 4; j++) {
                    const u32* bhp = &bh[j >> 1][(j & 1) * 2];
                    mma16816(acc[m][j], ah, bhp);
                    if (ASPLIT) mma16816(acc[m][j], al, bhp);
                    if (BSPLIT) {
                        const u32* blp = &bl[j >> 1][(j & 1) * 2];
                        mma16816(acc[m][j], ah, blp);
                    }
                }
            }
        }
        __syncthreads();
    }

    // ------------------------------ epilogue -------------------------------
    const int trow = lane >> 2;
    const int tcol = (lane & 3) * 2;

    #pragma unroll
    for (int m = 0; m < 4; m++) {
        #pragma unroll
        for (int j = 0; j < 4; j++) {
            int col = bn + wn + 8 * j + tcol;
            float b0 = bias ? bias[col] : 0.f;
            float b1 = bias ? bias[col + 1] : 0.f;
            #pragma unroll
            for (int h = 0; h < 2; h++) {
                long long row = bm + wm + 16 * m + trow + h * 8;
                float v0 = acc[m][j][2 * h + 0] * oscale + b0;
                float v1 = acc[m][j][2 * h + 1] * oscale + b1;
                long long idx = (long long)z * sC + row * N + col;
                if (OMODE == 0) {
                    *(float2*)(Cf + idx) = make_float2(v0, v1);
                } else if (OMODE == 2) {
                    *(half2*)(Ch + idx) = __floats2half2_rn(v0, v1);
                } else {
                    half h0 = __float2half_rn(v0);
                    half h1 = __float2half_rn(v1);
                    *(half2*)(Ch + idx) = __halves2half2(h0, h1);
                    *(half2*)(Cl + idx) = __floats2half2_rn(
                        v0 - __half2float(h0), v1 - __half2float(h1));
                }
            }
        }
    }
}

// ---------------------------------------------------------------------------
extern "C" void kernel_launch(void* const* d_in, const int* in_sizes, int n_in,
                              void* d_out, int out_size)
{
    const float* x  = (const float*)d_in[0];
    const float* Wq = (const float*)d_in[1];
    const float* bq = (const float*)d_in[2];
    const float* Wk = (const float*)d_in[3];
    const float* bk = (const float*)d_in[4];
    const float* Wv = (const float*)d_in[5];
    const float* bv = (const float*)d_in[6];
    const float* We = (const float*)d_in[7];
    const float* be = (const float*)d_in[8];
    const float* Wo = (const float*)d_in[9];
    const float* bo = (const float*)d_in[10];
    float* out = (float*)d_out;

    half *xh, *Wvh, *Wvl, *Woh, *Wol, *W2h, *W2l, *v2h, *anh, *anl;
    float* b2;
    cudaGetSymbolAddress((void**)&xh,  g_xh);
    cudaGetSymbolAddress((void**)&Wvh, g_Wvh);
    cudaGetSymbolAddress((void**)&Wvl, g_Wvl);
    cudaGetSymbolAddress((void**)&Woh, g_Woh);
    cudaGetSymbolAddress((void**)&Wol, g_Wol);
    cudaGetSymbolAddress((void**)&W2h, g_W2h);
    cudaGetSymbolAddress((void**)&W2l, g_W2l);
    cudaGetSymbolAddress((void**)&v2h, g_v2h);
    cudaGetSymbolAddress((void**)&anh, g_attnh);
    cudaGetSymbolAddress((void**)&anl, g_attnl);
    cudaGetSymbolAddress((void**)&b2,  g_b2);

    // dynamic smem sizes
    const int SM_PRE = H_ * 17 * 4;                       // 69632
    const int SM_EMB = (32 * H_ + 2 * H_) * 4;            // 139264
    const int SM_W2  = 2 * (2 * ATILE + 2 * BTILE);       // 75776
    const int SM_V2  = 2 * (1 * ATILE + 2 * BTILE);       // 55296
    const int SM_OUT = 2 * (2 * ATILE + 1 * BTILE);       // 58368

    cudaFuncSetAttribute(precompute_kernel, cudaFuncAttributeMaxDynamicSharedMemorySize, SM_PRE);
    cudaFuncSetAttribute(embed_kernel,      cudaFuncAttributeMaxDynamicSharedMemorySize, SM_EMB);
    cudaFuncSetAttribute(mmagemm<true,true,1>,   cudaFuncAttributeMaxDynamicSharedMemorySize, SM_W2);
    cudaFuncSetAttribute(mmagemm<false,true,2>,  cudaFuncAttributeMaxDynamicSharedMemorySize, SM_V2);
    cudaFuncSetAttribute(mmagemm<true,false,0>,  cudaFuncAttributeMaxDynamicSharedMemorySize, SM_OUT);

    // 1) fold We into Wq/Wk (+biases);  b2 = bv @ Wo
    precompute_kernel<<<257, 256, SM_PRE>>>(Wq, Wk, We, bq, bk, be);
    b2_kernel<<<H_ / 256, 256>>>(bv, Wo);
    // 2) q_q / k_q embeddings
    embed_kernel<<<ROWS_ / ERB, 256, SM_EMB>>>(x);
    // 3) fp16 casts: x (hi only), Wv/Wo (hi+lo)
    split_h<<<ROWS_ * H_ / 4 / 256, 256>>>(x, xh);
    split_hl<<<H_ * H_ / 4 / 256, 256>>>(Wv, Wvh, Wvl);
    split_hl<<<H_ * H_ / 4 / 256, 256>>>(Wo, Woh, Wol);
    // 4) softmax probs (x1024) -> fp16 split
    attn_kernel<<<dim3(S_ / 8, B_), 256>>>(anh, anl);
    // 5) W2 = Wv @ Wo   (3-term, fp16 split out)
    mmagemm<true,true,1><<<dim3(8, 8, 1), 256, SM_W2>>>(
        Wvh, Wvl, Woh, Wol, nullptr, 1.f, nullptr, W2h, W2l,
        H_, H_, H_, 0, 0, 0);
    // 6) v2 = x @ W2 + b2   (2-term: xh*(W2h+W2l), fp16 plain out)
    mmagemm<false,true,2><<<dim3(8, 64, 1), 256, SM_V2>>>(
        xh, nullptr, W2h, W2l, b2, 1.f, nullptr, v2h, nullptr,
        ROWS_, H_, H_, 0, 0, 0);
    // 7) out = attn @ v2 * 2^-10 + bo   (2-term: (Ah+Al)*v2h, fp32 out)
    mmagemm<true,false,0><<<dim3(8, 16, 4), 256, SM_OUT>>>(
        anh, anl, v2h, nullptr, bo, 1.f / 1024.f, out, nullptr, nullptr,
        S_, H_, S_, (long long)S_ * S_, (long long)S_ * H_, (long long)S_ * H_);
}

// round 5
// speedup vs baseline: 4.1178x; 1.2894x over previous
#include <cuda_runtime.h>
#include <cuda_fp16.h>

// ---------------------------------------------------------------------------
// QuantumAttention, restructured:
//   out = attn @ (x @ (Wv@Wo) + bv@Wo) + bo,  attn = softmax((q_q.k_q)^2)
//   q_q = normalize(x @ (Wq@We) + (bq@We+be)), k_q likewise.
// GEMMs on mma.sync fp16 (fp32 accum); W2=Wv@Wo in 3-term split-fp16,
// main-path GEMMs single-term (validated random-sign noise model: ~5e-4).
// ---------------------------------------------------------------------------

#define B_ 4
#define S_ 2048
#define H_ 1024
#define QD_ 16
#define ROWS_ (B_ * S_)          // 8192

typedef unsigned int u32;

// ------------------------------- scratch ----------------------------------
__device__ float g_WqeT[QD_ * H_];
__device__ float g_WkeT[QD_ * H_];
__device__ float g_bqe[QD_];
__device__ float g_bke[QD_];
__device__ float g_qq[ROWS_ * QD_];
__device__ float g_kq[ROWS_ * QD_];
__device__ float g_b2[H_];

__device__ half g_xh[ROWS_ * H_];
__device__ half g_Wvh[H_ * H_];
__device__ half g_Wvl[H_ * H_];
__device__ half g_Woh[H_ * H_];
__device__ half g_Wol[H_ * H_];
__device__ half g_W2h[H_ * H_];
__device__ half g_v2h[ROWS_ * H_];
__device__ half g_attnh[(long long)B_ * S_ * S_];

// ----------------------------- PTX helpers --------------------------------
__device__ __forceinline__ u32 smem_u32(const void* p) {
    u32 a;
    asm("{ .reg .u64 t; cvta.to.shared.u64 t, %1; cvt.u32.u64 %0, t; }"
        : "=r"(a) : "l"(p));
    return a;
}
__device__ __forceinline__ void cpa16(u32 d, const void* g) {
    asm volatile("cp.async.cg.shared.global [%0], [%1], 16;" :: "r"(d), "l"(g));
}
#define CP_COMMIT() asm volatile("cp.async.commit_group;" ::: "memory")
#define CP_WAIT(n)  asm volatile("cp.async.wait_group %0;" :: "n"(n) : "memory")

__device__ __forceinline__ void ldsm4(u32* r, u32 a) {
    asm volatile("ldmatrix.sync.aligned.m8n8.x4.shared.b16 {%0,%1,%2,%3}, [%4];"
        : "=r"(r[0]), "=r"(r[1]), "=r"(r[2]), "=r"(r[3]) : "r"(a));
}
__device__ __forceinline__ void ldsm4t(u32* r, u32 a) {
    asm volatile("ldmatrix.sync.aligned.m8n8.x4.trans.shared.b16 {%0,%1,%2,%3}, [%4];"
        : "=r"(r[0]), "=r"(r[1]), "=r"(r[2]), "=r"(r[3]) : "r"(a));
}
__device__ __forceinline__ void mma16816(float* d, const u32* a, const u32* b) {
    asm volatile("mma.sync.aligned.m16n8k16.row.col.f32.f16.f16.f32 "
        "{%0,%1,%2,%3}, {%4,%5,%6,%7}, {%8,%9}, {%0,%1,%2,%3};"
        : "+f"(d[0]), "+f"(d[1]), "+f"(d[2]), "+f"(d[3])
        : "r"(a[0]), "r"(a[1]), "r"(a[2]), "r"(a[3]), "r"(b[0]), "r"(b[1]));
}

// ------------------- 1) fold We into Wq/Wk (warp per row) ------------------
__global__ __launch_bounds__(256)
void precompute_kernel(const float* __restrict__ Wq,
                       const float* __restrict__ Wk,
                       const float* __restrict__ We,
                       const float* __restrict__ bq,
                       const float* __restrict__ bk,
                       const float* __restrict__ be)
{
    extern __shared__ float Wes[];          // [1024][17] padded
    int tid = threadIdx.x;
    for (int idx = tid; idx < H_ * QD_; idx += 256)
        Wes[(idx >> 4) * 17 + (idx & 15)] = We[idx];
    __syncthreads();

    int wg = blockIdx.x * 8 + (tid >> 5);
    if (wg >= 2 * (H_ + 1)) return;
    int m = wg / (H_ + 1);
    int i = wg % (H_ + 1);
    int lane = tid & 31;
    const float* W  = m ? Wk : Wq;
    const float* bb = m ? bk : bq;

    float p[QD_];
    #pragma unroll
    for (int o = 0; o < QD_; o++) p[o] = 0.f;

    for (int kk = 0; kk < H_ / 32; kk++) {
        int k = kk * 32 + lane;
        float w = (i < H_) ? W[(long long)i * H_ + k] : bb[k];
        const float* wr = &Wes[k * 17];
        #pragma unroll
        for (int o = 0; o < QD_; o++) p[o] = fmaf(w, wr[o], p[o]);
    }
    #pragma unroll
    for (int off = 16; off; off >>= 1)
        #pragma unroll
        for (int o = 0; o < QD_; o++)
            p[o] += __shfl_xor_sync(0xffffffffu, p[o], off);

    if (lane == 0) {
        if (i < H_) {
            float* dst = m ? g_WkeT : g_WqeT;
            #pragma unroll
            for (int o = 0; o < QD_; o++) dst[o * H_ + i] = p[o];
        } else {
            float* dst = m ? g_bke : g_bqe;
            #pragma unroll
            for (int o = 0; o < QD_; o++) dst[o] = p[o] + be[o];
        }
    }
}

// ---------------------- 1b) b2 = bv @ Wo  (1024-vector) --------------------
__global__ __launch_bounds__(256)
void b2_kernel(const float* __restrict__ bv, const float* __restrict__ Wo)
{
    int n = blockIdx.x * 256 + threadIdx.x;
    float s = 0.f;
    #pragma unroll 8
    for (int k = 0; k < H_; k++)
        s = fmaf(bv[k], Wo[(long long)k * H_ + n], s);
    g_b2[n] = s;
}

// ---- 2) embed: 64 rows/block, W staged in smem; also emits xh (fp16) ------
#define ERB 64
__global__ __launch_bounds__(256)
void embed_kernel(const float* __restrict__ x)
{
    extern __shared__ float sm[];
    float* Ws = sm;                       // [32][1024]: 16 q dims then 16 k
    float* xb = sm + 32 * H_;             // [2][1024] double buffer
    __shared__ float zbuf[32];

    int tid = threadIdx.x, lane = tid & 31, w = tid >> 5;

    for (int idx = tid; idx < QD_ * H_; idx += 256) {
        Ws[idx]            = g_WqeT[idx];
        Ws[QD_ * H_ + idx] = g_WkeT[idx];
    }
    long long row0 = (long long)blockIdx.x * ERB;

    float4 nxt = *(const float4*)&x[row0 * H_ + tid * 4];
    *(float4*)&xb[tid * 4] = nxt;
    {   // fused fp16 cast of row 0
        half2* xp = (half2*)&g_xh[row0 * H_ + tid * 4];
        xp[0] = __floats2half2_rn(nxt.x, nxt.y);
        xp[1] = __floats2half2_rn(nxt.z, nxt.w);
    }
    __syncthreads();

    for (int r = 0; r < ERB; r++) {
        if (r + 1 < ERB) {
            nxt = *(const float4*)&x[(row0 + r + 1) * H_ + tid * 4];
            half2* xp = (half2*)&g_xh[(row0 + r + 1) * H_ + tid * 4];
            xp[0] = __floats2half2_rn(nxt.x, nxt.y);
            xp[1] = __floats2half2_rn(nxt.z, nxt.w);
        }

        const float* xs = xb + (r & 1) * H_;
        float xr[32];
        #pragma unroll
        for (int i = 0; i < 8; i++)
            *(float4*)&xr[i * 4] = *(const float4*)&xs[i * 128 + lane * 4];

        #pragma unroll
        for (int oo = 0; oo < 4; oo++) {
            int o = w * 4 + oo;
            const float* wrow = Ws + o * H_;
            float s = 0.f;
            #pragma unroll
            for (int i = 0; i < 8; i++) {
                float4 wv = *(const float4*)&wrow[i * 128 + lane * 4];
                s += xr[i*4]*wv.x + xr[i*4+1]*wv.y + xr[i*4+2]*wv.z + xr[i*4+3]*wv.w;
            }
            #pragma unroll
            for (int off = 16; off; off >>= 1)
                s += __shfl_xor_sync(0xffffffffu, s, off);
            if (lane == 0) zbuf[o] = s;
        }
        __syncthreads();

        if (tid < 32) {
            int o = tid & 15;
            bool isq = tid < 16;
            float z = zbuf[tid] + (isq ? g_bqe[o] : g_bke[o]);
            float sq = z * z;
            #pragma unroll
            for (int off = 8; off; off >>= 1)
                sq += __shfl_xor_sync(0xffffffffu, sq, off);
            float val = z * rsqrtf(sq + 1e-8f);
            (isq ? g_qq : g_kq)[(row0 + r) * QD_ + o] = val;
        }
        if (r + 1 < ERB)
            *(float4*)&xb[((r + 1) & 1) * H_ + tid * 4] = nxt;
        __syncthreads();
    }
}

// --------------------- 3) fp32 -> fp16 hi+lo (weights) ---------------------
__global__ __launch_bounds__(256)
void split_hl(const float* __restrict__ src,
              half* __restrict__ h, half* __restrict__ l)
{
    int i = blockIdx.x * 256 + threadIdx.x;
    float4 v = ((const float4*)src)[i];
    half h0 = __float2half_rn(v.x), h1 = __float2half_rn(v.y);
    half h2 = __float2half_rn(v.z), h3 = __float2half_rn(v.w);
    half2* hp = (half2*)h;
    half2* lp = (half2*)l;
    hp[2*i]   = __halves2half2(h0, h1);
    hp[2*i+1] = __halves2half2(h2, h3);
    lp[2*i]   = __floats2half2_rn(v.x - __half2float(h0), v.y - __half2float(h1));
    lp[2*i+1] = __floats2half2_rn(v.z - __half2float(h2), v.w - __half2float(h3));
}

// ---------------- 4) scores + softmax -> fp16 probs (hi only) --------------
__global__ __launch_bounds__(256)
void attn_kernel(half* __restrict__ ah)
{
    int b = blockIdx.y;
    int q0 = blockIdx.x * 8;
    int tid = threadIdx.x;
    int lane = tid & 31, wid = tid >> 5;

    __shared__ float qs[8][QD_];
    __shared__ float red[8][9];

    if (tid < 128)
        ((float*)qs)[tid] = g_qq[((long long)b * S_ + q0) * QD_ + tid];
    __syncthreads();

    const float* kq = g_kq + (long long)b * S_ * QD_;
    float e[8][8];
    float sum[8] = {};

    #pragma unroll
    for (int j = 0; j < 8; j++) {
        int kk = tid + j * 256;
        const float4* kp = (const float4*)(kq + (long long)kk * QD_);
        float4 k0 = kp[0], k1 = kp[1], k2 = kp[2], k3 = kp[3];
        #pragma unroll
        for (int q = 0; q < 8; q++) {
            const float* qr = qs[q];
            float ov = qr[0]*k0.x + qr[1]*k0.y + qr[2]*k0.z + qr[3]*k0.w
                     + qr[4]*k1.x + qr[5]*k1.y + qr[6]*k1.z + qr[7]*k1.w
                     + qr[8]*k2.x + qr[9]*k2.y + qr[10]*k2.z + qr[11]*k2.w
                     + qr[12]*k3.x + qr[13]*k3.y + qr[14]*k3.z + qr[15]*k3.w;
            float ee = __expf(ov * ov);
            e[q][j] = ee;
            sum[q] += ee;
        }
    }

    #pragma unroll
    for (int q = 0; q < 8; q++) {
        float s = sum[q];
        #pragma unroll
        for (int off = 16; off; off >>= 1)
            s += __shfl_xor_sync(0xffffffffu, s, off);
        if (lane == 0) red[wid][q] = s;
    }
    __syncthreads();

    float inv[8];
    #pragma unroll
    for (int q = 0; q < 8; q++) {
        float t = 0.f;
        #pragma unroll
        for (int w = 0; w < 8; w++) t += red[w][q];
        inv[q] = 1.f / t;
    }

    #pragma unroll
    for (int q = 0; q < 8; q++) {
        long long rowo = ((long long)b * S_ + q0 + q) * S_;
        #pragma unroll
        for (int j = 0; j < 8; j++)
            ah[rowo + tid + j * 256] = __float2half_rn(e[q][j] * inv[q]);
    }
}

// --------------- 5) split-fp16 GEMM on mma.sync (templated) ----------------
// C[M,N] = A[M,K] @ B[K,N]; terms: AhBh (+AlBh if ASPLIT)(+AhBl if BSPLIT).
// OMODE 0: fp32 out = acc + bias; 2: fp16 plain out (+bias).
#define APITCH 80                      // 32 half = 64B + 16 pad
#define BPITCH 272                     // 128 half = 256B + 16 pad
#define ATILE (128 * APITCH)           // 10240
#define BTILE (32 * BPITCH)            // 8704

template<bool ASPLIT, bool BSPLIT>
__device__ __forceinline__ void load_stage(u32 sb,
    const half* __restrict__ Ah, const half* __restrict__ Al,
    const half* __restrict__ Bh, const half* __restrict__ Bl,
    int bm, int bn, int k0, int K, int N, int tid)
{
    constexpr int BOFF = ATILE * (ASPLIT ? 2 : 1);
    #pragma unroll
    for (int i = 0; i < 2; i++) {
        int u = tid + i * 256;
        int r = u >> 2, c = u & 3;
        long long g = (long long)(bm + r) * K + k0 + c * 8;
        cpa16(sb + r * APITCH + c * 16, Ah + g);
        if (ASPLIT) cpa16(sb + ATILE + r * APITCH + c * 16, Al + g);
    }
    #pragma unroll
    for (int i = 0; i < 2; i++) {
        int u = tid + i * 256;
        int r = u >> 4, c = u & 15;
        long long g = (long long)(k0 + r) * N + bn + c * 8;
        cpa16(sb + BOFF + r * BPITCH + c * 16, Bh + g);
        if (BSPLIT) cpa16(sb + BOFF + BTILE + r * BPITCH + c * 16, Bl + g);
    }
}

template<bool ASPLIT, bool BSPLIT, int OMODE>
__global__ __launch_bounds__(256)
void mmagemm(const half* __restrict__ Ah, const half* __restrict__ Al,
             const half* __restrict__ Bh, const half* __restrict__ Bl,
             const float* __restrict__ bias,
             float* __restrict__ Cf, half* __restrict__ Ch,
             int M, int N, int K, long long sA, long long sB, long long sC)
{
    constexpr int BOFF = ATILE * (ASPLIT ? 2 : 1);
    constexpr int STG  = BOFF + BTILE * (BSPLIT ? 2 : 1);

    extern __shared__ char dsm[];
    u32 sbase = smem_u32(dsm);

    const int tid = threadIdx.x;
    const int wid = tid >> 5, lane = tid & 31;
    const int bn = blockIdx.x * 128, bm = blockIdx.y * 128, z = blockIdx.z;
    Ah += (long long)z * sA; if (ASPLIT) Al += (long long)z * sA;
    Bh += (long long)z * sB; if (BSPLIT) Bl += (long long)z * sB;

    const int wm = (wid >> 2) * 64;
    const int wn = (wid & 3) * 32;

    float acc[4][4][4] = {};

    const int NC = K >> 5;
    load_stage<ASPLIT, BSPLIT>(sbase, Ah, Al, Bh, Bl, bm, bn, 0, K, N, tid);
    CP_COMMIT();

    const int arow = lane & 15;
    const int ak8  = ((lane >> 4) & 1) * 8;
    const int bk   = lane & 15;
    const int bn8  = ((lane >> 4) & 1) * 8;

    for (int c = 0; c < NC; c++) {
        if (c + 1 < NC) {
            load_stage<ASPLIT, BSPLIT>(sbase + ((c + 1) & 1) * STG,
                Ah, Al, Bh, Bl, bm, bn, (c + 1) << 5, K, N, tid);
            CP_COMMIT();
            CP_WAIT(1);
        } else {
            CP_WAIT(0);
        }
        __syncthreads();

        u32 st = sbase + (c & 1) * STG;
        u32 As = st, Als = st + ATILE;
        u32 Bs = st + BOFF, Bls = Bs + BTILE;

        #pragma unroll
        for (int ks = 0; ks < 32; ks += 16) {
            u32 bh[2][4], bl[2][4];
            #pragma unroll
            for (int n2 = 0; n2 < 2; n2++) {
                u32 boff = (ks + bk) * BPITCH + (wn + 16 * n2 + bn8) * 2;
                ldsm4t(bh[n2], Bs + boff);
                if (BSPLIT) ldsm4t(bl[n2], Bls + boff);
            }
            #pragma unroll
            for (int m = 0; m < 4; m++) {
                u32 ah[4], al[4];
                u32 aoff = (wm + 16 * m + arow) * APITCH + (ks + ak8) * 2;
                ldsm4(ah, As + aoff);
                if (ASPLIT) ldsm4(al, Als + aoff);
                #pragma unroll
                for (int j = 0; j < 4; j++) {
                    const u32* bhp = &bh[j >> 1][(j & 1) * 2];
                    mma16816(acc[m][j], ah, bhp);
                    if (ASPLIT) mma16816(acc[m][j], al, bhp);
                    if (BSPLIT) {
                        const u32* blp = &bl[j >> 1][(j & 1) * 2];
                        mma16816(acc[m][j], ah, blp);
                    }
                }
            }
        }
        __syncthreads();
    }

    // ------------------------------ epilogue -------------------------------
    const int trow = lane >> 2;
    const int tcol = (lane & 3) * 2;

    #pragma unroll
    for (int m = 0; m < 4; m++) {
        #pragma unroll
        for (int j = 0; j < 4; j++) {
            int col = bn + wn + 8 * j + tcol;
            float b0 = bias ? bias[col] : 0.f;
            float b1 = bias ? bias[col + 1] : 0.f;
            #pragma unroll
            for (int h = 0; h < 2; h++) {
                long long row = bm + wm + 16 * m + trow + h * 8;
                float v0 = acc[m][j][2 * h + 0] + b0;
                float v1 = acc[m][j][2 * h + 1] + b1;
                long long idx = (long long)z * sC + row * N + col;
                if (OMODE == 0)
                    *(float2*)(Cf + idx) = make_float2(v0, v1);
                else
                    *(half2*)(Ch + idx) = __floats2half2_rn(v0, v1);
            }
        }
    }
}

// ---------------------------------------------------------------------------
extern "C" void kernel_launch(void* const* d_in, const int* in_sizes, int n_in,
                              void* d_out, int out_size)
{
    const float* x  = (const float*)d_in[0];
    const float* Wq = (const float*)d_in[1];
    const float* bq = (const float*)d_in[2];
    const float* Wk = (const float*)d_in[3];
    const float* bk = (const float*)d_in[4];
    const float* Wv = (const float*)d_in[5];
    const float* bv = (const float*)d_in[6];
    const float* We = (const float*)d_in[7];
    const float* be = (const float*)d_in[8];
    const float* Wo = (const float*)d_in[9];
    const float* bo = (const float*)d_in[10];
    float* out = (float*)d_out;

    half *xh, *Wvh, *Wvl, *Woh, *Wol, *W2h, *v2h, *anh;
    float* b2;
    cudaGetSymbolAddress((void**)&xh,  g_xh);
    cudaGetSymbolAddress((void**)&Wvh, g_Wvh);
    cudaGetSymbolAddress((void**)&Wvl, g_Wvl);
    cudaGetSymbolAddress((void**)&Woh, g_Woh);
    cudaGetSymbolAddress((void**)&Wol, g_Wol);
    cudaGetSymbolAddress((void**)&W2h, g_W2h);
    cudaGetSymbolAddress((void**)&v2h, g_v2h);
    cudaGetSymbolAddress((void**)&anh, g_attnh);
    cudaGetSymbolAddress((void**)&b2,  g_b2);

    const int SM_PRE = H_ * 17 * 4;                       // 69632
    const int SM_EMB = (32 * H_ + 2 * H_) * 4;            // 139264
    const int SM_W2  = 2 * (2 * ATILE + 2 * BTILE);       // 75776
    const int SM_1T  = 2 * (ATILE + BTILE);               // 37888

    cudaFuncSetAttribute(precompute_kernel, cudaFuncAttributeMaxDynamicSharedMemorySize, SM_PRE);
    cudaFuncSetAttribute(embed_kernel,      cudaFuncAttributeMaxDynamicSharedMemorySize, SM_EMB);
    cudaFuncSetAttribute(mmagemm<true,true,2>,   cudaFuncAttributeMaxDynamicSharedMemorySize, SM_W2);
    cudaFuncSetAttribute(mmagemm<false,false,2>, cudaFuncAttributeMaxDynamicSharedMemorySize, SM_1T);
    cudaFuncSetAttribute(mmagemm<false,false,0>, cudaFuncAttributeMaxDynamicSharedMemorySize, SM_1T);

    // 1) fold We into Wq/Wk (+biases);  b2 = bv @ Wo
    precompute_kernel<<<257, 256, SM_PRE>>>(Wq, Wk, We, bq, bk, be);
    b2_kernel<<<H_ / 256, 256>>>(bv, Wo);
    // 2) q_q / k_q embeddings (+ fused x -> fp16 cast)
    embed_kernel<<<ROWS_ / ERB, 256, SM_EMB>>>(x);
    // 3) fp16 hi/lo splits of Wv, Wo (for the 3-term W2 GEMM)
    split_hl<<<H_ * H_ / 4 / 256, 256>>>(Wv, Wvh, Wvl);
    split_hl<<<H_ * H_ / 4 / 256, 256>>>(Wo, Woh, Wol);
    // 4) softmax probs -> fp16 (hi only)
    attn_kernel<<<dim3(S_ / 8, B_), 256>>>(anh);
    // 5) W2 = Wv @ Wo   (3-term split, fp16 out)
    mmagemm<true,true,2><<<dim3(8, 8, 1), 256, SM_W2>>>(
        Wvh, Wvl, Woh, Wol, nullptr, nullptr, W2h,
        H_, H_, H_, 0, 0, 0);
    // 6) v2 = xh @ W2h + b2   (1-term, fp16 out)
    mmagemm<false,false,2><<<dim3(8, 64, 1), 256, SM_1T>>>(
        xh, nullptr, W2h, nullptr, b2, nullptr, v2h,
        ROWS_, H_, H_, 0, 0, 0);
    // 7) out = attn @ v2 + bo   (1-term, fp32 out, batched over B)
    mmagemm<false,false,0><<<dim3(8, 16, 4), 256, SM_1T>>>(
        anh, nullptr, v2h, nullptr, bo, out, nullptr,
        S_, H_, S_, (long long)S_ * S_, (long long)S_ * H_, (long long)S_ * H_);
}

// round 6
// speedup vs baseline: 4.2408x; 1.0299x over previous
#include <cuda_runtime.h>
#include <cuda_fp16.h>

// ---------------------------------------------------------------------------
// QuantumAttention, restructured:
//   out = attn @ (x @ (Wv@Wo) + bv@Wo) + bo,  attn = softmax((q_q.k_q)^2)
//   q_q = normalize(x @ (Wq@We) + (bq@We+be)), k_q likewise.
// GEMMs on mma.sync fp16 (fp32 accum); W2=Wv@Wo 3-term split-fp16, main-path
// 1-term. R6: 3-stage cp.async pipeline, 1 sync/chunk, 2 CTAs/SM.
// ---------------------------------------------------------------------------

#define B_ 4
#define S_ 2048
#define H_ 1024
#define QD_ 16
#define ROWS_ (B_ * S_)          // 8192

typedef unsigned int u32;

// ------------------------------- scratch ----------------------------------
__device__ float g_WqeT[QD_ * H_];
__device__ float g_WkeT[QD_ * H_];
__device__ float g_bqe[QD_];
__device__ float g_bke[QD_];
__device__ float g_qq[ROWS_ * QD_];
__device__ float g_kq[ROWS_ * QD_];
__device__ float g_b2[H_];

__device__ half g_xh[ROWS_ * H_];
__device__ half g_Wvh[H_ * H_];
__device__ half g_Wvl[H_ * H_];
__device__ half g_Woh[H_ * H_];
__device__ half g_Wol[H_ * H_];
__device__ half g_W2h[H_ * H_];
__device__ half g_v2h[ROWS_ * H_];
__device__ half g_attnh[(long long)B_ * S_ * S_];

// ----------------------------- PTX helpers --------------------------------
__device__ __forceinline__ u32 smem_u32(const void* p) {
    u32 a;
    asm("{ .reg .u64 t; cvta.to.shared.u64 t, %1; cvt.u32.u64 %0, t; }"
        : "=r"(a) : "l"(p));
    return a;
}
__device__ __forceinline__ void cpa16(u32 d, const void* g) {
    asm volatile("cp.async.cg.shared.global [%0], [%1], 16;" :: "r"(d), "l"(g));
}
#define CP_COMMIT() asm volatile("cp.async.commit_group;" ::: "memory")
#define CP_WAIT(n)  asm volatile("cp.async.wait_group %0;" :: "n"(n) : "memory")

__device__ __forceinline__ void ldsm4(u32* r, u32 a) {
    asm volatile("ldmatrix.sync.aligned.m8n8.x4.shared.b16 {%0,%1,%2,%3}, [%4];"
        : "=r"(r[0]), "=r"(r[1]), "=r"(r[2]), "=r"(r[3]) : "r"(a));
}
__device__ __forceinline__ void ldsm4t(u32* r, u32 a) {
    asm volatile("ldmatrix.sync.aligned.m8n8.x4.trans.shared.b16 {%0,%1,%2,%3}, [%4];"
        : "=r"(r[0]), "=r"(r[1]), "=r"(r[2]), "=r"(r[3]) : "r"(a));
}
__device__ __forceinline__ void mma16816(float* d, const u32* a, const u32* b) {
    asm volatile("mma.sync.aligned.m16n8k16.row.col.f32.f16.f16.f32 "
        "{%0,%1,%2,%3}, {%4,%5,%6,%7}, {%8,%9}, {%0,%1,%2,%3};"
        : "+f"(d[0]), "+f"(d[1]), "+f"(d[2]), "+f"(d[3])
        : "r"(a[0]), "r"(a[1]), "r"(a[2]), "r"(a[3]), "r"(b[0]), "r"(b[1]));
}

// ------------------- 1) fold We into Wq/Wk (warp per row) ------------------
__global__ __launch_bounds__(256)
void precompute_kernel(const float* __restrict__ Wq,
                       const float* __restrict__ Wk,
                       const float* __restrict__ We,
                       const float* __restrict__ bq,
                       const float* __restrict__ bk,
                       const float* __restrict__ be)
{
    extern __shared__ float Wes[];          // [1024][17] padded
    int tid = threadIdx.x;
    for (int idx = tid; idx < H_ * QD_; idx += 256)
        Wes[(idx >> 4) * 17 + (idx & 15)] = We[idx];
    __syncthreads();

    int wg = blockIdx.x * 8 + (tid >> 5);
    if (wg >= 2 * (H_ + 1)) return;
    int m = wg / (H_ + 1);
    int i = wg % (H_ + 1);
    int lane = tid & 31;
    const float* W  = m ? Wk : Wq;
    const float* bb = m ? bk : bq;

    float p[QD_];
    #pragma unroll
    for (int o = 0; o < QD_; o++) p[o] = 0.f;

    for (int kk = 0; kk < H_ / 32; kk++) {
        int k = kk * 32 + lane;
        float w = (i < H_) ? W[(long long)i * H_ + k] : bb[k];
        const float* wr = &Wes[k * 17];
        #pragma unroll
        for (int o = 0; o < QD_; o++) p[o] = fmaf(w, wr[o], p[o]);
    }
    #pragma unroll
    for (int off = 16; off; off >>= 1)
        #pragma unroll
        for (int o = 0; o < QD_; o++)
            p[o] += __shfl_xor_sync(0xffffffffu, p[o], off);

    if (lane == 0) {
        if (i < H_) {
            float* dst = m ? g_WkeT : g_WqeT;
            #pragma unroll
            for (int o = 0; o < QD_; o++) dst[o * H_ + i] = p[o];
        } else {
            float* dst = m ? g_bke : g_bqe;
            #pragma unroll
            for (int o = 0; o < QD_; o++) dst[o] = p[o] + be[o];
        }
    }
}

// ---------------------- 1b) b2 = bv @ Wo  (1024-vector) --------------------
__global__ __launch_bounds__(256)
void b2_kernel(const float* __restrict__ bv, const float* __restrict__ Wo)
{
    int n = blockIdx.x * 256 + threadIdx.x;
    float s = 0.f;
    #pragma unroll 8
    for (int k = 0; k < H_; k++)
        s = fmaf(bv[k], Wo[(long long)k * H_ + n], s);
    g_b2[n] = s;
}

// ---- 2) embed: 64 rows/block, W staged in smem; also emits xh (fp16) ------
#define ERB 64
__global__ __launch_bounds__(256)
void embed_kernel(const float* __restrict__ x)
{
    extern __shared__ float sm[];
    float* Ws = sm;                       // [32][1024]: 16 q dims then 16 k
    float* xb = sm + 32 * H_;             // [2][1024] double buffer
    __shared__ float zbuf[32];

    int tid = threadIdx.x, lane = tid & 31, w = tid >> 5;

    for (int idx = tid; idx < QD_ * H_; idx += 256) {
        Ws[idx]            = g_WqeT[idx];
        Ws[QD_ * H_ + idx] = g_WkeT[idx];
    }
    long long row0 = (long long)blockIdx.x * ERB;

    float4 nxt = *(const float4*)&x[row0 * H_ + tid * 4];
    *(float4*)&xb[tid * 4] = nxt;
    {
        half2* xp = (half2*)&g_xh[row0 * H_ + tid * 4];
        xp[0] = __floats2half2_rn(nxt.x, nxt.y);
        xp[1] = __floats2half2_rn(nxt.z, nxt.w);
    }
    __syncthreads();

    for (int r = 0; r < ERB; r++) {
        if (r + 1 < ERB) {
            nxt = *(const float4*)&x[(row0 + r + 1) * H_ + tid * 4];
            half2* xp = (half2*)&g_xh[(row0 + r + 1) * H_ + tid * 4];
            xp[0] = __floats2half2_rn(nxt.x, nxt.y);
            xp[1] = __floats2half2_rn(nxt.z, nxt.w);
        }

        const float* xs = xb + (r & 1) * H_;
        float xr[32];
        #pragma unroll
        for (int i = 0; i < 8; i++)
            *(float4*)&xr[i * 4] = *(const float4*)&xs[i * 128 + lane * 4];

        #pragma unroll
        for (int oo = 0; oo < 4; oo++) {
            int o = w * 4 + oo;
            const float* wrow = Ws + o * H_;
            float s = 0.f;
            #pragma unroll
            for (int i = 0; i < 8; i++) {
                float4 wv = *(const float4*)&wrow[i * 128 + lane * 4];
                s += xr[i*4]*wv.x + xr[i*4+1]*wv.y + xr[i*4+2]*wv.z + xr[i*4+3]*wv.w;
            }
            #pragma unroll
            for (int off = 16; off; off >>= 1)
                s += __shfl_xor_sync(0xffffffffu, s, off);
            if (lane == 0) zbuf[o] = s;
        }
        __syncthreads();

        if (tid < 32) {
            int o = tid & 15;
            bool isq = tid < 16;
            float z = zbuf[tid] + (isq ? g_bqe[o] : g_bke[o]);
            float sq = z * z;
            #pragma unroll
            for (int off = 8; off; off >>= 1)
                sq += __shfl_xor_sync(0xffffffffu, sq, off);
            float val = z * rsqrtf(sq + 1e-8f);
            (isq ? g_qq : g_kq)[(row0 + r) * QD_ + o] = val;
        }
        if (r + 1 < ERB)
            *(float4*)&xb[((r + 1) & 1) * H_ + tid * 4] = nxt;
        __syncthreads();
    }
}

// ------------- 3) fp32 -> fp16 hi+lo (Wv and Wo in one launch) -------------
__global__ __launch_bounds__(256)
void split_hl2(const float* __restrict__ s0, half* __restrict__ h0p, half* __restrict__ l0p,
               const float* __restrict__ s1, half* __restrict__ h1p, half* __restrict__ l1p)
{
    const float* src = blockIdx.y ? s1 : s0;
    half* h = blockIdx.y ? h1p : h0p;
    half* l = blockIdx.y ? l1p : l0p;
    int i = blockIdx.x * 256 + threadIdx.x;
    float4 v = ((const float4*)src)[i];
    half a0 = __float2half_rn(v.x), a1 = __float2half_rn(v.y);
    half a2 = __float2half_rn(v.z), a3 = __float2half_rn(v.w);
    half2* hp = (half2*)h;
    half2* lp = (half2*)l;
    hp[2*i]   = __halves2half2(a0, a1);
    hp[2*i+1] = __halves2half2(a2, a3);
    lp[2*i]   = __floats2half2_rn(v.x - __half2float(a0), v.y - __half2float(a1));
    lp[2*i+1] = __floats2half2_rn(v.z - __half2float(a2), v.w - __half2float(a3));
}

// ---------------- 4) scores + softmax -> fp16 probs (hi only) --------------
__global__ __launch_bounds__(256)
void attn_kernel(half* __restrict__ ah)
{
    int b = blockIdx.y;
    int q0 = blockIdx.x * 8;
    int tid = threadIdx.x;
    int lane = tid & 31, wid = tid >> 5;

    __shared__ float qs[8][QD_];
    __shared__ float red[8][9];

    if (tid < 128)
        ((float*)qs)[tid] = g_qq[((long long)b * S_ + q0) * QD_ + tid];
    __syncthreads();

    const float* kq = g_kq + (long long)b * S_ * QD_;
    float e[8][8];
    float sum[8] = {};

    #pragma unroll
    for (int j = 0; j < 8; j++) {
        int kk = tid + j * 256;
        const float4* kp = (const float4*)(kq + (long long)kk * QD_);
        float4 k0 = kp[0], k1 = kp[1], k2 = kp[2], k3 = kp[3];
        #pragma unroll
        for (int q = 0; q < 8; q++) {
            const float* qr = qs[q];
            float ov = qr[0]*k0.x + qr[1]*k0.y + qr[2]*k0.z + qr[3]*k0.w
                     + qr[4]*k1.x + qr[5]*k1.y + qr[6]*k1.z + qr[7]*k1.w
                     + qr[8]*k2.x + qr[9]*k2.y + qr[10]*k2.z + qr[11]*k2.w
                     + qr[12]*k3.x + qr[13]*k3.y + qr[14]*k3.z + qr[15]*k3.w;
            float ee = __expf(ov * ov);
            e[q][j] = ee;
            sum[q] += ee;
        }
    }

    #pragma unroll
    for (int q = 0; q < 8; q++) {
        float s = sum[q];
        #pragma unroll
        for (int off = 16; off; off >>= 1)
            s += __shfl_xor_sync(0xffffffffu, s, off);
        if (lane == 0) red[wid][q] = s;
    }
    __syncthreads();

    float inv[8];
    #pragma unroll
    for (int q = 0; q < 8; q++) {
        float t = 0.f;
        #pragma unroll
        for (int w = 0; w < 8; w++) t += red[w][q];
        inv[q] = 1.f / t;
    }

    #pragma unroll
    for (int q = 0; q < 8; q++) {
        long long rowo = ((long long)b * S_ + q0 + q) * S_;
        #pragma unroll
        for (int j = 0; j < 8; j++)
            ah[rowo + tid + j * 256] = __float2half_rn(e[q][j] * inv[q]);
    }
}

// ------------- 5) split-fp16 GEMM on mma.sync (staged pipeline) ------------
// C[M,N] = A[M,K] @ B[K,N]; terms: AhBh (+AlBh if ASPLIT)(+AhBl if BSPLIT).
// OMODE 0: fp32 out = acc + bias; 2: fp16 plain out (+bias).
#define APITCH 80                      // 32 half = 64B + 16 pad
#define BPITCH 272                     // 128 half = 256B + 16 pad
#define ATILE (128 * APITCH)           // 10240
#define BTILE (32 * BPITCH)            // 8704

template<bool ASPLIT, bool BSPLIT>
__device__ __forceinline__ void load_stage(u32 sb,
    const half* __restrict__ Ah, const half* __restrict__ Al,
    const half* __restrict__ Bh, const half* __restrict__ Bl,
    int bm, int bn, int k0, int K, int N, int tid)
{
    constexpr int BOFF = ATILE * (ASPLIT ? 2 : 1);
    #pragma unroll
    for (int i = 0; i < 2; i++) {
        int u = tid + i * 256;
        int r = u >> 2, c = u & 3;
        long long g = (long long)(bm + r) * K + k0 + c * 8;
        cpa16(sb + r * APITCH + c * 16, Ah + g);
        if (ASPLIT) cpa16(sb + ATILE + r * APITCH + c * 16, Al + g);
    }
    #pragma unroll
    for (int i = 0; i < 2; i++) {
        int u = tid + i * 256;
        int r = u >> 4, c = u & 15;
        long long g = (long long)(k0 + r) * N + bn + c * 8;
        cpa16(sb + BOFF + r * BPITCH + c * 16, Bh + g);
        if (BSPLIT) cpa16(sb + BOFF + BTILE + r * BPITCH + c * 16, Bl + g);
    }
}

template<bool ASPLIT, bool BSPLIT, int OMODE, int STAGES, int MINBLK>
__global__ __launch_bounds__(256, MINBLK)
void mmagemm(const half* __restrict__ Ah, const half* __restrict__ Al,
             const half* __restrict__ Bh, const half* __restrict__ Bl,
             const float* __restrict__ bias,
             float* __restrict__ Cf, half* __restrict__ Ch,
             int M, int N, int K, long long sA, long long sB, long long sC)
{
    constexpr int BOFF = ATILE * (ASPLIT ? 2 : 1);
    constexpr int STG  = BOFF + BTILE * (BSPLIT ? 2 : 1);

    extern __shared__ char dsm[];
    u32 sbase = smem_u32(dsm);

    const int tid = threadIdx.x;
    const int wid = tid >> 5, lane = tid & 31;
    const int bn = blockIdx.x * 128, bm = blockIdx.y * 128, z = blockIdx.z;
    Ah += (long long)z * sA; if (ASPLIT) Al += (long long)z * sA;
    Bh += (long long)z * sB; if (BSPLIT) Bl += (long long)z * sB;

    const int wm = (wid >> 2) * 64;
    const int wn = (wid & 3) * 32;

    float acc[4][4][4] = {};

    const int NC = K >> 5;
    #pragma unroll
    for (int s = 0; s < STAGES - 1; s++) {
        load_stage<ASPLIT, BSPLIT>(sbase + s * STG, Ah, Al, Bh, Bl,
                                   bm, bn, s << 5, K, N, tid);
        CP_COMMIT();
    }

    const int arow = lane & 15;
    const int ak8  = ((lane >> 4) & 1) * 8;
    const int bk   = lane & 15;
    const int bn8  = ((lane >> 4) & 1) * 8;

    int ld = STAGES - 1;                 // next stage index to load
    for (int c = 0; c < NC; c++) {
        CP_WAIT(STAGES - 2);
        __syncthreads();

        if (ld < NC) {
            load_stage<ASPLIT, BSPLIT>(sbase + (ld % STAGES) * STG,
                Ah, Al, Bh, Bl, bm, bn, ld << 5, K, N, tid);
            CP_COMMIT();
            ld++;
        }

        u32 st = sbase + (c % STAGES) * STG;
        u32 As = st, Als = st + ATILE;
        u32 Bs = st + BOFF, Bls = Bs + BTILE;

        #pragma unroll
        for (int ks = 0; ks < 32; ks += 16) {
            u32 bh[2][4], bl[2][4];
            #pragma unroll
            for (int n2 = 0; n2 < 2; n2++) {
                u32 boff = (ks + bk) * BPITCH + (wn + 16 * n2 + bn8) * 2;
                ldsm4t(bh[n2], Bs + boff);
                if (BSPLIT) ldsm4t(bl[n2], Bls + boff);
            }
            #pragma unroll
            for (int m = 0; m < 4; m++) {
                u32 ah[4], al[4];
                u32 aoff = (wm + 16 * m + arow) * APITCH + (ks + ak8) * 2;
                ldsm4(ah, As + aoff);
                if (ASPLIT) ldsm4(al, Als + aoff);
                #pragma unroll
                for (int j = 0; j < 4; j++) {
                    const u32* bhp = &bh[j >> 1][(j & 1) * 2];
                    mma16816(acc[m][j], ah, bhp);
                    if (ASPLIT) mma16816(acc[m][j], al, bhp);
                    if (BSPLIT) {
                        const u32* blp = &bl[j >> 1][(j & 1) * 2];
                        mma16816(acc[m][j], ah, blp);
                    }
                }
            }
        }
    }

    // ------------------------------ epilogue -------------------------------
    const int trow = lane >> 2;
    const int tcol = (lane & 3) * 2;

    #pragma unroll
    for (int m = 0; m < 4; m++) {
        #pragma unroll
        for (int j = 0; j < 4; j++) {
            int col = bn + wn + 8 * j + tcol;
            float b0 = bias ? bias[col] : 0.f;
            float b1 = bias ? bias[col + 1] : 0.f;
            #pragma unroll
            for (int h = 0; h < 2; h++) {
                long long row = bm + wm + 16 * m + trow + h * 8;
                float v0 = acc[m][j][2 * h + 0] + b0;
                float v1 = acc[m][j][2 * h + 1] + b1;
                long long idx = (long long)z * sC + row * N + col;
                if (OMODE == 0)
                    *(float2*)(Cf + idx) = make_float2(v0, v1);
                else
                    *(half2*)(Ch + idx) = __floats2half2_rn(v0, v1);
            }
        }
    }
}

// ---------------------------------------------------------------------------
extern "C" void kernel_launch(void* const* d_in, const int* in_sizes, int n_in,
                              void* d_out, int out_size)
{
    const float* x  = (const float*)d_in[0];
    const float* Wq = (const float*)d_in[1];
    const float* bq = (const float*)d_in[2];
    const float* Wk = (const float*)d_in[3];
    const float* bk = (const float*)d_in[4];
    const float* Wv = (const float*)d_in[5];
    const float* bv = (const float*)d_in[6];
    const float* We = (const float*)d_in[7];
    const float* be = (const float*)d_in[8];
    const float* Wo = (const float*)d_in[9];
    const float* bo = (const float*)d_in[10];
    float* out = (float*)d_out;

    half *xh, *Wvh, *Wvl, *Woh, *Wol, *W2h, *v2h, *anh;
    float* b2;
    cudaGetSymbolAddress((void**)&xh,  g_xh);
    cudaGetSymbolAddress((void**)&Wvh, g_Wvh);
    cudaGetSymbolAddress((void**)&Wvl, g_Wvl);
    cudaGetSymbolAddress((void**)&Woh, g_Woh);
    cudaGetSymbolAddress((void**)&Wol, g_Wol);
    cudaGetSymbolAddress((void**)&W2h, g_W2h);
    cudaGetSymbolAddress((void**)&v2h, g_v2h);
    cudaGetSymbolAddress((void**)&anh, g_attnh);
    cudaGetSymbolAddress((void**)&b2,  g_b2);

    const int SM_PRE = H_ * 17 * 4;                       // 69632
    const int SM_EMB = (32 * H_ + 2 * H_) * 4;            // 139264
    const int SM_W2  = 2 * (2 * ATILE + 2 * BTILE);       // 75776 (2-stage 3-term)
    const int SM_1T  = 3 * (ATILE + BTILE);               // 56832 (3-stage 1-term)

    cudaFuncSetAttribute(precompute_kernel, cudaFuncAttributeMaxDynamicSharedMemorySize, SM_PRE);
    cudaFuncSetAttribute(embed_kernel,      cudaFuncAttributeMaxDynamicSharedMemorySize, SM_EMB);
    cudaFuncSetAttribute((mmagemm<true,true,2,2,1>),   cudaFuncAttributeMaxDynamicSharedMemorySize, SM_W2);
    cudaFuncSetAttribute((mmagemm<false,false,2,3,2>), cudaFuncAttributeMaxDynamicSharedMemorySize, SM_1T);
    cudaFuncSetAttribute((mmagemm<false,false,0,3,2>), cudaFuncAttributeMaxDynamicSharedMemorySize, SM_1T);

    // 1) fold We into Wq/Wk (+biases);  b2 = bv @ Wo
    precompute_kernel<<<257, 256, SM_PRE>>>(Wq, Wk, We, bq, bk, be);
    b2_kernel<<<H_ / 256, 256>>>(bv, Wo);
    // 2) q_q / k_q embeddings (+ fused x -> fp16 cast)
    embed_kernel<<<ROWS_ / ERB, 256, SM_EMB>>>(x);
    // 3) fp16 hi/lo splits of Wv and Wo (one launch)
    split_hl2<<<dim3(H_ * H_ / 4 / 256, 2), 256>>>(Wv, Wvh, Wvl, Wo, Woh, Wol);
    // 4) softmax probs -> fp16 (hi only)
    attn_kernel<<<dim3(S_ / 8, B_), 256>>>(anh);
    // 5) W2 = Wv @ Wo   (3-term split, fp16 out)
    mmagemm<true,true,2,2,1><<<dim3(8, 8, 1), 256, SM_W2>>>(
        Wvh, Wvl, Woh, Wol, nullptr, nullptr, W2h,
        H_, H_, H_, 0, 0, 0);
    // 6) v2 = xh @ W2h + b2   (1-term, fp16 out)
    mmagemm<false,false,2,3,2><<<dim3(8, 64, 1), 256, SM_1T>>>(
        xh, nullptr, W2h, nullptr, b2, nullptr, v2h,
        ROWS_, H_, H_, 0, 0, 0);
    // 7) out = attn @ v2 + bo   (1-term, fp32 out, batched over B)
    mmagemm<false,false,0,3,2><<<dim3(8, 16, 4), 256, SM_1T>>>(
        anh, nullptr, v2h, nullptr, bo, out, nullptr,
        S_, H_, S_, (long long)S_ * S_, (long long)S_ * H_, (long long)S_ * H_);
}

// round 7
// speedup vs baseline: 4.3250x; 1.0198x over previous
#include <cuda_runtime.h>
#include <cuda_fp16.h>

// ---------------------------------------------------------------------------
// QuantumAttention, restructured:
//   out = attn @ (x @ (Wv@Wo) + bv@Wo) + bo,  attn = softmax((q_q.k_q)^2)
//   q_q = normalize(x @ (Wq@We) + (bq@We+be)), k_q likewise.
// GEMMs on mma.sync fp16 (fp32 accum); W2=Wv@Wo 3-term split-fp16, main-path
// 1-term. R7: warp tile 64x64 (CTA 128x256), polynomial exp (kills MUFU
// bound in attn), parallel b2.
// ---------------------------------------------------------------------------

#define B_ 4
#define S_ 2048
#define H_ 1024
#define QD_ 16
#define ROWS_ (B_ * S_)          // 8192

typedef unsigned int u32;

// ------------------------------- scratch ----------------------------------
__device__ float g_WqeT[QD_ * H_];
__device__ float g_WkeT[QD_ * H_];
__device__ float g_bqe[QD_];
__device__ float g_bke[QD_];
__device__ float g_qq[ROWS_ * QD_];
__device__ float g_kq[ROWS_ * QD_];
__device__ float g_b2[H_];

__device__ half g_xh[ROWS_ * H_];
__device__ half g_Wvh[H_ * H_];
__device__ half g_Wvl[H_ * H_];
__device__ half g_Woh[H_ * H_];
__device__ half g_Wol[H_ * H_];
__device__ half g_W2h[H_ * H_];
__device__ half g_v2h[ROWS_ * H_];
__device__ half g_attnh[(long long)B_ * S_ * S_];

// ----------------------------- PTX helpers --------------------------------
__device__ __forceinline__ u32 smem_u32(const void* p) {
    u32 a;
    asm("{ .reg .u64 t; cvta.to.shared.u64 t, %1; cvt.u32.u64 %0, t; }"
        : "=r"(a) : "l"(p));
    return a;
}
__device__ __forceinline__ void cpa16(u32 d, const void* g) {
    asm volatile("cp.async.cg.shared.global [%0], [%1], 16;" :: "r"(d), "l"(g));
}
#define CP_COMMIT() asm volatile("cp.async.commit_group;" ::: "memory")
#define CP_WAIT(n)  asm volatile("cp.async.wait_group %0;" :: "n"(n) : "memory")

__device__ __forceinline__ void ldsm4(u32* r, u32 a) {
    asm volatile("ldmatrix.sync.aligned.m8n8.x4.shared.b16 {%0,%1,%2,%3}, [%4];"
        : "=r"(r[0]), "=r"(r[1]), "=r"(r[2]), "=r"(r[3]) : "r"(a));
}
__device__ __forceinline__ void ldsm4t(u32* r, u32 a) {
    asm volatile("ldmatrix.sync.aligned.m8n8.x4.trans.shared.b16 {%0,%1,%2,%3}, [%4];"
        : "=r"(r[0]), "=r"(r[1]), "=r"(r[2]), "=r"(r[3]) : "r"(a));
}
__device__ __forceinline__ void mma16816(float* d, const u32* a, const u32* b) {
    asm volatile("mma.sync.aligned.m16n8k16.row.col.f32.f16.f16.f32 "
        "{%0,%1,%2,%3}, {%4,%5,%6,%7}, {%8,%9}, {%0,%1,%2,%3};"
        : "+f"(d[0]), "+f"(d[1]), "+f"(d[2]), "+f"(d[3])
        : "r"(a[0]), "r"(a[1]), "r"(a[2]), "r"(a[3]), "r"(b[0]), "r"(b[1]));
}

// exp(s) for s in [0,1]: degree-6 Taylor around 0.5, FMA pipe only.
// max rel err ~1.3e-6; softmax divides by the sum of the same approximants.
__device__ __forceinline__ float exp01(float s) {
    float u = s - 0.5f;
    float p = 1.f / 720.f;
    p = fmaf(p, u, 1.f / 120.f);
    p = fmaf(p, u, 1.f / 24.f);
    p = fmaf(p, u, 1.f / 6.f);
    p = fmaf(p, u, 0.5f);
    p = fmaf(p, u, 1.f);
    p = fmaf(p, u, 1.f);
    return p * 1.6487212707f;            // e^0.5
}

// ------------------- 1) fold We into Wq/Wk (warp per row) ------------------
__global__ __launch_bounds__(256)
void precompute_kernel(const float* __restrict__ Wq,
                       const float* __restrict__ Wk,
                       const float* __restrict__ We,
                       const float* __restrict__ bq,
                       const float* __restrict__ bk,
                       const float* __restrict__ be)
{
    extern __shared__ float Wes[];          // [1024][17] padded
    int tid = threadIdx.x;
    for (int idx = tid; idx < H_ * QD_; idx += 256)
        Wes[(idx >> 4) * 17 + (idx & 15)] = We[idx];
    __syncthreads();

    int wg = blockIdx.x * 8 + (tid >> 5);
    if (wg >= 2 * (H_ + 1)) return;
    int m = wg / (H_ + 1);
    int i = wg % (H_ + 1);
    int lane = tid & 31;
    const float* W  = m ? Wk : Wq;
    const float* bb = m ? bk : bq;

    float p[QD_];
    #pragma unroll
    for (int o = 0; o < QD_; o++) p[o] = 0.f;

    for (int kk = 0; kk < H_ / 32; kk++) {
        int k = kk * 32 + lane;
        float w = (i < H_) ? W[(long long)i * H_ + k] : bb[k];
        const float* wr = &Wes[k * 17];
        #pragma unroll
        for (int o = 0; o < QD_; o++) p[o] = fmaf(w, wr[o], p[o]);
    }
    #pragma unroll
    for (int off = 16; off; off >>= 1)
        #pragma unroll
        for (int o = 0; o < QD_; o++)
            p[o] += __shfl_xor_sync(0xffffffffu, p[o], off);

    if (lane == 0) {
        if (i < H_) {
            float* dst = m ? g_WkeT : g_WqeT;
            #pragma unroll
            for (int o = 0; o < QD_; o++) dst[o * H_ + i] = p[o];
        } else {
            float* dst = m ? g_bke : g_bqe;
            #pragma unroll
            for (int o = 0; o < QD_; o++) dst[o] = p[o] + be[o];
        }
    }
}

// ------------- 1b) b2 = bv @ Wo  (split-K, 32 blocks) ----------------------
__global__ __launch_bounds__(256)
void b2_kernel(const float* __restrict__ bv, const float* __restrict__ Wo)
{
    __shared__ float red[8][33];
    int t = threadIdx.x;
    int n = blockIdx.x * 32 + (t & 31);
    int ks = t >> 5;                       // 8 k-slices of 128
    float s = 0.f;
    #pragma unroll 4
    for (int k = ks * 128; k < ks * 128 + 128; k++)
        s = fmaf(bv[k], Wo[(long long)k * H_ + n], s);
    red[ks][t & 31] = s;
    __syncthreads();
    if (t < 32) {
        float tot = 0.f;
        #pragma unroll
        for (int i = 0; i < 8; i++) tot += red[i][t];
        g_b2[blockIdx.x * 32 + t] = tot;
    }
}

// ---- 2) embed: 64 rows/block, W staged in smem; also emits xh (fp16) ------
#define ERB 64
__global__ __launch_bounds__(256)
void embed_kernel(const float* __restrict__ x)
{
    extern __shared__ float sm[];
    float* Ws = sm;                       // [32][1024]: 16 q dims then 16 k
    float* xb = sm + 32 * H_;             // [2][1024] double buffer
    __shared__ float zbuf[32];

    int tid = threadIdx.x, lane = tid & 31, w = tid >> 5;

    for (int idx = tid; idx < QD_ * H_; idx += 256) {
        Ws[idx]            = g_WqeT[idx];
        Ws[QD_ * H_ + idx] = g_WkeT[idx];
    }
    long long row0 = (long long)blockIdx.x * ERB;

    float4 nxt = *(const float4*)&x[row0 * H_ + tid * 4];
    *(float4*)&xb[tid * 4] = nxt;
    {
        half2* xp = (half2*)&g_xh[row0 * H_ + tid * 4];
        xp[0] = __floats2half2_rn(nxt.x, nxt.y);
        xp[1] = __floats2half2_rn(nxt.z, nxt.w);
    }
    __syncthreads();

    for (int r = 0; r < ERB; r++) {
        if (r + 1 < ERB) {
            nxt = *(const float4*)&x[(row0 + r + 1) * H_ + tid * 4];
            half2* xp = (half2*)&g_xh[(row0 + r + 1) * H_ + tid * 4];
            xp[0] = __floats2half2_rn(nxt.x, nxt.y);
            xp[1] = __floats2half2_rn(nxt.z, nxt.w);
        }

        const float* xs = xb + (r & 1) * H_;
        float xr[32];
        #pragma unroll
        for (int i = 0; i < 8; i++)
            *(float4*)&xr[i * 4] = *(const float4*)&xs[i * 128 + lane * 4];

        #pragma unroll
        for (int oo = 0; oo < 4; oo++) {
            int o = w * 4 + oo;
            const float* wrow = Ws + o * H_;
            float s = 0.f;
            #pragma unroll
            for (int i = 0; i < 8; i++) {
                float4 wv = *(const float4*)&wrow[i * 128 + lane * 4];
                s += xr[i*4]*wv.x + xr[i*4+1]*wv.y + xr[i*4+2]*wv.z + xr[i*4+3]*wv.w;
            }
            #pragma unroll
            for (int off = 16; off; off >>= 1)
                s += __shfl_xor_sync(0xffffffffu, s, off);
            if (lane == 0) zbuf[o] = s;
        }
        __syncthreads();

        if (tid < 32) {
            int o = tid & 15;
            bool isq = tid < 16;
            float z = zbuf[tid] + (isq ? g_bqe[o] : g_bke[o]);
            float sq = z * z;
            #pragma unroll
            for (int off = 8; off; off >>= 1)
                sq += __shfl_xor_sync(0xffffffffu, sq, off);
            float val = z * rsqrtf(sq + 1e-8f);
            (isq ? g_qq : g_kq)[(row0 + r) * QD_ + o] = val;
        }
        if (r + 1 < ERB)
            *(float4*)&xb[((r + 1) & 1) * H_ + tid * 4] = nxt;
        __syncthreads();
    }
}

// ------------- 3) fp32 -> fp16 hi+lo (Wv and Wo in one launch) -------------
__global__ __launch_bounds__(256)
void split_hl2(const float* __restrict__ s0, half* __restrict__ h0p, half* __restrict__ l0p,
               const float* __restrict__ s1, half* __restrict__ h1p, half* __restrict__ l1p)
{
    const float* src = blockIdx.y ? s1 : s0;
    half* h = blockIdx.y ? h1p : h0p;
    half* l = blockIdx.y ? l1p : l0p;
    int i = blockIdx.x * 256 + threadIdx.x;
    float4 v = ((const float4*)src)[i];
    half a0 = __float2half_rn(v.x), a1 = __float2half_rn(v.y);
    half a2 = __float2half_rn(v.z), a3 = __float2half_rn(v.w);
    half2* hp = (half2*)h;
    half2* lp = (half2*)l;
    hp[2*i]   = __halves2half2(a0, a1);
    hp[2*i+1] = __halves2half2(a2, a3);
    lp[2*i]   = __floats2half2_rn(v.x - __half2float(a0), v.y - __half2float(a1));
    lp[2*i+1] = __floats2half2_rn(v.z - __half2float(a2), v.w - __half2float(a3));
}

// ------ 4) scores + softmax (poly exp, FMA pipe) -> fp16 probs -------------
__global__ __launch_bounds__(256)
void attn_kernel(half* __restrict__ ah)
{
    int b = blockIdx.y;
    int q0 = blockIdx.x * 8;
    int tid = threadIdx.x;
    int lane = tid & 31, wid = tid >> 5;

    __shared__ float qs[8][QD_];
    __shared__ float red[8][9];

    if (tid < 128)
        ((float*)qs)[tid] = g_qq[((long long)b * S_ + q0) * QD_ + tid];
    __syncthreads();

    const float* kq = g_kq + (long long)b * S_ * QD_;
    float e[8][8];
    float sum[8] = {};

    #pragma unroll
    for (int j = 0; j < 8; j++) {
        int kk = tid + j * 256;
        const float4* kp = (const float4*)(kq + (long long)kk * QD_);
        float4 k0 = kp[0], k1 = kp[1], k2 = kp[2], k3 = kp[3];
        #pragma unroll
        for (int q = 0; q < 8; q++) {
            const float* qr = qs[q];
            float ov = qr[0]*k0.x + qr[1]*k0.y + qr[2]*k0.z + qr[3]*k0.w
                     + qr[4]*k1.x + qr[5]*k1.y + qr[6]*k1.z + qr[7]*k1.w
                     + qr[8]*k2.x + qr[9]*k2.y + qr[10]*k2.z + qr[11]*k2.w
                     + qr[12]*k3.x + qr[13]*k3.y + qr[14]*k3.z + qr[15]*k3.w;
            float ee = exp01(ov * ov);
            e[q][j] = ee;
            sum[q] += ee;
        }
    }

    #pragma unroll
    for (int q = 0; q < 8; q++) {
        float s = sum[q];
        #pragma unroll
        for (int off = 16; off; off >>= 1)
            s += __shfl_xor_sync(0xffffffffu, s, off);
        if (lane == 0) red[wid][q] = s;
    }
    __syncthreads();

    float inv[8];
    #pragma unroll
    for (int q = 0; q < 8; q++) {
        float t = 0.f;
        #pragma unroll
        for (int w = 0; w < 8; w++) t += red[w][q];
        inv[q] = 1.f / t;
    }

    #pragma unroll
    for (int q = 0; q < 8; q++) {
        long long rowo = ((long long)b * S_ + q0 + q) * S_;
        #pragma unroll
        for (int j = 0; j < 8; j++)
            ah[rowo + tid + j * 256] = __float2half_rn(e[q][j] * inv[q]);
    }
}

// ------- 5) split-fp16 GEMM, CTA 128x256, warp 64x64, staged cp.async ------
// C[M,N] = A[M,K] @ B[K,N]; terms: AhBh (+AlBh if ASPLIT)(+AhBl if BSPLIT).
// OMODE 0: fp32 out = acc + bias; 2: fp16 plain out (+bias).
#define APITCH 80                      // 32 half = 64B + 16 pad
#define BPITCH 528                     // 256 half = 512B + 16 pad
#define ATILE (128 * APITCH)           // 10240
#define BTILE (32 * BPITCH)            // 16896

template<bool ASPLIT, bool BSPLIT>
__device__ __forceinline__ void load_stage(u32 sb,
    const half* __restrict__ Ah, const half* __restrict__ Al,
    const half* __restrict__ Bh, const half* __restrict__ Bl,
    int bm, int bn, int k0, int K, int N, int tid)
{
    constexpr int BOFF = ATILE * (ASPLIT ? 2 : 1);
    #pragma unroll
    for (int i = 0; i < 2; i++) {
        int u = tid + i * 256;
        int r = u >> 2, c = u & 3;
        long long g = (long long)(bm + r) * K + k0 + c * 8;
        cpa16(sb + r * APITCH + c * 16, Ah + g);
        if (ASPLIT) cpa16(sb + ATILE + r * APITCH + c * 16, Al + g);
    }
    #pragma unroll
    for (int i = 0; i < 4; i++) {
        int u = tid + i * 256;
        int r = u >> 5, c = u & 31;
        long long g = (long long)(k0 + r) * N + bn + c * 8;
        cpa16(sb + BOFF + r * BPITCH + c * 16, Bh + g);
        if (BSPLIT) cpa16(sb + BOFF + BTILE + r * BPITCH + c * 16, Bl + g);
    }
}

template<bool ASPLIT, bool BSPLIT, int OMODE, int STAGES>
__global__ __launch_bounds__(256, 1)
void mmagemm(const half* __restrict__ Ah, const half* __restrict__ Al,
             const half* __restrict__ Bh, const half* __restrict__ Bl,
             const float* __restrict__ bias,
             float* __restrict__ Cf, half* __restrict__ Ch,
             int M, int N, int K, long long sA, long long sB, long long sC)
{
    constexpr int BOFF = ATILE * (ASPLIT ? 2 : 1);
    constexpr int STG  = BOFF + BTILE * (BSPLIT ? 2 : 1);

    extern __shared__ char dsm[];
    u32 sbase = smem_u32(dsm);

    const int tid = threadIdx.x;
    const int wid = tid >> 5, lane = tid & 31;
    const int bn = blockIdx.x * 256, bm = blockIdx.y * 128, z = blockIdx.z;
    Ah += (long long)z * sA; if (ASPLIT) Al += (long long)z * sA;
    Bh += (long long)z * sB; if (BSPLIT) Bl += (long long)z * sB;

    const int wm = (wid >> 2) * 64;        // 2 M-tiles of 64
    const int wn = (wid & 3) * 64;         // 4 N-tiles of 64

    float acc[4][8][4] = {};

    const int NC = K >> 5;
    #pragma unroll
    for (int s = 0; s < STAGES - 1; s++) {
        load_stage<ASPLIT, BSPLIT>(sbase + s * STG, Ah, Al, Bh, Bl,
                                   bm, bn, s << 5, K, N, tid);
        CP_COMMIT();
    }

    const int arow = lane & 15;
    const int ak8  = ((lane >> 4) & 1) * 8;
    const int bk   = lane & 15;
    const int bn8  = ((lane >> 4) & 1) * 8;

    int ld = STAGES - 1;
    for (int c = 0; c < NC; c++) {
        CP_WAIT(STAGES - 2);
        __syncthreads();

        if (ld < NC) {
            load_stage<ASPLIT, BSPLIT>(sbase + (ld % STAGES) * STG,
                Ah, Al, Bh, Bl, bm, bn, ld << 5, K, N, tid);
            CP_COMMIT();
            ld++;
        }

        u32 st = sbase + (c % STAGES) * STG;
        u32 As = st, Als = st + ATILE;
        u32 Bs = st + BOFF, Bls = Bs + BTILE;

        #pragma unroll
        for (int ks = 0; ks < 32; ks += 16) {
            u32 bh[4][4], bl[4][4];
            #pragma unroll
            for (int n2 = 0; n2 < 4; n2++) {
                u32 boff = (ks + bk) * BPITCH + (wn + 16 * n2 + bn8) * 2;
                ldsm4t(bh[n2], Bs + boff);
                if (BSPLIT) ldsm4t(bl[n2], Bls + boff);
            }
            #pragma unroll
            for (int m = 0; m < 4; m++) {
                u32 ah[4], al[4];
                u32 aoff = (wm + 16 * m + arow) * APITCH + (ks + ak8) * 2;
                ldsm4(ah, As + aoff);
                if (ASPLIT) ldsm4(al, Als + aoff);
                #pragma unroll
                for (int j = 0; j < 8; j++) {
                    const u32* bhp = &bh[j >> 1][(j & 1) * 2];
                    mma16816(acc[m][j], ah, bhp);
                    if (ASPLIT) mma16816(acc[m][j], al, bhp);
                    if (BSPLIT) {
                        const u32* blp = &bl[j >> 1][(j & 1) * 2];
                        mma16816(acc[m][j], ah, blp);
                    }
                }
            }
        }
    }

    // ------------------------------ epilogue -------------------------------
    const int trow = lane >> 2;
    const int tcol = (lane & 3) * 2;

    #pragma unroll
    for (int m = 0; m < 4; m++) {
        #pragma unroll
        for (int j = 0; j < 8; j++) {
            int col = bn + wn + 8 * j + tcol;
            float b0 = bias ? bias[col] : 0.f;
            float b1 = bias ? bias[col + 1] : 0.f;
            #pragma unroll
            for (int h = 0; h < 2; h++) {
                long long row = bm + wm + 16 * m + trow + h * 8;
                float v0 = acc[m][j][2 * h + 0] + b0;
                float v1 = acc[m][j][2 * h + 1] + b1;
                long long idx = (long long)z * sC + row * N + col;
                if (OMODE == 0)
                    *(float2*)(Cf + idx) = make_float2(v0, v1);
                else
                    *(half2*)(Ch + idx) = __floats2half2_rn(v0, v1);
            }
        }
    }
}

// ---------------------------------------------------------------------------
extern "C" void kernel_launch(void* const* d_in, const int* in_sizes, int n_in,
                              void* d_out, int out_size)
{
    const float* x  = (const float*)d_in[0];
    const float* Wq = (const float*)d_in[1];
    const float* bq = (const float*)d_in[2];
    const float* Wk = (const float*)d_in[3];
    const float* bk = (const float*)d_in[4];
    const float* Wv = (const float*)d_in[5];
    const float* bv = (const float*)d_in[6];
    const float* We = (const float*)d_in[7];
    const float* be = (const float*)d_in[8];
    const float* Wo = (const float*)d_in[9];
    const float* bo = (const float*)d_in[10];
    float* out = (float*)d_out;

    half *xh, *Wvh, *Wvl, *Woh, *Wol, *W2h, *v2h, *anh;
    cudaGetSymbolAddress((void**)&xh,  g_xh);
    cudaGetSymbolAddress((void**)&Wvh, g_Wvh);
    cudaGetSymbolAddress((void**)&Wvl, g_Wvl);
    cudaGetSymbolAddress((void**)&Woh, g_Woh);
    cudaGetSymbolAddress((void**)&Wol, g_Wol);
    cudaGetSymbolAddress((void**)&W2h, g_W2h);
    cudaGetSymbolAddress((void**)&v2h, g_v2h);
    cudaGetSymbolAddress((void**)&anh, g_attnh);
    float* b2;
    cudaGetSymbolAddress((void**)&b2,  g_b2);

    const int SM_PRE = H_ * 17 * 4;                       // 69632
    const int SM_EMB = (32 * H_ + 2 * H_) * 4;            // 139264
    const int SM_W2  = 2 * (2 * ATILE + 2 * BTILE);       // 108544 (2-stage 3-term)
    const int SM_1T  = 3 * (ATILE + BTILE);               // 81408  (3-stage 1-term)

    cudaFuncSetAttribute(precompute_kernel, cudaFuncAttributeMaxDynamicSharedMemorySize, SM_PRE);
    cudaFuncSetAttribute(embed_kernel,      cudaFuncAttributeMaxDynamicSharedMemorySize, SM_EMB);
    cudaFuncSetAttribute((mmagemm<true,true,2,2>),   cudaFuncAttributeMaxDynamicSharedMemorySize, SM_W2);
    cudaFuncSetAttribute((mmagemm<false,false,2,3>), cudaFuncAttributeMaxDynamicSharedMemorySize, SM_1T);
    cudaFuncSetAttribute((mmagemm<false,false,0,3>), cudaFuncAttributeMaxDynamicSharedMemorySize, SM_1T);

    // 1) fold We into Wq/Wk (+biases);  b2 = bv @ Wo (split-K)
    precompute_kernel<<<257, 256, SM_PRE>>>(Wq, Wk, We, bq, bk, be);
    b2_kernel<<<H_ / 32, 256>>>(bv, Wo);
    // 2) q_q / k_q embeddings (+ fused x -> fp16 cast)
    embed_kernel<<<ROWS_ / ERB, 256, SM_EMB>>>(x);
    // 3) fp16 hi/lo splits of Wv and Wo (one launch)
    split_hl2<<<dim3(H_ * H_ / 4 / 256, 2), 256>>>(Wv, Wvh, Wvl, Wo, Woh, Wol);
    // 4) softmax probs -> fp16 (hi only)
    attn_kernel<<<dim3(S_ / 8, B_), 256>>>(anh);
    // 5) W2 = Wv @ Wo   (3-term split, fp16 out)
    mmagemm<true,true,2,2><<<dim3(4, 8, 1), 256, SM_W2>>>(
        Wvh, Wvl, Woh, Wol, nullptr, nullptr, W2h,
        H_, H_, H_, 0, 0, 0);
    // 6) v2 = xh @ W2h + b2   (1-term, fp16 out)
    mmagemm<false,false,2,3><<<dim3(4, 64, 1), 256, SM_1T>>>(
        xh, nullptr, W2h, nullptr, b2, nullptr, v2h,
        ROWS_, H_, H_, 0, 0, 0);
    // 7) out = attn @ v2 + bo   (1-term, fp32 out, batched over B)
    mmagemm<false,false,0,3><<<dim3(4, 16, 4), 256, SM_1T>>>(
        anh, nullptr, v2h, nullptr, bo, out, nullptr,
        S_, H_, S_, (long long)S_ * S_, (long long)S_ * H_, (long long)S_ * H_);
}

// round 8
// speedup vs baseline: 4.9320x; 1.1404x over previous
#include <cuda_runtime.h>
#include <cuda_fp16.h>

// ---------------------------------------------------------------------------
// QuantumAttention, restructured:
//   out = attn @ (x @ (Wv@Wo) + bv@Wo) + bo,  attn = softmax((q_q.k_q)^2)
//   q_q = normalize(x @ (Wq@We) + (bq@We+be)), k_q likewise.
// R8: DAG-parallel fat kernels (4 launches):
//   L1: precompute || b2 || weight splits
//   L2: embed || W2-GEMM          L3: attn || v2-GEMM          L4: out-GEMM
// ---------------------------------------------------------------------------

#define B_ 4
#define S_ 2048
#define H_ 1024
#define QD_ 16
#define ROWS_ (B_ * S_)          // 8192

typedef unsigned int u32;

// ------------------------------- scratch ----------------------------------
__device__ float g_WqeT[QD_ * H_];
__device__ float g_WkeT[QD_ * H_];
__device__ float g_bqe[QD_];
__device__ float g_bke[QD_];
__device__ float g_qq[ROWS_ * QD_];
__device__ float g_kq[ROWS_ * QD_];
__device__ float g_b2[H_];

__device__ half g_xh[ROWS_ * H_];
__device__ half g_Wvh[H_ * H_];
__device__ half g_Wvl[H_ * H_];
__device__ half g_Woh[H_ * H_];
__device__ half g_Wol[H_ * H_];
__device__ half g_W2h[H_ * H_];
__device__ half g_v2h[ROWS_ * H_];
__device__ half g_attnh[(long long)B_ * S_ * S_];

// ----------------------------- PTX helpers --------------------------------
__device__ __forceinline__ u32 smem_u32(const void* p) {
    u32 a;
    asm("{ .reg .u64 t; cvta.to.shared.u64 t, %1; cvt.u32.u64 %0, t; }"
        : "=r"(a) : "l"(p));
    return a;
}
__device__ __forceinline__ void cpa16(u32 d, const void* g) {
    asm volatile("cp.async.cg.shared.global [%0], [%1], 16;" :: "r"(d), "l"(g));
}
#define CP_COMMIT() asm volatile("cp.async.commit_group;" ::: "memory")
#define CP_WAIT(n)  asm volatile("cp.async.wait_group %0;" :: "n"(n) : "memory")

__device__ __forceinline__ void ldsm4(u32* r, u32 a) {
    asm volatile("ldmatrix.sync.aligned.m8n8.x4.shared.b16 {%0,%1,%2,%3}, [%4];"
        : "=r"(r[0]), "=r"(r[1]), "=r"(r[2]), "=r"(r[3]) : "r"(a));
}
__device__ __forceinline__ void ldsm4t(u32* r, u32 a) {
    asm volatile("ldmatrix.sync.aligned.m8n8.x4.trans.shared.b16 {%0,%1,%2,%3}, [%4];"
        : "=r"(r[0]), "=r"(r[1]), "=r"(r[2]), "=r"(r[3]) : "r"(a));
}
__device__ __forceinline__ void mma16816(float* d, const u32* a, const u32* b) {
    asm volatile("mma.sync.aligned.m16n8k16.row.col.f32.f16.f16.f32 "
        "{%0,%1,%2,%3}, {%4,%5,%6,%7}, {%8,%9}, {%0,%1,%2,%3};"
        : "+f"(d[0]), "+f"(d[1]), "+f"(d[2]), "+f"(d[3])
        : "r"(a[0]), "r"(a[1]), "r"(a[2]), "r"(a[3]), "r"(b[0]), "r"(b[1]));
}

// exp(s), s in [0,1]: degree-6 Taylor around 0.5 (FMA pipe; rel err ~1.3e-6)
__device__ __forceinline__ float exp01(float s) {
    float u = s - 0.5f;
    float p = 1.f / 720.f;
    p = fmaf(p, u, 1.f / 120.f);
    p = fmaf(p, u, 1.f / 24.f);
    p = fmaf(p, u, 1.f / 6.f);
    p = fmaf(p, u, 0.5f);
    p = fmaf(p, u, 1.f);
    p = fmaf(p, u, 1.f);
    return p * 1.6487212707f;
}

// ---------------------------- role bodies ----------------------------------

// fold We into Wq/Wk (warp per row; virtual row H_ folds bias)
__device__ __forceinline__ void precompute_body(int bid,
    const float* __restrict__ Wq, const float* __restrict__ Wk,
    const float* __restrict__ We, const float* __restrict__ bq,
    const float* __restrict__ bk, const float* __restrict__ be)
{
    extern __shared__ char dsm[];
    float* Wes = (float*)dsm;               // [1024][17]
    int tid = threadIdx.x;
    for (int idx = tid; idx < H_ * QD_; idx += 256)
        Wes[(idx >> 4) * 17 + (idx & 15)] = We[idx];
    __syncthreads();

    int wg = bid * 8 + (tid >> 5);
    if (wg >= 2 * (H_ + 1)) return;
    int m = wg / (H_ + 1);
    int i = wg % (H_ + 1);
    int lane = tid & 31;
    const float* W  = m ? Wk : Wq;
    const float* bb = m ? bk : bq;

    float p[QD_];
    #pragma unroll
    for (int o = 0; o < QD_; o++) p[o] = 0.f;

    for (int kk = 0; kk < H_ / 32; kk++) {
        int k = kk * 32 + lane;
        float w = (i < H_) ? W[(long long)i * H_ + k] : bb[k];
        const float* wr = &Wes[k * 17];
        #pragma unroll
        for (int o = 0; o < QD_; o++) p[o] = fmaf(w, wr[o], p[o]);
    }
    #pragma unroll
    for (int off = 16; off; off >>= 1)
        #pragma unroll
        for (int o = 0; o < QD_; o++)
            p[o] += __shfl_xor_sync(0xffffffffu, p[o], off);

    if (lane == 0) {
        if (i < H_) {
            float* dst = m ? g_WkeT : g_WqeT;
            #pragma unroll
            for (int o = 0; o < QD_; o++) dst[o * H_ + i] = p[o];
        } else {
            float* dst = m ? g_bke : g_bqe;
            #pragma unroll
            for (int o = 0; o < QD_; o++) dst[o] = p[o] + be[o];
        }
    }
}

// b2 = bv @ Wo (split-K within block)
__device__ __forceinline__ void b2_body(int bid,
    const float* __restrict__ bv, const float* __restrict__ Wo)
{
    __shared__ float red[8][33];
    int t = threadIdx.x;
    int n = bid * 32 + (t & 31);
    int ks = t >> 5;
    float s = 0.f;
    #pragma unroll 4
    for (int k = ks * 128; k < ks * 128 + 128; k++)
        s = fmaf(bv[k], Wo[(long long)k * H_ + n], s);
    red[ks][t & 31] = s;
    __syncthreads();
    if (t < 32) {
        float tot = 0.f;
        #pragma unroll
        for (int i = 0; i < 8; i++) tot += red[i][t];
        g_b2[bid * 32 + t] = tot;
    }
}

// fp32 -> fp16 hi+lo split of Wv / Wo
__device__ __forceinline__ void split_body(int sidx,
    const float* __restrict__ Wv, const float* __restrict__ Wo)
{
    bool second = sidx >= 1024;
    const float* src = second ? Wo : Wv;
    half* h = second ? g_Woh : g_Wvh;
    half* l = second ? g_Wol : g_Wvl;
    int i = (sidx & 1023) * 256 + threadIdx.x;
    float4 v = ((const float4*)src)[i];
    half a0 = __float2half_rn(v.x), a1 = __float2half_rn(v.y);
    half a2 = __float2half_rn(v.z), a3 = __float2half_rn(v.w);
    half2* hp = (half2*)h;
    half2* lp = (half2*)l;
    hp[2*i]   = __halves2half2(a0, a1);
    hp[2*i+1] = __halves2half2(a2, a3);
    lp[2*i]   = __floats2half2_rn(v.x - __half2float(a0), v.y - __half2float(a1));
    lp[2*i+1] = __floats2half2_rn(v.z - __half2float(a2), v.w - __half2float(a3));
}

// embed: 64 rows/block, W staged in smem; also emits xh (fp16)
#define ERB 64
__device__ __forceinline__ void embed_body(int bid, const float* __restrict__ x)
{
    extern __shared__ char dsm[];
    float* sm = (float*)dsm;
    float* Ws = sm;                       // [32][1024]
    float* xb = sm + 32 * H_;             // [2][1024]
    __shared__ float zbuf[32];

    int tid = threadIdx.x, lane = tid & 31, w = tid >> 5;

    for (int idx = tid; idx < QD_ * H_; idx += 256) {
        Ws[idx]            = g_WqeT[idx];
        Ws[QD_ * H_ + idx] = g_WkeT[idx];
    }
    long long row0 = (long long)bid * ERB;

    float4 nxt = *(const float4*)&x[row0 * H_ + tid * 4];
    *(float4*)&xb[tid * 4] = nxt;
    {
        half2* xp = (half2*)&g_xh[row0 * H_ + tid * 4];
        xp[0] = __floats2half2_rn(nxt.x, nxt.y);
        xp[1] = __floats2half2_rn(nxt.z, nxt.w);
    }
    __syncthreads();

    for (int r = 0; r < ERB; r++) {
        if (r + 1 < ERB) {
            nxt = *(const float4*)&x[(row0 + r + 1) * H_ + tid * 4];
            half2* xp = (half2*)&g_xh[(row0 + r + 1) * H_ + tid * 4];
            xp[0] = __floats2half2_rn(nxt.x, nxt.y);
            xp[1] = __floats2half2_rn(nxt.z, nxt.w);
        }

        const float* xs = xb + (r & 1) * H_;
        float xr[32];
        #pragma unroll
        for (int i = 0; i < 8; i++)
            *(float4*)&xr[i * 4] = *(const float4*)&xs[i * 128 + lane * 4];

        #pragma unroll
        for (int oo = 0; oo < 4; oo++) {
            int o = w * 4 + oo;
            const float* wrow = Ws + o * H_;
            float s = 0.f;
            #pragma unroll
            for (int i = 0; i < 8; i++) {
                float4 wv = *(const float4*)&wrow[i * 128 + lane * 4];
                s += xr[i*4]*wv.x + xr[i*4+1]*wv.y + xr[i*4+2]*wv.z + xr[i*4+3]*wv.w;
            }
            #pragma unroll
            for (int off = 16; off; off >>= 1)
                s += __shfl_xor_sync(0xffffffffu, s, off);
            if (lane == 0) zbuf[o] = s;
        }
        __syncthreads();

        if (tid < 32) {
            int o = tid & 15;
            bool isq = tid < 16;
            float z = zbuf[tid] + (isq ? g_bqe[o] : g_bke[o]);
            float sq = z * z;
            #pragma unroll
            for (int off = 8; off; off >>= 1)
                sq += __shfl_xor_sync(0xffffffffu, sq, off);
            float val = z * rsqrtf(sq + 1e-8f);
            (isq ? g_qq : g_kq)[(row0 + r) * QD_ + o] = val;
        }
        if (r + 1 < ERB)
            *(float4*)&xb[((r + 1) & 1) * H_ + tid * 4] = nxt;
        __syncthreads();
    }
}

// scores + softmax (poly exp) -> fp16 probs
__device__ __forceinline__ void attn_body(int bid)
{
    int b = bid >> 8;
    int q0 = (bid & 255) * 8;
    int tid = threadIdx.x;
    int lane = tid & 31, wid = tid >> 5;

    __shared__ float qs[8][QD_];
    __shared__ float red[8][9];

    if (tid < 128)
        ((float*)qs)[tid] = g_qq[((long long)b * S_ + q0) * QD_ + tid];
    __syncthreads();

    const float* kq = g_kq + (long long)b * S_ * QD_;
    float e[8][8];
    float sum[8] = {};

    #pragma unroll
    for (int j = 0; j < 8; j++) {
        int kk = tid + j * 256;
        const float4* kp = (const float4*)(kq + (long long)kk * QD_);
        float4 k0 = kp[0], k1 = kp[1], k2 = kp[2], k3 = kp[3];
        #pragma unroll
        for (int q = 0; q < 8; q++) {
            const float* qr = qs[q];
            float ov = qr[0]*k0.x + qr[1]*k0.y + qr[2]*k0.z + qr[3]*k0.w
                     + qr[4]*k1.x + qr[5]*k1.y + qr[6]*k1.z + qr[7]*k1.w
                     + qr[8]*k2.x + qr[9]*k2.y + qr[10]*k2.z + qr[11]*k2.w
                     + qr[12]*k3.x + qr[13]*k3.y + qr[14]*k3.z + qr[15]*k3.w;
            float ee = exp01(ov * ov);
            e[q][j] = ee;
            sum[q] += ee;
        }
    }

    #pragma unroll
    for (int q = 0; q < 8; q++) {
        float s = sum[q];
        #pragma unroll
        for (int off = 16; off; off >>= 1)
            s += __shfl_xor_sync(0xffffffffu, s, off);
        if (lane == 0) red[wid][q] = s;
    }
    __syncthreads();

    float inv[8];
    #pragma unroll
    for (int q = 0; q < 8; q++) {
        float t = 0.f;
        #pragma unroll
        for (int w = 0; w < 8; w++) t += red[w][q];
        inv[q] = 1.f / t;
    }

    #pragma unroll
    for (int q = 0; q < 8; q++) {
        long long rowo = ((long long)b * S_ + q0 + q) * S_;
        #pragma unroll
        for (int j = 0; j < 8; j++)
            g_attnh[rowo + tid + j * 256] = __float2half_rn(e[q][j] * inv[q]);
    }
}

// ---- split-fp16 GEMM body: CTA 128x256, warp 64x64, staged cp.async -------
#define APITCH 80
#define BPITCH 528
#define ATILE (128 * APITCH)           // 10240
#define BTILE (32 * BPITCH)            // 16896

template<bool ASPLIT, bool BSPLIT>
__device__ __forceinline__ void load_stage(u32 sb,
    const half* __restrict__ Ah, const half* __restrict__ Al,
    const half* __restrict__ Bh, const half* __restrict__ Bl,
    int bm, int bn, int k0, int K, int N, int tid)
{
    constexpr int BOFF = ATILE * (ASPLIT ? 2 : 1);
    #pragma unroll
    for (int i = 0; i < 2; i++) {
        int u = tid + i * 256;
        int r = u >> 2, c = u & 3;
        long long g = (long long)(bm + r) * K + k0 + c * 8;
        cpa16(sb + r * APITCH + c * 16, Ah + g);
        if (ASPLIT) cpa16(sb + ATILE + r * APITCH + c * 16, Al + g);
    }
    #pragma unroll
    for (int i = 0; i < 4; i++) {
        int u = tid + i * 256;
        int r = u >> 5, c = u & 31;
        long long g = (long long)(k0 + r) * N + bn + c * 8;
        cpa16(sb + BOFF + r * BPITCH + c * 16, Bh + g);
        if (BSPLIT) cpa16(sb + BOFF + BTILE + r * BPITCH + c * 16, Bl + g);
    }
}

template<bool ASPLIT, bool BSPLIT, int OMODE, int STAGES>
__device__ __forceinline__ void gemm_body(
    const half* __restrict__ Ah, const half* __restrict__ Al,
    const half* __restrict__ Bh, const half* __restrict__ Bl,
    const float* __restrict__ bias,
    float* __restrict__ Cf, half* __restrict__ Ch,
    int bm, int bn, int N, int K)
{
    constexpr int BOFF = ATILE * (ASPLIT ? 2 : 1);
    constexpr int STG  = BOFF + BTILE * (BSPLIT ? 2 : 1);

    extern __shared__ char dsm[];
    u32 sbase = smem_u32(dsm);

    const int tid = threadIdx.x;
    const int wid = tid >> 5, lane = tid & 31;
    const int wm = (wid >> 2) * 64;
    const int wn = (wid & 3) * 64;

    float acc[4][8][4] = {};

    const int NC = K >> 5;
    #pragma unroll
    for (int s = 0; s < STAGES - 1; s++) {
        load_stage<ASPLIT, BSPLIT>(sbase + s * STG, Ah, Al, Bh, Bl,
                                   bm, bn, s << 5, K, N, tid);
        CP_COMMIT();
    }

    const int arow = lane & 15;
    const int ak8  = ((lane >> 4) & 1) * 8;
    const int bk   = lane & 15;
    const int bn8  = ((lane >> 4) & 1) * 8;

    int ld = STAGES - 1;
    for (int c = 0; c < NC; c++) {
        CP_WAIT(STAGES - 2);
        __syncthreads();

        if (ld < NC) {
            load_stage<ASPLIT, BSPLIT>(sbase + (ld % STAGES) * STG,
                Ah, Al, Bh, Bl, bm, bn, ld << 5, K, N, tid);
            CP_COMMIT();
            ld++;
        }

        u32 st = sbase + (c % STAGES) * STG;
        u32 As = st, Als = st + ATILE;
        u32 Bs = st + BOFF, Bls = Bs + BTILE;

        #pragma unroll
        for (int ks = 0; ks < 32; ks += 16) {
            u32 bh[4][4], bl[4][4];
            #pragma unroll
            for (int n2 = 0; n2 < 4; n2++) {
                u32 boff = (ks + bk) * BPITCH + (wn + 16 * n2 + bn8) * 2;
                ldsm4t(bh[n2], Bs + boff);
                if (BSPLIT) ldsm4t(bl[n2], Bls + boff);
            }
            #pragma unroll
            for (int m = 0; m < 4; m++) {
                u32 ah[4], al[4];
                u32 aoff = (wm + 16 * m + arow) * APITCH + (ks + ak8) * 2;
                ldsm4(ah, As + aoff);
                if (ASPLIT) ldsm4(al, Als + aoff);
                #pragma unroll
                for (int j = 0; j < 8; j++) {
                    const u32* bhp = &bh[j >> 1][(j & 1) * 2];
                    mma16816(acc[m][j], ah, bhp);
                    if (ASPLIT) mma16816(acc[m][j], al, bhp);
                    if (BSPLIT) {
                        const u32* blp = &bl[j >> 1][(j & 1) * 2];
                        mma16816(acc[m][j], ah, blp);
                    }
                }
            }
        }
    }

    const int trow = lane >> 2;
    const int tcol = (lane & 3) * 2;

    #pragma unroll
    for (int m = 0; m < 4; m++) {
        #pragma unroll
        for (int j = 0; j < 8; j++) {
            int col = bn + wn + 8 * j + tcol;
            float b0 = bias ? bias[col] : 0.f;
            float b1 = bias ? bias[col + 1] : 0.f;
            #pragma unroll
            for (int h = 0; h < 2; h++) {
                long long row = bm + wm + 16 * m + trow + h * 8;
                float v0 = acc[m][j][2 * h + 0] + b0;
                float v1 = acc[m][j][2 * h + 1] + b1;
                long long idx = row * N + col;
                if (OMODE == 0)
                    *(float2*)(Cf + idx) = make_float2(v0, v1);
                else
                    *(half2*)(Ch + idx) = __floats2half2_rn(v0, v1);
            }
        }
    }
}

// ------------------------------ fat kernels --------------------------------

// L1: precompute(257) || b2(32) || weight splits(2048)
__global__ __launch_bounds__(256)
void prep_kernel(const float* __restrict__ Wq, const float* __restrict__ Wk,
                 const float* __restrict__ We, const float* __restrict__ bq,
                 const float* __restrict__ bk, const float* __restrict__ be,
                 const float* __restrict__ bv, const float* __restrict__ Wv,
                 const float* __restrict__ Wo)
{
    int bid = blockIdx.x;
    if (bid < 257)       precompute_body(bid, Wq, Wk, We, bq, bk, be);
    else if (bid < 289)  b2_body(bid - 257, bv, Wo);
    else                 split_body(bid - 289, Wv, Wo);
}

// L2: embed(128) || W2 = Wv@Wo 3-term GEMM (32 CTAs, tiles 4x8)
__global__ __launch_bounds__(256)
void embed_w2_kernel(const float* __restrict__ x)
{
    int bid = blockIdx.x;
    if (bid < 128) {
        embed_body(bid, x);
    } else {
        int t = bid - 128;                       // 0..31
        gemm_body<true, true, 2, 2>(g_Wvh, g_Wvl, g_Woh, g_Wol,
                                    nullptr, nullptr, g_W2h,
                                    (t >> 2) * 128, (t & 3) * 256, H_, H_);
    }
}

// L3: attn(1024) || v2 = xh@W2h + b2 (256 CTAs, tiles 4x64)
__global__ __launch_bounds__(256)
void attn_v2_kernel()
{
    int bid = blockIdx.x;
    if (bid < 1024) {
        attn_body(bid);
    } else {
        int t = bid - 1024;                      // 0..255
        gemm_body<false, false, 2, 3>(g_xh, nullptr, g_W2h, nullptr,
                                      g_b2, nullptr, g_v2h,
                                      (t >> 2) * 128, (t & 3) * 256, H_, H_);
    }
}

// L4: out = attn @ v2 + bo (256 CTAs: 4 bn x 16 bm x 4 batch)
__global__ __launch_bounds__(256)
void out_kernel(const float* __restrict__ bo, float* __restrict__ out)
{
    int t = blockIdx.x;
    int z = t >> 6;
    int r = t & 63;
    gemm_body<false, false, 0, 3>(
        g_attnh + (long long)z * S_ * S_, nullptr,
        g_v2h + (long long)z * S_ * H_, nullptr,
        bo, out + (long long)z * S_ * H_, nullptr,
        (r >> 2) * 128, (r & 3) * 256, H_, S_);
}

// ---------------------------------------------------------------------------
extern "C" void kernel_launch(void* const* d_in, const int* in_sizes, int n_in,
                              void* d_out, int out_size)
{
    const float* x  = (const float*)d_in[0];
    const float* Wq = (const float*)d_in[1];
    const float* bq = (const float*)d_in[2];
    const float* Wk = (const float*)d_in[3];
    const float* bk = (const float*)d_in[4];
    const float* Wv = (const float*)d_in[5];
    const float* bv = (const float*)d_in[6];
    const float* We = (const float*)d_in[7];
    const float* be = (const float*)d_in[8];
    const float* Wo = (const float*)d_in[9];
    const float* bo = (const float*)d_in[10];
    float* out = (float*)d_out;

    const int SM_L1 = H_ * 17 * 4;                 // 69632  (precompute)
    const int SM_L2 = (32 * H_ + 2 * H_) * 4;      // 139264 (embed; > W2's 108544)
    const int SM_L3 = 3 * (ATILE + BTILE);         // 81408  (3-stage 1-term)
    const int SM_L4 = SM_L3;

    cudaFuncSetAttribute(prep_kernel,     cudaFuncAttributeMaxDynamicSharedMemorySize, SM_L1);
    cudaFuncSetAttribute(embed_w2_kernel, cudaFuncAttributeMaxDynamicSharedMemorySize, SM_L2);
    cudaFuncSetAttribute(attn_v2_kernel,  cudaFuncAttributeMaxDynamicSharedMemorySize, SM_L3);
    cudaFuncSetAttribute(out_kernel,      cudaFuncAttributeMaxDynamicSharedMemorySize, SM_L4);

    prep_kernel<<<257 + 32 + 2048, 256, SM_L1>>>(Wq, Wk, We, bq, bk, be, bv, Wv, Wo);
    embed_w2_kernel<<<128 + 32, 256, SM_L2>>>(x);
    attn_v2_kernel<<<1024 + 256, 256, SM_L3>>>();
    out_kernel<<<256, 256, SM_L4>>>(bo, out);
}

// round 9
// speedup vs baseline: 5.1215x; 1.0384x over previous
#include <cuda_runtime.h>
#include <cuda_fp16.h>

// ---------------------------------------------------------------------------
// QuantumAttention, restructured:
//   out = attn @ (x @ (Wv@Wo) + bv@Wo) + bo,  attn = softmax((q_q.k_q)^2)
//   q_q = normalize(x @ (Wq@We) + (bq@We+be)), k_q likewise.
// R9: DAG-parallel fat kernels (4 launches); W2-GEMM on 64x256 CTA tiles
// (64 CTAs instead of 32) to fix L2-phase SM starvation.
// ---------------------------------------------------------------------------

#define B_ 4
#define S_ 2048
#define H_ 1024
#define QD_ 16
#define ROWS_ (B_ * S_)          // 8192

typedef unsigned int u32;

// ------------------------------- scratch ----------------------------------
__device__ float g_WqeT[QD_ * H_];
__device__ float g_WkeT[QD_ * H_];
__device__ float g_bqe[QD_];
__device__ float g_bke[QD_];
__device__ float g_qq[ROWS_ * QD_];
__device__ float g_kq[ROWS_ * QD_];
__device__ float g_b2[H_];

__device__ half g_xh[ROWS_ * H_];
__device__ half g_Wvh[H_ * H_];
__device__ half g_Wvl[H_ * H_];
__device__ half g_Woh[H_ * H_];
__device__ half g_Wol[H_ * H_];
__device__ half g_W2h[H_ * H_];
__device__ half g_v2h[ROWS_ * H_];
__device__ half g_attnh[(long long)B_ * S_ * S_];

// ----------------------------- PTX helpers --------------------------------
__device__ __forceinline__ u32 smem_u32(const void* p) {
    u32 a;
    asm("{ .reg .u64 t; cvta.to.shared.u64 t, %1; cvt.u32.u64 %0, t; }"
        : "=r"(a) : "l"(p));
    return a;
}
__device__ __forceinline__ void cpa16(u32 d, const void* g) {
    asm volatile("cp.async.cg.shared.global [%0], [%1], 16;" :: "r"(d), "l"(g));
}
#define CP_COMMIT() asm volatile("cp.async.commit_group;" ::: "memory")
#define CP_WAIT(n)  asm volatile("cp.async.wait_group %0;" :: "n"(n) : "memory")

__device__ __forceinline__ void ldsm4(u32* r, u32 a) {
    asm volatile("ldmatrix.sync.aligned.m8n8.x4.shared.b16 {%0,%1,%2,%3}, [%4];"
        : "=r"(r[0]), "=r"(r[1]), "=r"(r[2]), "=r"(r[3]) : "r"(a));
}
__device__ __forceinline__ void ldsm4t(u32* r, u32 a) {
    asm volatile("ldmatrix.sync.aligned.m8n8.x4.trans.shared.b16 {%0,%1,%2,%3}, [%4];"
        : "=r"(r[0]), "=r"(r[1]), "=r"(r[2]), "=r"(r[3]) : "r"(a));
}
__device__ __forceinline__ void mma16816(float* d, const u32* a, const u32* b) {
    asm volatile("mma.sync.aligned.m16n8k16.row.col.f32.f16.f16.f32 "
        "{%0,%1,%2,%3}, {%4,%5,%6,%7}, {%8,%9}, {%0,%1,%2,%3};"
        : "+f"(d[0]), "+f"(d[1]), "+f"(d[2]), "+f"(d[3])
        : "r"(a[0]), "r"(a[1]), "r"(a[2]), "r"(a[3]), "r"(b[0]), "r"(b[1]));
}

// exp(s), s in [0,1]: degree-6 Taylor around 0.5 (FMA pipe; rel err ~1.3e-6)
__device__ __forceinline__ float exp01(float s) {
    float u = s - 0.5f;
    float p = 1.f / 720.f;
    p = fmaf(p, u, 1.f / 120.f);
    p = fmaf(p, u, 1.f / 24.f);
    p = fmaf(p, u, 1.f / 6.f);
    p = fmaf(p, u, 0.5f);
    p = fmaf(p, u, 1.f);
    p = fmaf(p, u, 1.f);
    return p * 1.6487212707f;
}

// ---------------------------- role bodies ----------------------------------

__device__ __forceinline__ void precompute_body(int bid,
    const float* __restrict__ Wq, const float* __restrict__ Wk,
    const float* __restrict__ We, const float* __restrict__ bq,
    const float* __restrict__ bk, const float* __restrict__ be)
{
    extern __shared__ char dsm[];
    float* Wes = (float*)dsm;               // [1024][17]
    int tid = threadIdx.x;
    for (int idx = tid; idx < H_ * QD_; idx += 256)
        Wes[(idx >> 4) * 17 + (idx & 15)] = We[idx];
    __syncthreads();

    int wg = bid * 8 + (tid >> 5);
    if (wg >= 2 * (H_ + 1)) return;
    int m = wg / (H_ + 1);
    int i = wg % (H_ + 1);
    int lane = tid & 31;
    const float* W  = m ? Wk : Wq;
    const float* bb = m ? bk : bq;

    float p[QD_];
    #pragma unroll
    for (int o = 0; o < QD_; o++) p[o] = 0.f;

    for (int kk = 0; kk < H_ / 32; kk++) {
        int k = kk * 32 + lane;
        float w = (i < H_) ? W[(long long)i * H_ + k] : bb[k];
        const float* wr = &Wes[k * 17];
        #pragma unroll
        for (int o = 0; o < QD_; o++) p[o] = fmaf(w, wr[o], p[o]);
    }
    #pragma unroll
    for (int off = 16; off; off >>= 1)
        #pragma unroll
        for (int o = 0; o < QD_; o++)
            p[o] += __shfl_xor_sync(0xffffffffu, p[o], off);

    if (lane == 0) {
        if (i < H_) {
            float* dst = m ? g_WkeT : g_WqeT;
            #pragma unroll
            for (int o = 0; o < QD_; o++) dst[o * H_ + i] = p[o];
        } else {
            float* dst = m ? g_bke : g_bqe;
            #pragma unroll
            for (int o = 0; o < QD_; o++) dst[o] = p[o] + be[o];
        }
    }
}

__device__ __forceinline__ void b2_body(int bid,
    const float* __restrict__ bv, const float* __restrict__ Wo)
{
    __shared__ float red[8][33];
    int t = threadIdx.x;
    int n = bid * 32 + (t & 31);
    int ks = t >> 5;
    float s = 0.f;
    #pragma unroll 4
    for (int k = ks * 128; k < ks * 128 + 128; k++)
        s = fmaf(bv[k], Wo[(long long)k * H_ + n], s);
    red[ks][t & 31] = s;
    __syncthreads();
    if (t < 32) {
        float tot = 0.f;
        #pragma unroll
        for (int i = 0; i < 8; i++) tot += red[i][t];
        g_b2[bid * 32 + t] = tot;
    }
}

__device__ __forceinline__ void split_body(int sidx,
    const float* __restrict__ Wv, const float* __restrict__ Wo)
{
    bool second = sidx >= 1024;
    const float* src = second ? Wo : Wv;
    half* h = second ? g_Woh : g_Wvh;
    half* l = second ? g_Wol : g_Wvl;
    int i = (sidx & 1023) * 256 + threadIdx.x;
    float4 v = ((const float4*)src)[i];
    half a0 = __float2half_rn(v.x), a1 = __float2half_rn(v.y);
    half a2 = __float2half_rn(v.z), a3 = __float2half_rn(v.w);
    half2* hp = (half2*)h;
    half2* lp = (half2*)l;
    hp[2*i]   = __halves2half2(a0, a1);
    hp[2*i+1] = __halves2half2(a2, a3);
    lp[2*i]   = __floats2half2_rn(v.x - __half2float(a0), v.y - __half2float(a1));
    lp[2*i+1] = __floats2half2_rn(v.z - __half2float(a2), v.w - __half2float(a3));
}

#define ERB 64
__device__ __forceinline__ void embed_body(int bid, const float* __restrict__ x)
{
    extern __shared__ char dsm[];
    float* sm = (float*)dsm;
    float* Ws = sm;                       // [32][1024]
    float* xb = sm + 32 * H_;             // [2][1024]
    __shared__ float zbuf[32];

    int tid = threadIdx.x, lane = tid & 31, w = tid >> 5;

    for (int idx = tid; idx < QD_ * H_; idx += 256) {
        Ws[idx]            = g_WqeT[idx];
        Ws[QD_ * H_ + idx] = g_WkeT[idx];
    }
    long long row0 = (long long)bid * ERB;

    float4 nxt = *(const float4*)&x[row0 * H_ + tid * 4];
    *(float4*)&xb[tid * 4] = nxt;
    {
        half2* xp = (half2*)&g_xh[row0 * H_ + tid * 4];
        xp[0] = __floats2half2_rn(nxt.x, nxt.y);
        xp[1] = __floats2half2_rn(nxt.z, nxt.w);
    }
    __syncthreads();

    for (int r = 0; r < ERB; r++) {
        if (r + 1 < ERB) {
            nxt = *(const float4*)&x[(row0 + r + 1) * H_ + tid * 4];
            half2* xp = (half2*)&g_xh[(row0 + r + 1) * H_ + tid * 4];
            xp[0] = __floats2half2_rn(nxt.x, nxt.y);
            xp[1] = __floats2half2_rn(nxt.z, nxt.w);
        }

        const float* xs = xb + (r & 1) * H_;
        float xr[32];
        #pragma unroll
        for (int i = 0; i < 8; i++)
            *(float4*)&xr[i * 4] = *(const float4*)&xs[i * 128 + lane * 4];

        #pragma unroll
        for (int oo = 0; oo < 4; oo++) {
            int o = w * 4 + oo;
            const float* wrow = Ws + o * H_;
            float s = 0.f;
            #pragma unroll
            for (int i = 0; i < 8; i++) {
                float4 wv = *(const float4*)&wrow[i * 128 + lane * 4];
                s += xr[i*4]*wv.x + xr[i*4+1]*wv.y + xr[i*4+2]*wv.z + xr[i*4+3]*wv.w;
            }
            #pragma unroll
            for (int off = 16; off; off >>= 1)
                s += __shfl_xor_sync(0xffffffffu, s, off);
            if (lane == 0) zbuf[o] = s;
        }
        __syncthreads();

        if (tid < 32) {
            int o = tid & 15;
            bool isq = tid < 16;
            float z = zbuf[tid] + (isq ? g_bqe[o] : g_bke[o]);
            float sq = z * z;
            #pragma unroll
            for (int off = 8; off; off >>= 1)
                sq += __shfl_xor_sync(0xffffffffu, sq, off);
            float val = z * rsqrtf(sq + 1e-8f);
            (isq ? g_qq : g_kq)[(row0 + r) * QD_ + o] = val;
        }
        if (r + 1 < ERB)
            *(float4*)&xb[((r + 1) & 1) * H_ + tid * 4] = nxt;
        __syncthreads();
    }
}

__device__ __forceinline__ void attn_body(int bid)
{
    int b = bid >> 8;
    int q0 = (bid & 255) * 8;
    int tid = threadIdx.x;
    int lane = tid & 31, wid = tid >> 5;

    __shared__ float qs[8][QD_];
    __shared__ float red[8][9];

    if (tid < 128)
        ((float*)qs)[tid] = g_qq[((long long)b * S_ + q0) * QD_ + tid];
    __syncthreads();

    const float* kq = g_kq + (long long)b * S_ * QD_;
    float e[8][8];
    float sum[8] = {};

    #pragma unroll
    for (int j = 0; j < 8; j++) {
        int kk = tid + j * 256;
        const float4* kp = (const float4*)(kq + (long long)kk * QD_);
        float4 k0 = kp[0], k1 = kp[1], k2 = kp[2], k3 = kp[3];
        #pragma unroll
        for (int q = 0; q < 8; q++) {
            const float* qr = qs[q];
            float ov = qr[0]*k0.x + qr[1]*k0.y + qr[2]*k0.z + qr[3]*k0.w
                     + qr[4]*k1.x + qr[5]*k1.y + qr[6]*k1.z + qr[7]*k1.w
                     + qr[8]*k2.x + qr[9]*k2.y + qr[10]*k2.z + qr[11]*k2.w
                     + qr[12]*k3.x + qr[13]*k3.y + qr[14]*k3.z + qr[15]*k3.w;
            float ee = exp01(ov * ov);
            e[q][j] = ee;
            sum[q] += ee;
        }
    }

    #pragma unroll
    for (int q = 0; q < 8; q++) {
        float s = sum[q];
        #pragma unroll
        for (int off = 16; off; off >>= 1)
            s += __shfl_xor_sync(0xffffffffu, s, off);
        if (lane == 0) red[wid][q] = s;
    }
    __syncthreads();

    float inv[8];
    #pragma unroll
    for (int q = 0; q < 8; q++) {
        float t = 0.f;
        #pragma unroll
        for (int w = 0; w < 8; w++) t += red[w][q];
        inv[q] = 1.f / t;
    }

    #pragma unroll
    for (int q = 0; q < 8; q++) {
        long long rowo = ((long long)b * S_ + q0 + q) * S_;
        #pragma unroll
        for (int j = 0; j < 8; j++)
            g_attnh[rowo + tid + j * 256] = __float2half_rn(e[q][j] * inv[q]);
    }
}

// ---- split-fp16 GEMM body: CTA AMx256, warp (AM/2)x64, staged cp.async ----
#define APITCH 80
#define BPITCH 528
#define BTILE (32 * BPITCH)            // 16896

template<bool ASPLIT, bool BSPLIT, int AM>
__device__ __forceinline__ void load_stage(u32 sb,
    const half* __restrict__ Ah, const half* __restrict__ Al,
    const half* __restrict__ Bh, const half* __restrict__ Bl,
    int bm, int bn, int k0, int K, int N, int tid)
{
    constexpr int ATILEc = AM * APITCH;
    constexpr int BOFF = ATILEc * (ASPLIT ? 2 : 1);
    #pragma unroll
    for (int i = 0; i < AM / 64; i++) {
        int u = tid + i * 256;
        int r = u >> 2, c = u & 3;
        long long g = (long long)(bm + r) * K + k0 + c * 8;
        cpa16(sb + r * APITCH + c * 16, Ah + g);
        if (ASPLIT) cpa16(sb + ATILEc + r * APITCH + c * 16, Al + g);
    }
    #pragma unroll
    for (int i = 0; i < 4; i++) {
        int u = tid + i * 256;
        int r = u >> 5, c = u & 31;
        long long g = (long long)(k0 + r) * N + bn + c * 8;
        cpa16(sb + BOFF + r * BPITCH + c * 16, Bh + g);
        if (BSPLIT) cpa16(sb + BOFF + BTILE + r * BPITCH + c * 16, Bl + g);
    }
}

template<bool ASPLIT, bool BSPLIT, int OMODE, int STAGES, int AM>
__device__ __forceinline__ void gemm_body(
    const half* __restrict__ Ah, const half* __restrict__ Al,
    const half* __restrict__ Bh, const half* __restrict__ Bl,
    const float* __restrict__ bias,
    float* __restrict__ Cf, half* __restrict__ Ch,
    int bm, int bn, int N, int K)
{
    constexpr int ATILEc = AM * APITCH;
    constexpr int BOFF = ATILEc * (ASPLIT ? 2 : 1);
    constexpr int STG  = BOFF + BTILE * (BSPLIT ? 2 : 1);
    constexpr int MT   = AM / 32;           // 16-row m-tiles per warp

    extern __shared__ char dsm[];
    u32 sbase = smem_u32(dsm);

    const int tid = threadIdx.x;
    const int wid = tid >> 5, lane = tid & 31;
    const int wm = (wid >> 2) * (AM / 2);
    const int wn = (wid & 3) * 64;

    float acc[MT][8][4] = {};

    const int NC = K >> 5;
    #pragma unroll
    for (int s = 0; s < STAGES - 1; s++) {
        load_stage<ASPLIT, BSPLIT, AM>(sbase + s * STG, Ah, Al, Bh, Bl,
                                       bm, bn, s << 5, K, N, tid);
        CP_COMMIT();
    }

    const int arow = lane & 15;
    const int ak8  = ((lane >> 4) & 1) * 8;
    const int bk   = lane & 15;
    const int bn8  = ((lane >> 4) & 1) * 8;

    int ld = STAGES - 1;
    for (int c = 0; c < NC; c++) {
        CP_WAIT(STAGES - 2);
        __syncthreads();

        if (ld < NC) {
            load_stage<ASPLIT, BSPLIT, AM>(sbase + (ld % STAGES) * STG,
                Ah, Al, Bh, Bl, bm, bn, ld << 5, K, N, tid);
            CP_COMMIT();
            ld++;
        }

        u32 st = sbase + (c % STAGES) * STG;
        u32 As = st, Als = st + ATILEc;
        u32 Bs = st + BOFF, Bls = Bs + BTILE;

        #pragma unroll
        for (int ks = 0; ks < 32; ks += 16) {
            u32 bh[4][4], bl[4][4];
            #pragma unroll
            for (int n2 = 0; n2 < 4; n2++) {
                u32 boff = (ks + bk) * BPITCH + (wn + 16 * n2 + bn8) * 2;
                ldsm4t(bh[n2], Bs + boff);
                if (BSPLIT) ldsm4t(bl[n2], Bls + boff);
            }
            #pragma unroll
            for (int m = 0; m < MT; m++) {
                u32 ah[4], al[4];
                u32 aoff = (wm + 16 * m + arow) * APITCH + (ks + ak8) * 2;
                ldsm4(ah, As + aoff);
                if (ASPLIT) ldsm4(al, Als + aoff);
                #pragma unroll
                for (int j = 0; j < 8; j++) {
                    const u32* bhp = &bh[j >> 1][(j & 1) * 2];
                    mma16816(acc[m][j], ah, bhp);
                    if (ASPLIT) mma16816(acc[m][j], al, bhp);
                    if (BSPLIT) {
                        const u32* blp = &bl[j >> 1][(j & 1) * 2];
                        mma16816(acc[m][j], ah, blp);
                    }
                }
            }
        }
    }

    const int trow = lane >> 2;
    const int tcol = (lane & 3) * 2;

    #pragma unroll
    for (int m = 0; m < MT; m++) {
        #pragma unroll
        for (int j = 0; j < 8; j++) {
            int col = bn + wn + 8 * j + tcol;
            float b0 = bias ? bias[col] : 0.f;
            float b1 = bias ? bias[col + 1] : 0.f;
            #pragma unroll
            for (int h = 0; h < 2; h++) {
                long long row = bm + wm + 16 * m + trow + h * 8;
                float v0 = acc[m][j][2 * h + 0] + b0;
                float v1 = acc[m][j][2 * h + 1] + b1;
                long long idx = row * N + col;
                if (OMODE == 0)
                    *(float2*)(Cf + idx) = make_float2(v0, v1);
                else
                    *(half2*)(Ch + idx) = __floats2half2_rn(v0, v1);
            }
        }
    }
}

// ------------------------------ fat kernels --------------------------------

// L1: precompute(257) || b2(32) || weight splits(2048)
__global__ __launch_bounds__(256)
void prep_kernel(const float* __restrict__ Wq, const float* __restrict__ Wk,
                 const float* __restrict__ We, const float* __restrict__ bq,
                 const float* __restrict__ bk, const float* __restrict__ be,
                 const float* __restrict__ bv, const float* __restrict__ Wv,
                 const float* __restrict__ Wo)
{
    int bid = blockIdx.x;
    if (bid < 257)       precompute_body(bid, Wq, Wk, We, bq, bk, be);
    else if (bid < 289)  b2_body(bid - 257, bv, Wo);
    else                 split_body(bid - 289, Wv, Wo);
}

// L2: embed(128) || W2 = Wv@Wo 3-term GEMM (64 CTAs of 64x256)
__global__ __launch_bounds__(256)
void embed_w2_kernel(const float* __restrict__ x)
{
    int bid = blockIdx.x;
    if (bid < 128) {
        embed_body(bid, x);
    } else {
        int t = bid - 128;                       // 0..63
        gemm_body<true, true, 2, 2, 64>(g_Wvh, g_Wvl, g_Woh, g_Wol,
                                        nullptr, nullptr, g_W2h,
                                        (t >> 2) * 64, (t & 3) * 256, H_, H_);
    }
}

// L3: attn(1024) || v2 = xh@W2h + b2 (256 CTAs of 128x256)
__global__ __launch_bounds__(256)
void attn_v2_kernel()
{
    int bid = blockIdx.x;
    if (bid < 1024) {
        attn_body(bid);
    } else {
        int t = bid - 1024;                      // 0..255
        gemm_body<false, false, 2, 3, 128>(g_xh, nullptr, g_W2h, nullptr,
                                           g_b2, nullptr, g_v2h,
                                           (t >> 2) * 128, (t & 3) * 256, H_, H_);
    }
}

// L4: out = attn @ v2 + bo (256 CTAs: 4 bn x 16 bm x 4 batch)
__global__ __launch_bounds__(256)
void out_kernel(const float* __restrict__ bo, float* __restrict__ out)
{
    int t = blockIdx.x;
    int z = t >> 6;
    int r = t & 63;
    gemm_body<false, false, 0, 3, 128>(
        g_attnh + (long long)z * S_ * S_, nullptr,
        g_v2h + (long long)z * S_ * H_, nullptr,
        bo, out + (long long)z * S_ * H_, nullptr,
        (r >> 2) * 128, (r & 3) * 256, H_, S_);
}

// ---------------------------------------------------------------------------
extern "C" void kernel_launch(void* const* d_in, const int* in_sizes, int n_in,
                              void* d_out, int out_size)
{
    const float* x  = (const float*)d_in[0];
    const float* Wq = (const float*)d_in[1];
    const float* bq = (const float*)d_in[2];
    const float* Wk = (const float*)d_in[3];
    const float* bk = (const float*)d_in[4];
    const float* Wv = (const float*)d_in[5];
    const float* bv = (const float*)d_in[6];
    const float* We = (const float*)d_in[7];
    const float* be = (const float*)d_in[8];
    const float* Wo = (const float*)d_in[9];
    const float* bo = (const float*)d_in[10];
    float* out = (float*)d_out;

    const int SM_L1 = H_ * 17 * 4;                 // 69632  (precompute)
    const int SM_L2 = (32 * H_ + 2 * H_) * 4;      // 139264 (embed; > W2's 2*(2*5120+2*16896)=88064)
    const int SM_L3 = 3 * (128 * APITCH + BTILE);  // 81408  (3-stage 1-term AM=128)
    const int SM_L4 = SM_L3;

    cudaFuncSetAttribute(prep_kernel,     cudaFuncAttributeMaxDynamicSharedMemorySize, SM_L1);
    cudaFuncSetAttribute(embed_w2_kernel, cudaFuncAttributeMaxDynamicSharedMemorySize, SM_L2);
    cudaFuncSetAttribute(attn_v2_kernel,  cudaFuncAttributeMaxDynamicSharedMemorySize, SM_L3);
    cudaFuncSetAttribute(out_kernel,      cudaFuncAttributeMaxDynamicSharedMemorySize, SM_L4);

    prep_kernel<<<257 + 32 + 2048, 256, SM_L1>>>(Wq, Wk, We, bq, bk, be, bv, Wv, Wo);
    embed_w2_kernel<<<128 + 64, 256, SM_L2>>>(x);
    attn_v2_kernel<<<1024 + 256, 256, SM_L3>>>();
    out_kernel<<<256, 256, SM_L4>>>(bo, out);
}

// round 10
// speedup vs baseline: 5.3967x; 1.0537x over previous
#include <cuda_runtime.h>
#include <cuda_fp16.h>

// ---------------------------------------------------------------------------
// QuantumAttention, restructured:
//   out = attn @ (x @ (Wv@Wo) + bv@Wo) + bo,  attn = softmax((q_q.k_q)^2)
//   q_q = normalize(x @ (Wq@We) + (bq@We+be)), k_q likewise.
// R10: main-path GEMMs on 128x128 CTA tiles (warp 64x32, <=128 regs,
// 2 CTAs/SM) to cover HMMA bubbles; DAG-parallel fat kernels (4 launches).
// ---------------------------------------------------------------------------

#define B_ 4
#define S_ 2048
#define H_ 1024
#define QD_ 16
#define ROWS_ (B_ * S_)          // 8192

typedef unsigned int u32;

// ------------------------------- scratch ----------------------------------
__device__ float g_WqeT[QD_ * H_];
__device__ float g_WkeT[QD_ * H_];
__device__ float g_bqe[QD_];
__device__ float g_bke[QD_];
__device__ float g_qq[ROWS_ * QD_];
__device__ float g_kq[ROWS_ * QD_];
__device__ float g_b2[H_];

__device__ half g_xh[ROWS_ * H_];
__device__ half g_Wvh[H_ * H_];
__device__ half g_Wvl[H_ * H_];
__device__ half g_Woh[H_ * H_];
__device__ half g_Wol[H_ * H_];
__device__ half g_W2h[H_ * H_];
__device__ half g_v2h[ROWS_ * H_];
__device__ half g_attnh[(long long)B_ * S_ * S_];

// ----------------------------- PTX helpers --------------------------------
__device__ __forceinline__ u32 smem_u32(const void* p) {
    u32 a;
    asm("{ .reg .u64 t; cvta.to.shared.u64 t, %1; cvt.u32.u64 %0, t; }"
        : "=r"(a) : "l"(p));
    return a;
}
__device__ __forceinline__ void cpa16(u32 d, const void* g) {
    asm volatile("cp.async.cg.shared.global [%0], [%1], 16;" :: "r"(d), "l"(g));
}
#define CP_COMMIT() asm volatile("cp.async.commit_group;" ::: "memory")
#define CP_WAIT(n)  asm volatile("cp.async.wait_group %0;" :: "n"(n) : "memory")

__device__ __forceinline__ void ldsm4(u32* r, u32 a) {
    asm volatile("ldmatrix.sync.aligned.m8n8.x4.shared.b16 {%0,%1,%2,%3}, [%4];"
        : "=r"(r[0]), "=r"(r[1]), "=r"(r[2]), "=r"(r[3]) : "r"(a));
}
__device__ __forceinline__ void ldsm4t(u32* r, u32 a) {
    asm volatile("ldmatrix.sync.aligned.m8n8.x4.trans.shared.b16 {%0,%1,%2,%3}, [%4];"
        : "=r"(r[0]), "=r"(r[1]), "=r"(r[2]), "=r"(r[3]) : "r"(a));
}
__device__ __forceinline__ void mma16816(float* d, const u32* a, const u32* b) {
    asm volatile("mma.sync.aligned.m16n8k16.row.col.f32.f16.f16.f32 "
        "{%0,%1,%2,%3}, {%4,%5,%6,%7}, {%8,%9}, {%0,%1,%2,%3};"
        : "+f"(d[0]), "+f"(d[1]), "+f"(d[2]), "+f"(d[3])
        : "r"(a[0]), "r"(a[1]), "r"(a[2]), "r"(a[3]), "r"(b[0]), "r"(b[1]));
}

// exp(s), s in [0,1]: degree-6 Taylor around 0.5 (FMA pipe; rel err ~1.3e-6)
__device__ __forceinline__ float exp01(float s) {
    float u = s - 0.5f;
    float p = 1.f / 720.f;
    p = fmaf(p, u, 1.f / 120.f);
    p = fmaf(p, u, 1.f / 24.f);
    p = fmaf(p, u, 1.f / 6.f);
    p = fmaf(p, u, 0.5f);
    p = fmaf(p, u, 1.f);
    p = fmaf(p, u, 1.f);
    return p * 1.6487212707f;
}

// ---------------------------- role bodies ----------------------------------

__device__ __forceinline__ void precompute_body(int bid,
    const float* __restrict__ Wq, const float* __restrict__ Wk,
    const float* __restrict__ We, const float* __restrict__ bq,
    const float* __restrict__ bk, const float* __restrict__ be)
{
    extern __shared__ char dsm[];
    float* Wes = (float*)dsm;               // [1024][17]
    int tid = threadIdx.x;
    for (int idx = tid; idx < H_ * QD_; idx += 256)
        Wes[(idx >> 4) * 17 + (idx & 15)] = We[idx];
    __syncthreads();

    int wg = bid * 8 + (tid >> 5);
    if (wg >= 2 * (H_ + 1)) return;
    int m = wg / (H_ + 1);
    int i = wg % (H_ + 1);
    int lane = tid & 31;
    const float* W  = m ? Wk : Wq;
    const float* bb = m ? bk : bq;

    float p[QD_];
    #pragma unroll
    for (int o = 0; o < QD_; o++) p[o] = 0.f;

    for (int kk = 0; kk < H_ / 32; kk++) {
        int k = kk * 32 + lane;
        float w = (i < H_) ? W[(long long)i * H_ + k] : bb[k];
        const float* wr = &Wes[k * 17];
        #pragma unroll
        for (int o = 0; o < QD_; o++) p[o] = fmaf(w, wr[o], p[o]);
    }
    #pragma unroll
    for (int off = 16; off; off >>= 1)
        #pragma unroll
        for (int o = 0; o < QD_; o++)
            p[o] += __shfl_xor_sync(0xffffffffu, p[o], off);

    if (lane == 0) {
        if (i < H_) {
            float* dst = m ? g_WkeT : g_WqeT;
            #pragma unroll
            for (int o = 0; o < QD_; o++) dst[o * H_ + i] = p[o];
        } else {
            float* dst = m ? g_bke : g_bqe;
            #pragma unroll
            for (int o = 0; o < QD_; o++) dst[o] = p[o] + be[o];
        }
    }
}

__device__ __forceinline__ void b2_body(int bid,
    const float* __restrict__ bv, const float* __restrict__ Wo)
{
    __shared__ float red[8][33];
    int t = threadIdx.x;
    int n = bid * 32 + (t & 31);
    int ks = t >> 5;
    float s = 0.f;
    #pragma unroll 4
    for (int k = ks * 128; k < ks * 128 + 128; k++)
        s = fmaf(bv[k], Wo[(long long)k * H_ + n], s);
    red[ks][t & 31] = s;
    __syncthreads();
    if (t < 32) {
        float tot = 0.f;
        #pragma unroll
        for (int i = 0; i < 8; i++) tot += red[i][t];
        g_b2[bid * 32 + t] = tot;
    }
}

__device__ __forceinline__ void split_body(int sidx,
    const float* __restrict__ Wv, const float* __restrict__ Wo)
{
    bool second = sidx >= 1024;
    const float* src = second ? Wo : Wv;
    half* h = second ? g_Woh : g_Wvh;
    half* l = second ? g_Wol : g_Wvl;
    int i = (sidx & 1023) * 256 + threadIdx.x;
    float4 v = ((const float4*)src)[i];
    half a0 = __float2half_rn(v.x), a1 = __float2half_rn(v.y);
    half a2 = __float2half_rn(v.z), a3 = __float2half_rn(v.w);
    half2* hp = (half2*)h;
    half2* lp = (half2*)l;
    hp[2*i]   = __halves2half2(a0, a1);
    hp[2*i+1] = __halves2half2(a2, a3);
    lp[2*i]   = __floats2half2_rn(v.x - __half2float(a0), v.y - __half2float(a1));
    lp[2*i+1] = __floats2half2_rn(v.z - __half2float(a2), v.w - __half2float(a3));
}

#define ERB 64
__device__ __forceinline__ void embed_body(int bid, const float* __restrict__ x)
{
    extern __shared__ char dsm[];
    float* sm = (float*)dsm;
    float* Ws = sm;                       // [32][1024]
    float* xb = sm + 32 * H_;             // [2][1024]
    __shared__ float zbuf[32];

    int tid = threadIdx.x, lane = tid & 31, w = tid >> 5;

    for (int idx = tid; idx < QD_ * H_; idx += 256) {
        Ws[idx]            = g_WqeT[idx];
        Ws[QD_ * H_ + idx] = g_WkeT[idx];
    }
    long long row0 = (long long)bid * ERB;

    float4 nxt = *(const float4*)&x[row0 * H_ + tid * 4];
    *(float4*)&xb[tid * 4] = nxt;
    {
        half2* xp = (half2*)&g_xh[row0 * H_ + tid * 4];
        xp[0] = __floats2half2_rn(nxt.x, nxt.y);
        xp[1] = __floats2half2_rn(nxt.z, nxt.w);
    }
    __syncthreads();

    for (int r = 0; r < ERB; r++) {
        if (r + 1 < ERB) {
            nxt = *(const float4*)&x[(row0 + r + 1) * H_ + tid * 4];
            half2* xp = (half2*)&g_xh[(row0 + r + 1) * H_ + tid * 4];
            xp[0] = __floats2half2_rn(nxt.x, nxt.y);
            xp[1] = __floats2half2_rn(nxt.z, nxt.w);
        }

        const float* xs = xb + (r & 1) * H_;
        float xr[32];
        #pragma unroll
        for (int i = 0; i < 8; i++)
            *(float4*)&xr[i * 4] = *(const float4*)&xs[i * 128 + lane * 4];

        #pragma unroll
        for (int oo = 0; oo < 4; oo++) {
            int o = w * 4 + oo;
            const float* wrow = Ws + o * H_;
            float s = 0.f;
            #pragma unroll
            for (int i = 0; i < 8; i++) {
                float4 wv = *(const float4*)&wrow[i * 128 + lane * 4];
                s += xr[i*4]*wv.x + xr[i*4+1]*wv.y + xr[i*4+2]*wv.z + xr[i*4+3]*wv.w;
            }
            #pragma unroll
            for (int off = 16; off; off >>= 1)
                s += __shfl_xor_sync(0xffffffffu, s, off);
            if (lane == 0) zbuf[o] = s;
        }
        __syncthreads();

        if (tid < 32) {
            int o = tid & 15;
            bool isq = tid < 16;
            float z = zbuf[tid] + (isq ? g_bqe[o] : g_bke[o]);
            float sq = z * z;
            #pragma unroll
            for (int off = 8; off; off >>= 1)
                sq += __shfl_xor_sync(0xffffffffu, sq, off);
            float val = z * rsqrtf(sq + 1e-8f);
            (isq ? g_qq : g_kq)[(row0 + r) * QD_ + o] = val;
        }
        if (r + 1 < ERB)
            *(float4*)&xb[((r + 1) & 1) * H_ + tid * 4] = nxt;
        __syncthreads();
    }
}

__device__ __forceinline__ void attn_body(int bid)
{
    int b = bid >> 8;
    int q0 = (bid & 255) * 8;
    int tid = threadIdx.x;
    int lane = tid & 31, wid = tid >> 5;

    __shared__ float qs[8][QD_];
    __shared__ float red[8][9];

    if (tid < 128)
        ((float*)qs)[tid] = g_qq[((long long)b * S_ + q0) * QD_ + tid];
    __syncthreads();

    const float* kq = g_kq + (long long)b * S_ * QD_;
    float e[8][8];
    float sum[8] = {};

    #pragma unroll
    for (int j = 0; j < 8; j++) {
        int kk = tid + j * 256;
        const float4* kp = (const float4*)(kq + (long long)kk * QD_);
        float4 k0 = kp[0], k1 = kp[1], k2 = kp[2], k3 = kp[3];
        #pragma unroll
        for (int q = 0; q < 8; q++) {
            const float* qr = qs[q];
            float ov = qr[0]*k0.x + qr[1]*k0.y + qr[2]*k0.z + qr[3]*k0.w
                     + qr[4]*k1.x + qr[5]*k1.y + qr[6]*k1.z + qr[7]*k1.w
                     + qr[8]*k2.x + qr[9]*k2.y + qr[10]*k2.z + qr[11]*k2.w
                     + qr[12]*k3.x + qr[13]*k3.y + qr[14]*k3.z + qr[15]*k3.w;
            float ee = exp01(ov * ov);
            e[q][j] = ee;
            sum[q] += ee;
        }
    }

    #pragma unroll
    for (int q = 0; q < 8; q++) {
        float s = sum[q];
        #pragma unroll
        for (int off = 16; off; off >>= 1)
            s += __shfl_xor_sync(0xffffffffu, s, off);
        if (lane == 0) red[wid][q] = s;
    }
    __syncthreads();

    float inv[8];
    #pragma unroll
    for (int q = 0; q < 8; q++) {
        float t = 0.f;
        #pragma unroll
        for (int w = 0; w < 8; w++) t += red[w][q];
        inv[q] = 1.f / t;
    }

    #pragma unroll
    for (int q = 0; q < 8; q++) {
        long long rowo = ((long long)b * S_ + q0 + q) * S_;
        #pragma unroll
        for (int j = 0; j < 8; j++)
            g_attnh[rowo + tid + j * 256] = __float2half_rn(e[q][j] * inv[q]);
    }
}

// ---- split-fp16 GEMM body: CTA AMxBN, 8 warps (AM/2)x(BN/4), cp.async -----
#define APITCH 80

template<bool ASPLIT, bool BSPLIT, int AM, int BN>
__device__ __forceinline__ void load_stage(u32 sb,
    const half* __restrict__ Ah, const half* __restrict__ Al,
    const half* __restrict__ Bh, const half* __restrict__ Bl,
    int bm, int bn, int k0, int K, int N, int tid)
{
    constexpr int BPITCHc = BN * 2 + 16;
    constexpr int BTILEc  = 32 * BPITCHc;
    constexpr int ATILEc  = AM * APITCH;
    constexpr int BOFF    = ATILEc * (ASPLIT ? 2 : 1);
    #pragma unroll
    for (int i = 0; i < AM / 64; i++) {
        int u = tid + i * 256;
        int r = u >> 2, c = u & 3;
        long long g = (long long)(bm + r) * K + k0 + c * 8;
        cpa16(sb + r * APITCH + c * 16, Ah + g);
        if (ASPLIT) cpa16(sb + ATILEc + r * APITCH + c * 16, Al + g);
    }
    #pragma unroll
    for (int i = 0; i < BN / 64; i++) {
        int u = tid + i * 256;
        int r = u / (BN / 8), c = u % (BN / 8);
        long long g = (long long)(k0 + r) * N + bn + c * 8;
        cpa16(sb + BOFF + r * BPITCHc + c * 16, Bh + g);
        if (BSPLIT) cpa16(sb + BOFF + BTILEc + r * BPITCHc + c * 16, Bl + g);
    }
}

template<bool ASPLIT, bool BSPLIT, int OMODE, int STAGES, int AM, int BN>
__device__ __forceinline__ void gemm_body(
    const half* __restrict__ Ah, const half* __restrict__ Al,
    const half* __restrict__ Bh, const half* __restrict__ Bl,
    const float* __restrict__ bias,
    float* __restrict__ Cf, half* __restrict__ Ch,
    int bm, int bn, int N, int K)
{
    constexpr int BPITCHc = BN * 2 + 16;
    constexpr int BTILEc  = 32 * BPITCHc;
    constexpr int ATILEc  = AM * APITCH;
    constexpr int BOFF    = ATILEc * (ASPLIT ? 2 : 1);
    constexpr int STG     = BOFF + BTILEc * (BSPLIT ? 2 : 1);
    constexpr int MT      = AM / 32;        // 16-row m-tiles per warp
    constexpr int WN      = BN / 4;         // per-warp n width
    constexpr int NT      = WN / 16;        // ldsm4t tiles per warp
    constexpr int JN      = WN / 8;         // 8-col mma tiles per warp

    extern __shared__ char dsm[];
    u32 sbase = smem_u32(dsm);

    const int tid = threadIdx.x;
    const int wid = tid >> 5, lane = tid & 31;
    const int wm = (wid >> 2) * (AM / 2);
    const int wn = (wid & 3) * WN;

    float acc[MT][JN][4] = {};

    const int NC = K >> 5;
    #pragma unroll
    for (int s = 0; s < STAGES - 1; s++) {
        load_stage<ASPLIT, BSPLIT, AM, BN>(sbase + s * STG, Ah, Al, Bh, Bl,
                                           bm, bn, s << 5, K, N, tid);
        CP_COMMIT();
    }

    const int arow = lane & 15;
    const int ak8  = ((lane >> 4) & 1) * 8;
    const int bk   = lane & 15;
    const int bn8  = ((lane >> 4) & 1) * 8;

    int ld = STAGES - 1;
    for (int c = 0; c < NC; c++) {
        CP_WAIT(STAGES - 2);
        __syncthreads();

        if (ld < NC) {
            load_stage<ASPLIT, BSPLIT, AM, BN>(sbase + (ld % STAGES) * STG,
                Ah, Al, Bh, Bl, bm, bn, ld << 5, K, N, tid);
            CP_COMMIT();
            ld++;
        }

        u32 st = sbase + (c % STAGES) * STG;
        u32 As = st, Als = st + ATILEc;
        u32 Bs = st + BOFF, Bls = Bs + BTILEc;

        #pragma unroll
        for (int ks = 0; ks < 32; ks += 16) {
            u32 bh[NT][4], bl[NT][4];
            #pragma unroll
            for (int n2 = 0; n2 < NT; n2++) {
                u32 boff = (ks + bk) * BPITCHc + (wn + 16 * n2 + bn8) * 2;
                ldsm4t(bh[n2], Bs + boff);
                if (BSPLIT) ldsm4t(bl[n2], Bls + boff);
            }
            #pragma unroll
            for (int m = 0; m < MT; m++) {
                u32 ah[4], al[4];
                u32 aoff = (wm + 16 * m + arow) * APITCH + (ks + ak8) * 2;
                ldsm4(ah, As + aoff);
                if (ASPLIT) ldsm4(al, Als + aoff);
                #pragma unroll
                for (int j = 0; j < JN; j++) {
                    const u32* bhp = &bh[j >> 1][(j & 1) * 2];
                    mma16816(acc[m][j], ah, bhp);
                    if (ASPLIT) mma16816(acc[m][j], al, bhp);
                    if (BSPLIT) {
                        const u32* blp = &bl[j >> 1][(j & 1) * 2];
                        mma16816(acc[m][j], ah, blp);
                    }
                }
            }
        }
    }

    const int trow = lane >> 2;
    const int tcol = (lane & 3) * 2;

    #pragma unroll
    for (int m = 0; m < MT; m++) {
        #pragma unroll
        for (int j = 0; j < JN; j++) {
            int col = bn + wn + 8 * j + tcol;
            float b0 = bias ? bias[col] : 0.f;
            float b1 = bias ? bias[col + 1] : 0.f;
            #pragma unroll
            for (int h = 0; h < 2; h++) {
                long long row = bm + wm + 16 * m + trow + h * 8;
                float v0 = acc[m][j][2 * h + 0] + b0;
                float v1 = acc[m][j][2 * h + 1] + b1;
                long long idx = row * N + col;
                if (OMODE == 0)
                    *(float2*)(Cf + idx) = make_float2(v0, v1);
                else
                    *(half2*)(Ch + idx) = __floats2half2_rn(v0, v1);
            }
        }
    }
}

// ------------------------------ fat kernels --------------------------------

// L1: precompute(257) || b2(32) || weight splits(2048)
__global__ __launch_bounds__(256)
void prep_kernel(const float* __restrict__ Wq, const float* __restrict__ Wk,
                 const float* __restrict__ We, const float* __restrict__ bq,
                 const float* __restrict__ bk, const float* __restrict__ be,
                 const float* __restrict__ bv, const float* __restrict__ Wv,
                 const float* __restrict__ Wo)
{
    int bid = blockIdx.x;
    if (bid < 257)       precompute_body(bid, Wq, Wk, We, bq, bk, be);
    else if (bid < 289)  b2_body(bid - 257, bv, Wo);
    else                 split_body(bid - 289, Wv, Wo);
}

// L2: embed(128) || W2 = Wv@Wo 3-term GEMM (64 CTAs of 64x256)
__global__ __launch_bounds__(256)
void embed_w2_kernel(const float* __restrict__ x)
{
    int bid = blockIdx.x;
    if (bid < 128) {
        embed_body(bid, x);
    } else {
        int t = bid - 128;                       // 0..63
        gemm_body<true, true, 2, 2, 64, 256>(g_Wvh, g_Wvl, g_Woh, g_Wol,
                                             nullptr, nullptr, g_W2h,
                                             (t >> 2) * 64, (t & 3) * 256, H_, H_);
    }
}

// L3: attn(1024) || v2 = xh@W2h + b2 (512 CTAs of 128x128, 2 CTAs/SM)
__global__ __launch_bounds__(256, 2)
void attn_v2_kernel()
{
    int bid = blockIdx.x;
    if (bid < 1024) {
        attn_body(bid);
    } else {
        int t = bid - 1024;                      // 0..511
        gemm_body<false, false, 2, 3, 128, 128>(g_xh, nullptr, g_W2h, nullptr,
                                                g_b2, nullptr, g_v2h,
                                                (t >> 3) * 128, (t & 7) * 128, H_, H_);
    }
}

// L4: out = attn @ v2 + bo (512 CTAs of 128x128: 16 bm x 8 bn x 4 z)
__global__ __launch_bounds__(256, 2)
void out_kernel(const float* __restrict__ bo, float* __restrict__ out)
{
    int t = blockIdx.x;
    int z = t >> 7;
    int r = t & 127;
    gemm_body<false, false, 0, 3, 128, 128>(
        g_attnh + (long long)z * S_ * S_, nullptr,
        g_v2h + (long long)z * S_ * H_, nullptr,
        bo, out + (long long)z * S_ * H_, nullptr,
        (r >> 3) * 128, (r & 7) * 128, H_, S_);
}

// ---------------------------------------------------------------------------
extern "C" void kernel_launch(void* const* d_in, const int* in_sizes, int n_in,
                              void* d_out, int out_size)
{
    const float* x  = (const float*)d_in[0];
    const float* Wq = (const float*)d_in[1];
    const float* bq = (const float*)d_in[2];
    const float* Wk = (const float*)d_in[3];
    const float* bk = (const float*)d_in[4];
    const float* Wv = (const float*)d_in[5];
    const float* bv = (const float*)d_in[6];
    const float* We = (const float*)d_in[7];
    const float* be = (const float*)d_in[8];
    const float* Wo = (const float*)d_in[9];
    const float* bo = (const float*)d_in[10];
    float* out = (float*)d_out;

    const int SM_L1 = H_ * 17 * 4;                       // 69632  (precompute)
    const int SM_L2 = (32 * H_ + 2 * H_) * 4;            // 139264 (embed)
    const int SM_L3 = 3 * (128 * APITCH + 32 * (128 * 2 + 16));  // 56832
    const int SM_L4 = SM_L3;

    cudaFuncSetAttribute(prep_kernel,     cudaFuncAttributeMaxDynamicSharedMemorySize, SM_L1);
    cudaFuncSetAttribute(embed_w2_kernel, cudaFuncAttributeMaxDynamicSharedMemorySize, SM_L2);
    cudaFuncSetAttribute(attn_v2_kernel,  cudaFuncAttributeMaxDynamicSharedMemorySize, SM_L3);
    cudaFuncSetAttribute(out_kernel,      cudaFuncAttributeMaxDynamicSharedMemorySize, SM_L4);

    prep_kernel<<<257 + 32 + 2048, 256, SM_L1>>>(Wq, Wk, We, bq, bk, be, bv, Wv, Wo);
    embed_w2_kernel<<<128 + 64, 256, SM_L2>>>(x);
    attn_v2_kernel<<<1024 + 512, 256, SM_L3>>>();
    out_kernel<<<512, 256, SM_L4>>>(bo, out);
}

// round 13
// speedup vs baseline: 5.9140x; 1.0958x over previous
#include <cuda_runtime.h>
#include <cuda_fp16.h>

// ---------------------------------------------------------------------------
// QuantumAttention, restructured:
//   out = attn @ (x @ (Wv@Wo) + bv@Wo) + bo,  attn = softmax((q_q.k_q)^2)
//   q_q = normalize(x @ (Wq@We) + (bq@We+be)), k_q likewise.
// R13: R12 design with the embed shuffle deadlock fixed (full-warp-active
// reduction, as in R10). W2 3-term on 64x128 2-stage tiles; embed split
// into q/k blocks (72KB smem) so the whole L2 launch runs 2 CTAs/SM.
// Numerics bitwise-identical to R10 (rel_err must be 4.042953e-4).
// ---------------------------------------------------------------------------

#define B_ 4
#define S_ 2048
#define H_ 1024
#define QD_ 16
#define ROWS_ (B_ * S_)          // 8192

typedef unsigned int u32;

// ------------------------------- scratch ----------------------------------
__device__ float g_WqeT[QD_ * H_];
__device__ float g_WkeT[QD_ * H_];
__device__ float g_bqe[QD_];
__device__ float g_bke[QD_];
__device__ float g_qq[ROWS_ * QD_];
__device__ float g_kq[ROWS_ * QD_];
__device__ float g_b2[H_];

__device__ half g_xh[ROWS_ * H_];
__device__ half g_Wvh[H_ * H_];
__device__ half g_Wvl[H_ * H_];
__device__ half g_Woh[H_ * H_];
__device__ half g_Wol[H_ * H_];
__device__ half g_W2h[H_ * H_];
__device__ half g_v2h[ROWS_ * H_];
__device__ half g_attnh[(long long)B_ * S_ * S_];

// ----------------------------- PTX helpers --------------------------------
__device__ __forceinline__ u32 smem_u32(const void* p) {
    u32 a;
    asm("{ .reg .u64 t; cvta.to.shared.u64 t, %1; cvt.u32.u64 %0, t; }"
        : "=r"(a) : "l"(p));
    return a;
}
__device__ __forceinline__ void cpa16(u32 d, const void* g) {
    asm volatile("cp.async.cg.shared.global [%0], [%1], 16;" :: "r"(d), "l"(g));
}
#define CP_COMMIT() asm volatile("cp.async.commit_group;" ::: "memory")
#define CP_WAIT(n)  asm volatile("cp.async.wait_group %0;" :: "n"(n) : "memory")

__device__ __forceinline__ void ldsm4(u32* r, u32 a) {
    asm volatile("ldmatrix.sync.aligned.m8n8.x4.shared.b16 {%0,%1,%2,%3}, [%4];"
        : "=r"(r[0]), "=r"(r[1]), "=r"(r[2]), "=r"(r[3]) : "r"(a));
}
__device__ __forceinline__ void ldsm4t(u32* r, u32 a) {
    asm volatile("ldmatrix.sync.aligned.m8n8.x4.trans.shared.b16 {%0,%1,%2,%3}, [%4];"
        : "=r"(r[0]), "=r"(r[1]), "=r"(r[2]), "=r"(r[3]) : "r"(a));
}
__device__ __forceinline__ void mma16816(float* d, const u32* a, const u32* b) {
    asm volatile("mma.sync.aligned.m16n8k16.row.col.f32.f16.f16.f32 "
        "{%0,%1,%2,%3}, {%4,%5,%6,%7}, {%8,%9}, {%0,%1,%2,%3};"
        : "+f"(d[0]), "+f"(d[1]), "+f"(d[2]), "+f"(d[3])
        : "r"(a[0]), "r"(a[1]), "r"(a[2]), "r"(a[3]), "r"(b[0]), "r"(b[1]));
}

// exp(s), s in [0,1]: degree-6 Taylor around 0.5 (FMA pipe; rel err ~1.3e-6)
__device__ __forceinline__ float exp01(float s) {
    float u = s - 0.5f;
    float p = 1.f / 720.f;
    p = fmaf(p, u, 1.f / 120.f);
    p = fmaf(p, u, 1.f / 24.f);
    p = fmaf(p, u, 1.f / 6.f);
    p = fmaf(p, u, 0.5f);
    p = fmaf(p, u, 1.f);
    p = fmaf(p, u, 1.f);
    return p * 1.6487212707f;
}

// ---------------------------- role bodies ----------------------------------

__device__ __forceinline__ void precompute_body(int bid,
    const float* __restrict__ Wq, const float* __restrict__ Wk,
    const float* __restrict__ We, const float* __restrict__ bq,
    const float* __restrict__ bk, const float* __restrict__ be)
{
    extern __shared__ char dsm[];
    float* Wes = (float*)dsm;               // [1024][17]
    int tid = threadIdx.x;
    for (int idx = tid; idx < H_ * QD_; idx += 256)
        Wes[(idx >> 4) * 17 + (idx & 15)] = We[idx];
    __syncthreads();

    int wg = bid * 8 + (tid >> 5);
    if (wg >= 2 * (H_ + 1)) return;
    int m = wg / (H_ + 1);
    int i = wg % (H_ + 1);
    int lane = tid & 31;
    const float* W  = m ? Wk : Wq;
    const float* bb = m ? bk : bq;

    float p[QD_];
    #pragma unroll
    for (int o = 0; o < QD_; o++) p[o] = 0.f;

    for (int kk = 0; kk < H_ / 32; kk++) {
        int k = kk * 32 + lane;
        float w = (i < H_) ? W[(long long)i * H_ + k] : bb[k];
        const float* wr = &Wes[k * 17];
        #pragma unroll
        for (int o = 0; o < QD_; o++) p[o] = fmaf(w, wr[o], p[o]);
    }
    #pragma unroll
    for (int off = 16; off; off >>= 1)
        #pragma unroll
        for (int o = 0; o < QD_; o++)
            p[o] += __shfl_xor_sync(0xffffffffu, p[o], off);

    if (lane == 0) {
        if (i < H_) {
            float* dst = m ? g_WkeT : g_WqeT;
            #pragma unroll
            for (int o = 0; o < QD_; o++) dst[o * H_ + i] = p[o];
        } else {
            float* dst = m ? g_bke : g_bqe;
            #pragma unroll
            for (int o = 0; o < QD_; o++) dst[o] = p[o] + be[o];
        }
    }
}

__device__ __forceinline__ void b2_body(int bid,
    const float* __restrict__ bv, const float* __restrict__ Wo)
{
    __shared__ float red[8][33];
    int t = threadIdx.x;
    int n = bid * 32 + (t & 31);
    int ks = t >> 5;
    float s = 0.f;
    #pragma unroll 4
    for (int k = ks * 128; k < ks * 128 + 128; k++)
        s = fmaf(bv[k], Wo[(long long)k * H_ + n], s);
    red[ks][t & 31] = s;
    __syncthreads();
    if (t < 32) {
        float tot = 0.f;
        #pragma unroll
        for (int i = 0; i < 8; i++) tot += red[i][t];
        g_b2[bid * 32 + t] = tot;
    }
}

// fp32 -> fp16 hi+lo split of Wv / Wo
__device__ __forceinline__ void split_body(int sidx,
    const float* __restrict__ Wv, const float* __restrict__ Wo)
{
    bool second = sidx >= 1024;
    const float* src = second ? Wo : Wv;
    half* h = second ? g_Woh : g_Wvh;
    half* l = second ? g_Wol : g_Wvl;
    int i = (sidx & 1023) * 256 + threadIdx.x;
    float4 v = ((const float4*)src)[i];
    half a0 = __float2half_rn(v.x), a1 = __float2half_rn(v.y);
    half a2 = __float2half_rn(v.z), a3 = __float2half_rn(v.w);
    half2* hp = (half2*)h;
    half2* lp = (half2*)l;
    hp[2*i]   = __halves2half2(a0, a1);
    hp[2*i+1] = __halves2half2(a2, a3);
    lp[2*i]   = __floats2half2_rn(v.x - __half2float(a0), v.y - __half2float(a1));
    lp[2*i+1] = __floats2half2_rn(v.z - __half2float(a2), v.w - __half2float(a3));
}

// embed (q-or-k half): 64 rows/block, 16 dims; q-blocks also emit xh (fp16).
// 16*1024 fp32 W stage + 2*1024 fp32 x double-buffer = 72KB smem.
#define ERB 64
__device__ __forceinline__ void embed_body16(int bid, const float* __restrict__ x,
                                             bool isq)
{
    extern __shared__ char dsm[];
    float* sm = (float*)dsm;
    float* Ws = sm;                       // [16][1024]
    float* xb = sm + QD_ * H_;            // [2][1024]
    __shared__ float zbuf[QD_];

    int tid = threadIdx.x, lane = tid & 31, w = tid >> 5;

    const float* WT = isq ? g_WqeT : g_WkeT;
    for (int idx = tid; idx < QD_ * H_; idx += 256)
        Ws[idx] = WT[idx];
    long long row0 = (long long)bid * ERB;

    float4 nxt = *(const float4*)&x[row0 * H_ + tid * 4];
    *(float4*)&xb[tid * 4] = nxt;
    if (isq) {
        half2* xp = (half2*)&g_xh[row0 * H_ + tid * 4];
        xp[0] = __floats2half2_rn(nxt.x, nxt.y);
        xp[1] = __floats2half2_rn(nxt.z, nxt.w);
    }
    __syncthreads();

    for (int r = 0; r < ERB; r++) {
        if (r + 1 < ERB) {
            nxt = *(const float4*)&x[(row0 + r + 1) * H_ + tid * 4];
            if (isq) {
                half2* xp = (half2*)&g_xh[(row0 + r + 1) * H_ + tid * 4];
                xp[0] = __floats2half2_rn(nxt.x, nxt.y);
                xp[1] = __floats2half2_rn(nxt.z, nxt.w);
            }
        }

        const float* xs = xb + (r & 1) * H_;
        float xr[32];
        #pragma unroll
        for (int i = 0; i < 8; i++)
            *(float4*)&xr[i * 4] = *(const float4*)&xs[i * 128 + lane * 4];

        #pragma unroll
        for (int oo = 0; oo < 2; oo++) {
            int o = w * 2 + oo;
            const float* wrow = Ws + o * H_;
            float s = 0.f;
            #pragma unroll
            for (int i = 0; i < 8; i++) {
                float4 wv = *(const float4*)&wrow[i * 128 + lane * 4];
                s += xr[i*4]*wv.x + xr[i*4+1]*wv.y + xr[i*4+2]*wv.z + xr[i*4+3]*wv.w;
            }
            #pragma unroll
            for (int off = 16; off; off >>= 1)
                s += __shfl_xor_sync(0xffffffffu, s, off);
            if (lane == 0) zbuf[o] = s;
        }
        __syncthreads();

        // Full warp active (fixes R12 deadlock): both 16-lane halves compute
        // the same dim o = tid & 15; reduction offsets 8..1 stay in-half;
        // only lanes 0..15 write.
        if (tid < 32) {
            int o = tid & 15;
            float z = zbuf[o] + (isq ? g_bqe[o] : g_bke[o]);
            float sq = z * z;
            #pragma unroll
            for (int off = 8; off; off >>= 1)
                sq += __shfl_xor_sync(0xffffffffu, sq, off);
            float val = z * rsqrtf(sq + 1e-8f);
            if (tid < QD_)
                (isq ? g_qq : g_kq)[(row0 + r) * QD_ + o] = val;
        }
        if (r + 1 < ERB)
            *(float4*)&xb[((r + 1) & 1) * H_ + tid * 4] = nxt;
        __syncthreads();
    }
}

__device__ __forceinline__ void attn_body(int bid)
{
    int b = bid >> 8;
    int q0 = (bid & 255) * 8;
    int tid = threadIdx.x;
    int lane = tid & 31, wid = tid >> 5;

    __shared__ float qs[8][QD_];
    __shared__ float red[8][9];

    if (tid < 128)
        ((float*)qs)[tid] = g_qq[((long long)b * S_ + q0) * QD_ + tid];
    __syncthreads();

    const float* kq = g_kq + (long long)b * S_ * QD_;
    float e[8][8];
    float sum[8] = {};

    #pragma unroll
    for (int j = 0; j < 8; j++) {
        int kk = tid + j * 256;
        const float4* kp = (const float4*)(kq + (long long)kk * QD_);
        float4 k0 = kp[0], k1 = kp[1], k2 = kp[2], k3 = kp[3];
        #pragma unroll
        for (int q = 0; q < 8; q++) {
            const float* qr = qs[q];
            float ov = qr[0]*k0.x + qr[1]*k0.y + qr[2]*k0.z + qr[3]*k0.w
                     + qr[4]*k1.x + qr[5]*k1.y + qr[6]*k1.z + qr[7]*k1.w
                     + qr[8]*k2.x + qr[9]*k2.y + qr[10]*k2.z + qr[11]*k2.w
                     + qr[12]*k3.x + qr[13]*k3.y + qr[14]*k3.z + qr[15]*k3.w;
            float ee = exp01(ov * ov);
            e[q][j] = ee;
            sum[q] += ee;
        }
    }

    #pragma unroll
    for (int q = 0; q < 8; q++) {
        float s = sum[q];
        #pragma unroll
        for (int off = 16; off; off >>= 1)
            s += __shfl_xor_sync(0xffffffffu, s, off);
        if (lane == 0) red[wid][q] = s;
    }
    __syncthreads();

    float inv[8];
    #pragma unroll
    for (int q = 0; q < 8; q++) {
        float t = 0.f;
        #pragma unroll
        for (int w = 0; w < 8; w++) t += red[w][q];
        inv[q] = 1.f / t;
    }

    #pragma unroll
    for (int q = 0; q < 8; q++) {
        long long rowo = ((long long)b * S_ + q0 + q) * S_;
        #pragma unroll
        for (int j = 0; j < 8; j++)
            g_attnh[rowo + tid + j * 256] = __float2half_rn(e[q][j] * inv[q]);
    }
}

// ---- split-fp16 GEMM body: CTA AMxBN, 8 warps (AM/2)x(BN/4), cp.async -----
#define APITCH 80

template<bool ASPLIT, bool BSPLIT, int AM, int BN>
__device__ __forceinline__ void load_stage(u32 sb,
    const half* __restrict__ Ah, const half* __restrict__ Al,
    const half* __restrict__ Bh, const half* __restrict__ Bl,
    int bm, int bn, int k0, int K, int N, int tid)
{
    constexpr int BPITCHc = BN * 2 + 16;
    constexpr int BTILEc  = 32 * BPITCHc;
    constexpr int ATILEc  = AM * APITCH;
    constexpr int BOFF    = ATILEc * (ASPLIT ? 2 : 1);
    #pragma unroll
    for (int i = 0; i < AM / 64; i++) {
        int u = tid + i * 256;
        int r = u >> 2, c = u & 3;
        long long g = (long long)(bm + r) * K + k0 + c * 8;
        cpa16(sb + r * APITCH + c * 16, Ah + g);
        if (ASPLIT) cpa16(sb + ATILEc + r * APITCH + c * 16, Al + g);
    }
    #pragma unroll
    for (int i = 0; i < BN / 64; i++) {
        int u = tid + i * 256;
        int r = u / (BN / 8), c = u % (BN / 8);
        long long g = (long long)(k0 + r) * N + bn + c * 8;
        cpa16(sb + BOFF + r * BPITCHc + c * 16, Bh + g);
        if (BSPLIT) cpa16(sb + BOFF + BTILEc + r * BPITCHc + c * 16, Bl + g);
    }
}

template<bool ASPLIT, bool BSPLIT, int OMODE, int STAGES, int AM, int BN>
__device__ __forceinline__ void gemm_body(
    const half* __restrict__ Ah, const half* __restrict__ Al,
    const half* __restrict__ Bh, const half* __restrict__ Bl,
    const float* __restrict__ bias,
    float* __restrict__ Cf, half* __restrict__ Ch,
    int bm, int bn, int N, int K)
{
    constexpr int BPITCHc = BN * 2 + 16;
    constexpr int BTILEc  = 32 * BPITCHc;
    constexpr int ATILEc  = AM * APITCH;
    constexpr int BOFF    = ATILEc * (ASPLIT ? 2 : 1);
    constexpr int STG     = BOFF + BTILEc * (BSPLIT ? 2 : 1);
    constexpr int MT      = AM / 32;        // 16-row m-tiles per warp
    constexpr int WN      = BN / 4;         // per-warp n width
    constexpr int NT      = WN / 16;        // ldsm4t tiles per warp
    constexpr int JN      = WN / 8;         // 8-col mma tiles per warp

    extern __shared__ char dsm[];
    u32 sbase = smem_u32(dsm);

    const int tid = threadIdx.x;
    const int wid = tid >> 5, lane = tid & 31;
    const int wm = (wid >> 2) * (AM / 2);
    const int wn = (wid & 3) * WN;

    float acc[MT][JN][4] = {};

    const int NC = K >> 5;
    #pragma unroll
    for (int s = 0; s < STAGES - 1; s++) {
        load_stage<ASPLIT, BSPLIT, AM, BN>(sbase + s * STG, Ah, Al, Bh, Bl,
                                           bm, bn, s << 5, K, N, tid);
        CP_COMMIT();
    }

    const int arow = lane & 15;
    const int ak8  = ((lane >> 4) & 1) * 8;
    const int bk   = lane & 15;
    const int bn8  = ((lane >> 4) & 1) * 8;

    int ld = STAGES - 1;
    for (int c = 0; c < NC; c++) {
        CP_WAIT(STAGES - 2);
        __syncthreads();

        if (ld < NC) {
            load_stage<ASPLIT, BSPLIT, AM, BN>(sbase + (ld % STAGES) * STG,
                Ah, Al, Bh, Bl, bm, bn, ld << 5, K, N, tid);
            CP_COMMIT();
            ld++;
        }

        u32 st = sbase + (c % STAGES) * STG;
        u32 As = st, Als = st + ATILEc;
        u32 Bs = st + BOFF, Bls = Bs + BTILEc;

        #pragma unroll
        for (int ks = 0; ks < 32; ks += 16) {
            u32 bh[NT][4], bl[NT][4];
            #pragma unroll
            for (int n2 = 0; n2 < NT; n2++) {
                u32 boff = (ks + bk) * BPITCHc + (wn + 16 * n2 + bn8) * 2;
                ldsm4t(bh[n2], Bs + boff);
                if (BSPLIT) ldsm4t(bl[n2], Bls + boff);
            }
            #pragma unroll
            for (int m = 0; m < MT; m++) {
                u32 ah[4], al[4];
                u32 aoff = (wm + 16 * m + arow) * APITCH + (ks + ak8) * 2;
                ldsm4(ah, As + aoff);
                if (ASPLIT) ldsm4(al, Als + aoff);
                #pragma unroll
                for (int j = 0; j < JN; j++) {
                    const u32* bhp = &bh[j >> 1][(j & 1) * 2];
                    mma16816(acc[m][j], ah, bhp);
                    if (ASPLIT) mma16816(acc[m][j], al, bhp);
                    if (BSPLIT) {
                        const u32* blp = &bl[j >> 1][(j & 1) * 2];
                        mma16816(acc[m][j], ah, blp);
                    }
                }
            }
        }
    }

    const int trow = lane >> 2;
    const int tcol = (lane & 3) * 2;

    #pragma unroll
    for (int m = 0; m < MT; m++) {
        #pragma unroll
        for (int j = 0; j < JN; j++) {
            int col = bn + wn + 8 * j + tcol;
            float b0 = bias ? bias[col] : 0.f;
            float b1 = bias ? bias[col + 1] : 0.f;
            #pragma unroll
            for (int h = 0; h < 2; h++) {
                long long row = bm + wm + 16 * m + trow + h * 8;
                float v0 = acc[m][j][2 * h + 0] + b0;
                float v1 = acc[m][j][2 * h + 1] + b1;
                long long idx = row * N + col;
                if (OMODE == 0)
                    *(float2*)(Cf + idx) = make_float2(v0, v1);
                else
                    *(half2*)(Ch + idx) = __floats2half2_rn(v0, v1);
            }
        }
    }
}

// ------------------------------ fat kernels --------------------------------

// L1: precompute(257) || b2(32) || weight hi+lo splits(2048)
__global__ __launch_bounds__(256)
void prep_kernel(const float* __restrict__ Wq, const float* __restrict__ Wk,
                 const float* __restrict__ We, const float* __restrict__ bq,
                 const float* __restrict__ bk, const float* __restrict__ be,
                 const float* __restrict__ bv, const float* __restrict__ Wv,
                 const float* __restrict__ Wo)
{
    int bid = blockIdx.x;
    if (bid < 257)       precompute_body(bid, Wq, Wk, We, bq, bk, be);
    else if (bid < 289)  b2_body(bid - 257, bv, Wo);
    else                 split_body(bid - 289, Wv, Wo);
}

// L2: embed-q(128) || embed-k(128) || W2 = Wv@Wo 3-term (128 CTAs of 64x128)
// All at <=73728B smem, 2 CTAs/SM.
__global__ __launch_bounds__(256, 2)
void embed_w2_kernel(const float* __restrict__ x)
{
    int bid = blockIdx.x;
    if (bid < 128) {
        embed_body16(bid, x, true);
    } else if (bid < 256) {
        embed_body16(bid - 128, x, false);
    } else {
        int t = bid - 256;                       // 0..127
        gemm_body<true, true, 2, 2, 64, 128>(g_Wvh, g_Wvl, g_Woh, g_Wol,
                                             nullptr, nullptr, g_W2h,
                                             (t >> 3) * 64, (t & 7) * 128, H_, H_);
    }
}

// L3: attn(1024) || v2 = xh@W2h + b2 (512 CTAs of 128x128, 2 CTAs/SM)
__global__ __launch_bounds__(256, 2)
void attn_v2_kernel()
{
    int bid = blockIdx.x;
    if (bid < 1024) {
        attn_body(bid);
    } else {
        int t = bid - 1024;                      // 0..511
        gemm_body<false, false, 2, 3, 128, 128>(g_xh, nullptr, g_W2h, nullptr,
                                                g_b2, nullptr, g_v2h,
                                                (t >> 3) * 128, (t & 7) * 128, H_, H_);
    }
}

// L4: out = attn @ v2 + bo (512 CTAs of 128x128: 16 bm x 8 bn x 4 z)
__global__ __launch_bounds__(256, 2)
void out_kernel(const float* __restrict__ bo, float* __restrict__ out)
{
    int t = blockIdx.x;
    int z = t >> 7;
    int r = t & 127;
    gemm_body<false, false, 0, 3, 128, 128>(
        g_attnh + (long long)z * S_ * S_, nullptr,
        g_v2h + (long long)z * S_ * H_, nullptr,
        bo, out + (long long)z * S_ * H_, nullptr,
        (r >> 3) * 128, (r & 7) * 128, H_, S_);
}

// ---------------------------------------------------------------------------
extern "C" void kernel_launch(void* const* d_in, const int* in_sizes, int n_in,
                              void* d_out, int out_size)
{
    const float* x  = (const float*)d_in[0];
    const float* Wq = (const float*)d_in[1];
    const float* bq = (const float*)d_in[2];
    const float* Wk = (const float*)d_in[3];
    const float* bk = (const float*)d_in[4];
    const float* Wv = (const float*)d_in[5];
    const float* bv = (const float*)d_in[6];
    const float* We = (const float*)d_in[7];
    const float* be = (const float*)d_in[8];
    const float* Wo = (const float*)d_in[9];
    const float* bo = (const float*)d_in[10];
    float* out = (float*)d_out;

    const int SM_L1 = H_ * 17 * 4;                       // 69632 (precompute)
    const int SM_L2 = (QD_ * H_ + 2 * H_) * 4;           // 73728 (embed16; W2 needs 55296)
    const int SM_L3 = 3 * (128 * APITCH + 32 * (128 * 2 + 16));  // 56832
    const int SM_L4 = SM_L3;

    cudaFuncSetAttribute(prep_kernel,     cudaFuncAttributeMaxDynamicSharedMemorySize, SM_L1);
    cudaFuncSetAttribute(embed_w2_kernel, cudaFuncAttributeMaxDynamicSharedMemorySize, SM_L2);
    cudaFuncSetAttribute(attn_v2_kernel,  cudaFuncAttributeMaxDynamicSharedMemorySize, SM_L3);
    cudaFuncSetAttribute(out_kernel,      cudaFuncAttributeMaxDynamicSharedMemorySize, SM_L4);

    prep_kernel<<<257 + 32 + 2048, 256, SM_L1>>>(Wq, Wk, We, bq, bk, be, bv, Wv, Wo);
    embed_w2_kernel<<<128 + 128 + 128, 256, SM_L2>>>(x);
    attn_v2_kernel<<<1024 + 512, 256, SM_L3>>>();
    out_kernel<<<512, 256, SM_L4>>>(bo, out);
}

// round 15
// speedup vs baseline: 6.0006x; 1.0146x over previous
#include <cuda_runtime.h>
#include <cuda_fp16.h>

// ---------------------------------------------------------------------------
// QuantumAttention, restructured:
//   out = attn @ (x @ (Wv@Wo) + bv@Wo) + bo,  attn = softmax((q_q.k_q)^2)
//   q_q = normalize(x @ (Wq@We) + (bq@We+be)), k_q likewise.
// R15: R13 bodies verbatim; only block ORDER changed — long-pole GEMM CTAs
// scheduled first in L2 (W2 before embed) and L3 (v2 before attn) so short
// blocks fill GEMM bubbles instead of delaying the GEMM start.
// Numerics bitwise-identical to R13 (rel_err must be 4.042953e-4).
// ---------------------------------------------------------------------------

#define B_ 4
#define S_ 2048
#define H_ 1024
#define QD_ 16
#define ROWS_ (B_ * S_)          // 8192

typedef unsigned int u32;

// ------------------------------- scratch ----------------------------------
__device__ float g_WqeT[QD_ * H_];
__device__ float g_WkeT[QD_ * H_];
__device__ float g_bqe[QD_];
__device__ float g_bke[QD_];
__device__ float g_qq[ROWS_ * QD_];
__device__ float g_kq[ROWS_ * QD_];
__device__ float g_b2[H_];

__device__ half g_xh[ROWS_ * H_];
__device__ half g_Wvh[H_ * H_];
__device__ half g_Wvl[H_ * H_];
__device__ half g_Woh[H_ * H_];
__device__ half g_Wol[H_ * H_];
__device__ half g_W2h[H_ * H_];
__device__ half g_v2h[ROWS_ * H_];
__device__ half g_attnh[(long long)B_ * S_ * S_];

// ----------------------------- PTX helpers --------------------------------
__device__ __forceinline__ u32 smem_u32(const void* p) {
    u32 a;
    asm("{ .reg .u64 t; cvta.to.shared.u64 t, %1; cvt.u32.u64 %0, t; }"
        : "=r"(a) : "l"(p));
    return a;
}
__device__ __forceinline__ void cpa16(u32 d, const void* g) {
    asm volatile("cp.async.cg.shared.global [%0], [%1], 16;" :: "r"(d), "l"(g));
}
#define CP_COMMIT() asm volatile("cp.async.commit_group;" ::: "memory")
#define CP_WAIT(n)  asm volatile("cp.async.wait_group %0;" :: "n"(n) : "memory")

__device__ __forceinline__ void ldsm4(u32* r, u32 a) {
    asm volatile("ldmatrix.sync.aligned.m8n8.x4.shared.b16 {%0,%1,%2,%3}, [%4];"
        : "=r"(r[0]), "=r"(r[1]), "=r"(r[2]), "=r"(r[3]) : "r"(a));
}
__device__ __forceinline__ void ldsm4t(u32* r, u32 a) {
    asm volatile("ldmatrix.sync.aligned.m8n8.x4.trans.shared.b16 {%0,%1,%2,%3}, [%4];"
        : "=r"(r[0]), "=r"(r[1]), "=r"(r[2]), "=r"(r[3]) : "r"(a));
}
__device__ __forceinline__ void mma16816(float* d, const u32* a, const u32* b) {
    asm volatile("mma.sync.aligned.m16n8k16.row.col.f32.f16.f16.f32 "
        "{%0,%1,%2,%3}, {%4,%5,%6,%7}, {%8,%9}, {%0,%1,%2,%3};"
        : "+f"(d[0]), "+f"(d[1]), "+f"(d[2]), "+f"(d[3])
        : "r"(a[0]), "r"(a[1]), "r"(a[2]), "r"(a[3]), "r"(b[0]), "r"(b[1]));
}

// exp(s), s in [0,1]: degree-6 Taylor around 0.5 (FMA pipe; rel err ~1.3e-6)
__device__ __forceinline__ float exp01(float s) {
    float u = s - 0.5f;
    float p = 1.f / 720.f;
    p = fmaf(p, u, 1.f / 120.f);
    p = fmaf(p, u, 1.f / 24.f);
    p = fmaf(p, u, 1.f / 6.f);
    p = fmaf(p, u, 0.5f);
    p = fmaf(p, u, 1.f);
    p = fmaf(p, u, 1.f);
    return p * 1.6487212707f;
}

// ---------------------------- role bodies ----------------------------------

__device__ __forceinline__ void precompute_body(int bid,
    const float* __restrict__ Wq, const float* __restrict__ Wk,
    const float* __restrict__ We, const float* __restrict__ bq,
    const float* __restrict__ bk, const float* __restrict__ be)
{
    extern __shared__ char dsm[];
    float* Wes = (float*)dsm;               // [1024][17]
    int tid = threadIdx.x;
    for (int idx = tid; idx < H_ * QD_; idx += 256)
        Wes[(idx >> 4) * 17 + (idx & 15)] = We[idx];
    __syncthreads();

    int wg = bid * 8 + (tid >> 5);
    if (wg >= 2 * (H_ + 1)) return;
    int m = wg / (H_ + 1);
    int i = wg % (H_ + 1);
    int lane = tid & 31;
    const float* W  = m ? Wk : Wq;
    const float* bb = m ? bk : bq;

    float p[QD_];
    #pragma unroll
    for (int o = 0; o < QD_; o++) p[o] = 0.f;

    for (int kk = 0; kk < H_ / 32; kk++) {
        int k = kk * 32 + lane;
        float w = (i < H_) ? W[(long long)i * H_ + k] : bb[k];
        const float* wr = &Wes[k * 17];
        #pragma unroll
        for (int o = 0; o < QD_; o++) p[o] = fmaf(w, wr[o], p[o]);
    }
    #pragma unroll
    for (int off = 16; off; off >>= 1)
        #pragma unroll
        for (int o = 0; o < QD_; o++)
            p[o] += __shfl_xor_sync(0xffffffffu, p[o], off);

    if (lane == 0) {
        if (i < H_) {
            float* dst = m ? g_WkeT : g_WqeT;
            #pragma unroll
            for (int o = 0; o < QD_; o++) dst[o * H_ + i] = p[o];
        } else {
            float* dst = m ? g_bke : g_bqe;
            #pragma unroll
            for (int o = 0; o < QD_; o++) dst[o] = p[o] + be[o];
        }
    }
}

__device__ __forceinline__ void b2_body(int bid,
    const float* __restrict__ bv, const float* __restrict__ Wo)
{
    __shared__ float red[8][33];
    int t = threadIdx.x;
    int n = bid * 32 + (t & 31);
    int ks = t >> 5;
    float s = 0.f;
    #pragma unroll 4
    for (int k = ks * 128; k < ks * 128 + 128; k++)
        s = fmaf(bv[k], Wo[(long long)k * H_ + n], s);
    red[ks][t & 31] = s;
    __syncthreads();
    if (t < 32) {
        float tot = 0.f;
        #pragma unroll
        for (int i = 0; i < 8; i++) tot += red[i][t];
        g_b2[bid * 32 + t] = tot;
    }
}

// fp32 -> fp16 hi+lo split of Wv / Wo
__device__ __forceinline__ void split_body(int sidx,
    const float* __restrict__ Wv, const float* __restrict__ Wo)
{
    bool second = sidx >= 1024;
    const float* src = second ? Wo : Wv;
    half* h = second ? g_Woh : g_Wvh;
    half* l = second ? g_Wol : g_Wvl;
    int i = (sidx & 1023) * 256 + threadIdx.x;
    float4 v = ((const float4*)src)[i];
    half a0 = __float2half_rn(v.x), a1 = __float2half_rn(v.y);
    half a2 = __float2half_rn(v.z), a3 = __float2half_rn(v.w);
    half2* hp = (half2*)h;
    half2* lp = (half2*)l;
    hp[2*i]   = __halves2half2(a0, a1);
    hp[2*i+1] = __halves2half2(a2, a3);
    lp[2*i]   = __floats2half2_rn(v.x - __half2float(a0), v.y - __half2float(a1));
    lp[2*i+1] = __floats2half2_rn(v.z - __half2float(a2), v.w - __half2float(a3));
}

// embed (q-or-k half): 64 rows/block, 16 dims; q-blocks also emit xh (fp16).
#define ERB 64
__device__ __forceinline__ void embed_body16(int bid, const float* __restrict__ x,
                                             bool isq)
{
    extern __shared__ char dsm[];
    float* sm = (float*)dsm;
    float* Ws = sm;                       // [16][1024]
    float* xb = sm + QD_ * H_;            // [2][1024]
    __shared__ float zbuf[QD_];

    int tid = threadIdx.x, lane = tid & 31, w = tid >> 5;

    const float* WT = isq ? g_WqeT : g_WkeT;
    for (int idx = tid; idx < QD_ * H_; idx += 256)
        Ws[idx] = WT[idx];
    long long row0 = (long long)bid * ERB;

    float4 nxt = *(const float4*)&x[row0 * H_ + tid * 4];
    *(float4*)&xb[tid * 4] = nxt;
    if (isq) {
        half2* xp = (half2*)&g_xh[row0 * H_ + tid * 4];
        xp[0] = __floats2half2_rn(nxt.x, nxt.y);
        xp[1] = __floats2half2_rn(nxt.z, nxt.w);
    }
    __syncthreads();

    for (int r = 0; r < ERB; r++) {
        if (r + 1 < ERB) {
            nxt = *(const float4*)&x[(row0 + r + 1) * H_ + tid * 4];
            if (isq) {
                half2* xp = (half2*)&g_xh[(row0 + r + 1) * H_ + tid * 4];
                xp[0] = __floats2half2_rn(nxt.x, nxt.y);
                xp[1] = __floats2half2_rn(nxt.z, nxt.w);
            }
        }

        const float* xs = xb + (r & 1) * H_;
        float xr[32];
        #pragma unroll
        for (int i = 0; i < 8; i++)
            *(float4*)&xr[i * 4] = *(const float4*)&xs[i * 128 + lane * 4];

        #pragma unroll
        for (int oo = 0; oo < 2; oo++) {
            int o = w * 2 + oo;
            const float* wrow = Ws + o * H_;
            float s = 0.f;
            #pragma unroll
            for (int i = 0; i < 8; i++) {
                float4 wv = *(const float4*)&wrow[i * 128 + lane * 4];
                s += xr[i*4]*wv.x + xr[i*4+1]*wv.y + xr[i*4+2]*wv.z + xr[i*4+3]*wv.w;
            }
            #pragma unroll
            for (int off = 16; off; off >>= 1)
                s += __shfl_xor_sync(0xffffffffu, s, off);
            if (lane == 0) zbuf[o] = s;
        }
        __syncthreads();

        if (tid < 32) {
            int o = tid & 15;
            float z = zbuf[o] + (isq ? g_bqe[o] : g_bke[o]);
            float sq = z * z;
            #pragma unroll
            for (int off = 8; off; off >>= 1)
                sq += __shfl_xor_sync(0xffffffffu, sq, off);
            float val = z * rsqrtf(sq + 1e-8f);
            if (tid < QD_)
                (isq ? g_qq : g_kq)[(row0 + r) * QD_ + o] = val;
        }
        if (r + 1 < ERB)
            *(float4*)&xb[((r + 1) & 1) * H_ + tid * 4] = nxt;
        __syncthreads();
    }
}

__device__ __forceinline__ void attn_body(int bid)
{
    int b = bid >> 8;
    int q0 = (bid & 255) * 8;
    int tid = threadIdx.x;
    int lane = tid & 31, wid = tid >> 5;

    __shared__ float qs[8][QD_];
    __shared__ float red[8][9];

    if (tid < 128)
        ((float*)qs)[tid] = g_qq[((long long)b * S_ + q0) * QD_ + tid];
    __syncthreads();

    const float* kq = g_kq + (long long)b * S_ * QD_;
    float e[8][8];
    float sum[8] = {};

    #pragma unroll
    for (int j = 0; j < 8; j++) {
        int kk = tid + j * 256;
        const float4* kp = (const float4*)(kq + (long long)kk * QD_);
        float4 k0 = kp[0], k1 = kp[1], k2 = kp[2], k3 = kp[3];
        #pragma unroll
        for (int q = 0; q < 8; q++) {
            const float* qr = qs[q];
            float ov = qr[0]*k0.x + qr[1]*k0.y + qr[2]*k0.z + qr[3]*k0.w
                     + qr[4]*k1.x + qr[5]*k1.y + qr[6]*k1.z + qr[7]*k1.w
                     + qr[8]*k2.x + qr[9]*k2.y + qr[10]*k2.z + qr[11]*k2.w
                     + qr[12]*k3.x + qr[13]*k3.y + qr[14]*k3.z + qr[15]*k3.w;
            float ee = exp01(ov * ov);
            e[q][j] = ee;
            sum[q] += ee;
        }
    }

    #pragma unroll
    for (int q = 0; q < 8; q++) {
        float s = sum[q];
        #pragma unroll
        for (int off = 16; off; off >>= 1)
            s += __shfl_xor_sync(0xffffffffu, s, off);
        if (lane == 0) red[wid][q] = s;
    }
    __syncthreads();

    float inv[8];
    #pragma unroll
    for (int q = 0; q < 8; q++) {
        float t = 0.f;
        #pragma unroll
        for (int w = 0; w < 8; w++) t += red[w][q];
        inv[q] = 1.f / t;
    }

    #pragma unroll
    for (int q = 0; q < 8; q++) {
        long long rowo = ((long long)b * S_ + q0 + q) * S_;
        #pragma unroll
        for (int j = 0; j < 8; j++)
            g_attnh[rowo + tid + j * 256] = __float2half_rn(e[q][j] * inv[q]);
    }
}

// ---- split-fp16 GEMM body: CTA AMxBN, 8 warps (AM/2)x(BN/4), cp.async -----
#define APITCH 80

template<bool ASPLIT, bool BSPLIT, int AM, int BN>
__device__ __forceinline__ void load_stage(u32 sb,
    const half* __restrict__ Ah, const half* __restrict__ Al,
    const half* __restrict__ Bh, const half* __restrict__ Bl,
    int bm, int bn, int k0, int K, int N, int tid)
{
    constexpr int BPITCHc = BN * 2 + 16;
    constexpr int BTILEc  = 32 * BPITCHc;
    constexpr int ATILEc  = AM * APITCH;
    constexpr int BOFF    = ATILEc * (ASPLIT ? 2 : 1);
    #pragma unroll
    for (int i = 0; i < AM / 64; i++) {
        int u = tid + i * 256;
        int r = u >> 2, c = u & 3;
        long long g = (long long)(bm + r) * K + k0 + c * 8;
        cpa16(sb + r * APITCH + c * 16, Ah + g);
        if (ASPLIT) cpa16(sb + ATILEc + r * APITCH + c * 16, Al + g);
    }
    #pragma unroll
    for (int i = 0; i < BN / 64; i++) {
        int u = tid + i * 256;
        int r = u / (BN / 8), c = u % (BN / 8);
        long long g = (long long)(k0 + r) * N + bn + c * 8;
        cpa16(sb + BOFF + r * BPITCHc + c * 16, Bh + g);
        if (BSPLIT) cpa16(sb + BOFF + BTILEc + r * BPITCHc + c * 16, Bl + g);
    }
}

template<bool ASPLIT, bool BSPLIT, int OMODE, int STAGES, int AM, int BN>
__device__ __forceinline__ void gemm_body(
    const half* __restrict__ Ah, const half* __restrict__ Al,
    const half* __restrict__ Bh, const half* __restrict__ Bl,
    const float* __restrict__ bias,
    float* __restrict__ Cf, half* __restrict__ Ch,
    int bm, int bn, int N, int K)
{
    constexpr int BPITCHc = BN * 2 + 16;
    constexpr int BTILEc  = 32 * BPITCHc;
    constexpr int ATILEc  = AM * APITCH;
    constexpr int BOFF    = ATILEc * (ASPLIT ? 2 : 1);
    constexpr int STG     = BOFF + BTILEc * (BSPLIT ? 2 : 1);
    constexpr int MT      = AM / 32;        // 16-row m-tiles per warp
    constexpr int WN      = BN / 4;         // per-warp n width
    constexpr int NT      = WN / 16;        // ldsm4t tiles per warp
    constexpr int JN      = WN / 8;         // 8-col mma tiles per warp

    extern __shared__ char dsm[];
    u32 sbase = smem_u32(dsm);

    const int tid = threadIdx.x;
    const int wid = tid >> 5, lane = tid & 31;
    const int wm = (wid >> 2) * (AM / 2);
    const int wn = (wid & 3) * WN;

    float acc[MT][JN][4] = {};

    const int NC = K >> 5;
    #pragma unroll
    for (int s = 0; s < STAGES - 1; s++) {
        load_stage<ASPLIT, BSPLIT, AM, BN>(sbase + s * STG, Ah, Al, Bh, Bl,
                                           bm, bn, s << 5, K, N, tid);
        CP_COMMIT();
    }

    const int arow = lane & 15;
    const int ak8  = ((lane >> 4) & 1) * 8;
    const int bk   = lane & 15;
    const int bn8  = ((lane >> 4) & 1) * 8;

    int ld = STAGES - 1;
    for (int c = 0; c < NC; c++) {
        CP_WAIT(STAGES - 2);
        __syncthreads();

        if (ld < NC) {
            load_stage<ASPLIT, BSPLIT, AM, BN>(sbase + (ld % STAGES) * STG,
                Ah, Al, Bh, Bl, bm, bn, ld << 5, K, N, tid);
            CP_COMMIT();
            ld++;
        }

        u32 st = sbase + (c % STAGES) * STG;
        u32 As = st, Als = st + ATILEc;
        u32 Bs = st + BOFF, Bls = Bs + BTILEc;

        #pragma unroll
        for (int ks = 0; ks < 32; ks += 16) {
            u32 bh[NT][4], bl[NT][4];
            #pragma unroll
            for (int n2 = 0; n2 < NT; n2++) {
                u32 boff = (ks + bk) * BPITCHc + (wn + 16 * n2 + bn8) * 2;
                ldsm4t(bh[n2], Bs + boff);
                if (BSPLIT) ldsm4t(bl[n2], Bls + boff);
            }
            #pragma unroll
            for (int m = 0; m < MT; m++) {
                u32 ah[4], al[4];
                u32 aoff = (wm + 16 * m + arow) * APITCH + (ks + ak8) * 2;
                ldsm4(ah, As + aoff);
                if (ASPLIT) ldsm4(al, Als + aoff);
                #pragma unroll
                for (int j = 0; j < JN; j++) {
                    const u32* bhp = &bh[j >> 1][(j & 1) * 2];
                    mma16816(acc[m][j], ah, bhp);
                    if (ASPLIT) mma16816(acc[m][j], al, bhp);
                    if (BSPLIT) {
                        const u32* blp = &bl[j >> 1][(j & 1) * 2];
                        mma16816(acc[m][j], ah, blp);
                    }
                }
            }
        }
    }

    const int trow = lane >> 2;
    const int tcol = (lane & 3) * 2;

    #pragma unroll
    for (int m = 0; m < MT; m++) {
        #pragma unroll
        for (int j = 0; j < JN; j++) {
            int col = bn + wn + 8 * j + tcol;
            float b0 = bias ? bias[col] : 0.f;
            float b1 = bias ? bias[col + 1] : 0.f;
            #pragma unroll
            for (int h = 0; h < 2; h++) {
                long long row = bm + wm + 16 * m + trow + h * 8;
                float v0 = acc[m][j][2 * h + 0] + b0;
                float v1 = acc[m][j][2 * h + 1] + b1;
                long long idx = row * N + col;
                if (OMODE == 0)
                    *(float2*)(Cf + idx) = make_float2(v0, v1);
                else
                    *(half2*)(Ch + idx) = __floats2half2_rn(v0, v1);
            }
        }
    }
}

// ------------------------------ fat kernels --------------------------------

// L1: precompute(257) || b2(32) || weight hi+lo splits(2048)
__global__ __launch_bounds__(256)
void prep_kernel(const float* __restrict__ Wq, const float* __restrict__ Wk,
                 const float* __restrict__ We, const float* __restrict__ bq,
                 const float* __restrict__ bk, const float* __restrict__ be,
                 const float* __restrict__ bv, const float* __restrict__ Wv,
                 const float* __restrict__ Wo)
{
    int bid = blockIdx.x;
    if (bid < 257)       precompute_body(bid, Wq, Wk, We, bq, bk, be);
    else if (bid < 289)  b2_body(bid - 257, bv, Wo);
    else                 split_body(bid - 289, Wv, Wo);
}

// L2: W2 = Wv@Wo 3-term (128 CTAs of 64x128, FIRST) || embed-q(128) || embed-k(128)
__global__ __launch_bounds__(256, 2)
void embed_w2_kernel(const float* __restrict__ x)
{
    int bid = blockIdx.x;
    if (bid < 128) {
        gemm_body<true, true, 2, 2, 64, 128>(g_Wvh, g_Wvl, g_Woh, g_Wol,
                                             nullptr, nullptr, g_W2h,
                                             (bid >> 3) * 64, (bid & 7) * 128, H_, H_);
    } else if (bid < 256) {
        embed_body16(bid - 128, x, true);
    } else {
        embed_body16(bid - 256, x, false);
    }
}

// L3: v2 = xh@W2h + b2 (512 CTAs of 128x128, FIRST) || attn(1024)
__global__ __launch_bounds__(256, 2)
void attn_v2_kernel()
{
    int bid = blockIdx.x;
    if (bid < 512) {
        gemm_body<false, false, 2, 3, 128, 128>(g_xh, nullptr, g_W2h, nullptr,
                                                g_b2, nullptr, g_v2h,
                                                (bid >> 3) * 128, (bid & 7) * 128, H_, H_);
    } else {
        attn_body(bid - 512);
    }
}

// L4: out = attn @ v2 + bo (512 CTAs of 128x128: 16 bm x 8 bn x 4 z)
__global__ __launch_bounds__(256, 2)
void out_kernel(const float* __restrict__ bo, float* __restrict__ out)
{
    int t = blockIdx.x;
    int z = t >> 7;
    int r = t & 127;
    gemm_body<false, false, 0, 3, 128, 128>(
        g_attnh + (long long)z * S_ * S_, nullptr,
        g_v2h + (long long)z * S_ * H_, nullptr,
        bo, out + (long long)z * S_ * H_, nullptr,
        (r >> 3) * 128, (r & 7) * 128, H_, S_);
}

// ---------------------------------------------------------------------------
extern "C" void kernel_launch(void* const* d_in, const int* in_sizes, int n_in,
                              void* d_out, int out_size)
{
    const float* x  = (const float*)d_in[0];
    const float* Wq = (const float*)d_in[1];
    const float* bq = (const float*)d_in[2];
    const float* Wk = (const float*)d_in[3];
    const float* bk = (const float*)d_in[4];
    const float* Wv = (const float*)d_in[5];
    const float* bv = (const float*)d_in[6];
    const float* We = (const float*)d_in[7];
    const float* be = (const float*)d_in[8];
    const float* Wo = (const float*)d_in[9];
    const float* bo = (const float*)d_in[10];
    float* out = (float*)d_out;

    const int SM_L1 = H_ * 17 * 4;                       // 69632 (precompute)
    const int SM_L2 = (QD_ * H_ + 2 * H_) * 4;           // 73728 (embed16; W2 needs 55296)
    const int SM_L3 = 3 * (128 * APITCH + 32 * (128 * 2 + 16));  // 56832
    const int SM_L4 = SM_L3;

    cudaFuncSetAttribute(prep_kernel,     cudaFuncAttributeMaxDynamicSharedMemorySize, SM_L1);
    cudaFuncSetAttribute(embed_w2_kernel, cudaFuncAttributeMaxDynamicSharedMemorySize, SM_L2);
    cudaFuncSetAttribute(attn_v2_kernel,  cudaFuncAttributeMaxDynamicSharedMemorySize, SM_L3);
    cudaFuncSetAttribute(out_kernel,      cudaFuncAttributeMaxDynamicSharedMemorySize, SM_L4);

    prep_kernel<<<257 + 32 + 2048, 256, SM_L1>>>(Wq, Wk, We, bq, bk, be, bv, Wv, Wo);
    embed_w2_kernel<<<128 + 128 + 128, 256, SM_L2>>>(x);
    attn_v2_kernel<<<512 + 1024, 256, SM_L3>>>();
    out_kernel<<<512, 256, SM_L4>>>(bo, out);
}